// round 2
// baseline (speedup 1.0000x reference)
#include <cuda_runtime.h>
#include <cuda_bf16.h>
#include <cstdint>
#include <cstddef>

#define CB   2
#define CS   4096
#define CL   512
#define CDIM 5120
#define CH   40
#define CHD  128
#define CKV  (2*CDIM)
#define FSCALE 0.08838834764831845f
#define FEPS 1e-6f

// ---------------- static device scratch (allocation-free rule) ----------------
__device__ __nv_bfloat16 g_wq_h [(size_t)CDIM*CDIM];
__device__ __nv_bfloat16 g_wq_l [(size_t)CDIM*CDIM];
__device__ __nv_bfloat16 g_wkv_h[(size_t)CDIM*CKV];
__device__ __nv_bfloat16 g_wkv_l[(size_t)CDIM*CKV];
__device__ __nv_bfloat16 g_wo_h [(size_t)CDIM*CDIM];
__device__ __nv_bfloat16 g_wo_l [(size_t)CDIM*CDIM];
__device__ float         g_q    [(size_t)CB*CS*CDIM];
__device__ float         g_kv   [(size_t)CB*CL*CKV];
__device__ __nv_bfloat16 g_k_h  [(size_t)CB*CH*CL*CHD];
__device__ __nv_bfloat16 g_k_l  [(size_t)CB*CH*CL*CHD];
__device__ __nv_bfloat16 g_v_h  [(size_t)CB*CH*CHD*CL];
__device__ __nv_bfloat16 g_v_l  [(size_t)CB*CH*CHD*CL];
__device__ float         g_sc   [(size_t)CB*CH*CS*CL];
__device__ float         g_att  [(size_t)CB*CS*CDIM];

// ---------------- helpers ----------------
__device__ __forceinline__ void split2(float x, float y, uint32_t& hi, uint32_t& lo) {
    __nv_bfloat162 h = __floats2bfloat162_rn(x, y);
    float2 hf = __bfloat1622float2(h);
    __nv_bfloat162 l = __floats2bfloat162_rn(x - hf.x, y - hf.y);
    hi = *reinterpret_cast<uint32_t*>(&h);
    lo = *reinterpret_cast<uint32_t*>(&l);
}

__device__ __forceinline__ void mma16816(float* c, uint32_t a0, uint32_t a1, uint32_t a2,
                                         uint32_t a3, uint32_t b0, uint32_t b1) {
    asm volatile(
        "mma.sync.aligned.m16n8k16.row.col.f32.bf16.bf16.f32 "
        "{%0,%1,%2,%3},{%4,%5,%6,%7},{%8,%9},{%0,%1,%2,%3};\n"
        : "+f"(c[0]), "+f"(c[1]), "+f"(c[2]), "+f"(c[3])
        : "r"(a0), "r"(a1), "r"(a2), "r"(a3), "r"(b0), "r"(b1));
}

// ---------------- weight transpose + bf16 split:  T[n][k] = W[k][n] ----------------
__global__ void transpose_split(const float* __restrict__ W, __nv_bfloat16* __restrict__ Thi,
                                __nv_bfloat16* __restrict__ Tlo, int K, int N) {
    __shared__ float t[32][33];
    int n0 = blockIdx.x * 32, k0 = blockIdx.y * 32;
    int tx = threadIdx.x, ty = threadIdx.y;
#pragma unroll
    for (int i = 0; i < 32; i += 8)
        t[ty + i][tx] = W[(size_t)(k0 + ty + i) * N + n0 + tx];
    __syncthreads();
#pragma unroll
    for (int i = 0; i < 32; i += 8) {
        float v = t[tx][ty + i];
        __nv_bfloat16 h = __float2bfloat16(v);
        size_t o = (size_t)(n0 + ty + i) * K + k0 + tx;
        Thi[o] = h;
        Tlo[o] = __float2bfloat16(v - __bfloat162float(h));
    }
}

// ---------------- in-place RMSNorm over first CDIM cols of each row ----------------
__global__ void rmsnorm_rows(float* __restrict__ X, long ld, const float* __restrict__ g) {
    float* row = X + (size_t)blockIdx.x * ld;
    int tid = threadIdx.x;
    float4* r4 = (float4*)row;
    const float4* g4 = (const float4*)g;
    float s = 0.f;
#pragma unroll 5
    for (int i = tid; i < CDIM / 4; i += 256) {
        float4 v = r4[i];
        s += v.x * v.x + v.y * v.y + v.z * v.z + v.w * v.w;
    }
#pragma unroll
    for (int o = 16; o; o >>= 1) s += __shfl_xor_sync(0xffffffffu, s, o);
    __shared__ float ws[8];
    if ((tid & 31) == 0) ws[tid >> 5] = s;
    __syncthreads();
    if (tid == 0) {
        float x = 0.f;
#pragma unroll
        for (int i = 0; i < 8; i++) x += ws[i];
        ws[0] = rsqrtf(x / (float)CDIM + FEPS);
    }
    __syncthreads();
    float rs = ws[0];
#pragma unroll 5
    for (int i = tid; i < CDIM / 4; i += 256) {
        float4 v = r4[i];
        float4 w = g4[i];
        v.x *= rs * w.x; v.y *= rs * w.y; v.z *= rs * w.z; v.w *= rs * w.w;
        r4[i] = v;
    }
}

// ---------------- split K into per-head [ (b*H+h)*L + l ][ d ] bf16 hi/lo ----------------
__global__ void split_k(const float* __restrict__ kv, __nv_bfloat16* __restrict__ h,
                        __nv_bfloat16* __restrict__ l) {
    size_t i = (size_t)blockIdx.x * 256 + threadIdx.x;
    if (i >= (size_t)CB * CH * CL * CHD) return;
    int d = (int)(i & 127);
    size_t r = i >> 7;
    int ll = (int)(r & 511); r >>= 9;
    int hh = (int)(r % CH);
    int b  = (int)(r / CH);
    float v = kv[((size_t)(b * CL + ll)) * CKV + hh * CHD + d];
    __nv_bfloat16 x = __float2bfloat16(v);
    h[i] = x;
    l[i] = __float2bfloat16(v - __bfloat162float(x));
}

// ---------------- split V transposed: [ (b*H+h)*D + d ][ l ] bf16 hi/lo ----------------
__global__ void split_v(const float* __restrict__ kv, __nv_bfloat16* __restrict__ h,
                        __nv_bfloat16* __restrict__ l) {
    size_t i = (size_t)blockIdx.x * 256 + threadIdx.x;
    if (i >= (size_t)CB * CH * CHD * CL) return;
    int ll = (int)(i & 511);
    size_t r = i >> 9;
    int d = (int)(r & 127); r >>= 7;
    int hh = (int)(r % CH);
    int b  = (int)(r / CH);
    float v = kv[((size_t)(b * CL + ll)) * CKV + CDIM + hh * CHD + d];
    __nv_bfloat16 x = __float2bfloat16(v);
    h[i] = x;
    l[i] = __float2bfloat16(v - __bfloat162float(x));
}

// ---------------- softmax over rows of 512, warp per row, scale folded in ----------------
__global__ void softmax512(float* __restrict__ X) {
    int warp = threadIdx.x >> 5, lane = threadIdx.x & 31;
    size_t row = (size_t)blockIdx.x * 8 + warp;
    float4* p = (float4*)(X + row * CL);
    float4 v[4];
    float mx = -1e30f;
#pragma unroll
    for (int i = 0; i < 4; i++) {
        v[i] = p[lane + 32 * i];
        v[i].x *= FSCALE; v[i].y *= FSCALE; v[i].z *= FSCALE; v[i].w *= FSCALE;
        mx = fmaxf(mx, fmaxf(fmaxf(v[i].x, v[i].y), fmaxf(v[i].z, v[i].w)));
    }
#pragma unroll
    for (int o = 16; o; o >>= 1) mx = fmaxf(mx, __shfl_xor_sync(0xffffffffu, mx, o));
    float s = 0.f;
#pragma unroll
    for (int i = 0; i < 4; i++) {
        v[i].x = __expf(v[i].x - mx); v[i].y = __expf(v[i].y - mx);
        v[i].z = __expf(v[i].z - mx); v[i].w = __expf(v[i].w - mx);
        s += v[i].x + v[i].y + v[i].z + v[i].w;
    }
#pragma unroll
    for (int o = 16; o; o >>= 1) s += __shfl_xor_sync(0xffffffffu, s, o);
    float inv = 1.f / s;
#pragma unroll
    for (int i = 0; i < 4; i++) {
        v[i].x *= inv; v[i].y *= inv; v[i].z *= inv; v[i].w *= inv;
        p[lane + 32 * i] = v[i];
    }
}

// ---------------- generic batched bf16x3 GEMM: C = A(fp32) * B(split bf16 [N][K]) + bias ----------------
struct GP {
    const float* A;  long ldA, sAb, sAh;
    const __nv_bfloat16 *Bhi, *Blo;  long sBb, sBh;
    float* C;  long ldC, sCb, sCh;
    const float* bias;
    int K, Hdiv;
};

__global__ __launch_bounds__(256) void gemm_bf16x3(GP p) {
    __shared__ __nv_bfloat16 sAhi[128 * 36], sAlo[128 * 36], sBhi[128 * 36], sBlo[128 * 36];
    uint32_t* wAhi = (uint32_t*)sAhi;
    uint32_t* wAlo = (uint32_t*)sAlo;
    uint32_t* wBhi = (uint32_t*)sBhi;
    uint32_t* wBlo = (uint32_t*)sBlo;

    int z = blockIdx.z, bb = z / p.Hdiv, hh = z % p.Hdiv;
    const float* A = p.A + (size_t)bb * p.sAb + (size_t)hh * p.sAh +
                     (size_t)blockIdx.y * 128 * p.ldA;
    const __nv_bfloat16* Bh = p.Bhi + (size_t)bb * p.sBb + (size_t)hh * p.sBh +
                              (size_t)blockIdx.x * 128 * p.K;
    const __nv_bfloat16* Bl = p.Blo + (size_t)bb * p.sBb + (size_t)hh * p.sBh +
                              (size_t)blockIdx.x * 128 * p.K;

    int tid = threadIdx.x, lane = tid & 31, wp = tid >> 5;
    int wm = wp >> 1, wn = wp & 1;
    int arow = tid >> 3, acv = tid & 7;   // A loader: rows arow + 32*i, float4 col acv
    int brow = tid >> 2, bcv = tid & 3;   // B loader: rows brow + 64*i, uint4 col bcv

    float acc[2][8][4];
#pragma unroll
    for (int mi = 0; mi < 2; mi++)
#pragma unroll
        for (int nj = 0; nj < 8; nj++)
#pragma unroll
            for (int q = 0; q < 4; q++) acc[mi][nj][q] = 0.f;

    float4 ra[4];
    uint4 rbh[2], rbl[2];
    int nk = p.K / 32;

    auto ldTile = [&](int kt) {
#pragma unroll
        for (int i = 0; i < 4; i++)
            ra[i] = *(const float4*)(A + (size_t)(arow + 32 * i) * p.ldA + kt * 32 + acv * 4);
#pragma unroll
        for (int i = 0; i < 2; i++) {
            rbh[i] = *(const uint4*)(Bh + (size_t)(brow + 64 * i) * p.K + kt * 32 + bcv * 8);
            rbl[i] = *(const uint4*)(Bl + (size_t)(brow + 64 * i) * p.K + kt * 32 + bcv * 8);
        }
    };
    auto stTile = [&]() {
#pragma unroll
        for (int i = 0; i < 4; i++) {
            int r = arow + 32 * i;
            uint32_t h0, l0, h1, l1;
            split2(ra[i].x, ra[i].y, h0, l0);
            split2(ra[i].z, ra[i].w, h1, l1);
            wAhi[r * 18 + acv * 2] = h0; wAhi[r * 18 + acv * 2 + 1] = h1;
            wAlo[r * 18 + acv * 2] = l0; wAlo[r * 18 + acv * 2 + 1] = l1;
        }
#pragma unroll
        for (int i = 0; i < 2; i++) {
            int r = brow + 64 * i;
            uint32_t* d0 = &wBhi[r * 18 + bcv * 4];
            d0[0] = rbh[i].x; d0[1] = rbh[i].y; d0[2] = rbh[i].z; d0[3] = rbh[i].w;
            uint32_t* d1 = &wBlo[r * 18 + bcv * 4];
            d1[0] = rbl[i].x; d1[1] = rbl[i].y; d1[2] = rbl[i].z; d1[3] = rbl[i].w;
        }
    };

    ldTile(0);
    stTile();
    __syncthreads();

    for (int kt = 0; kt < nk; kt++) {
        if (kt + 1 < nk) ldTile(kt + 1);
#pragma unroll
        for (int kk = 0; kk < 2; kk++) {
            int colw = kk * 8 + (lane & 3);
            uint32_t ah[2][4], al[2][4];
#pragma unroll
            for (int mi = 0; mi < 2; mi++) {
                int r = wm * 32 + mi * 16 + (lane >> 2);
                ah[mi][0] = wAhi[r * 18 + colw];
                ah[mi][1] = wAhi[(r + 8) * 18 + colw];
                ah[mi][2] = wAhi[r * 18 + colw + 4];
                ah[mi][3] = wAhi[(r + 8) * 18 + colw + 4];
                al[mi][0] = wAlo[r * 18 + colw];
                al[mi][1] = wAlo[(r + 8) * 18 + colw];
                al[mi][2] = wAlo[r * 18 + colw + 4];
                al[mi][3] = wAlo[(r + 8) * 18 + colw + 4];
            }
#pragma unroll
            for (int nj = 0; nj < 8; nj++) {
                int n = wn * 64 + nj * 8 + (lane >> 2);
                uint32_t bh0 = wBhi[n * 18 + colw], bh1 = wBhi[n * 18 + colw + 4];
                uint32_t bl0 = wBlo[n * 18 + colw], bl1 = wBlo[n * 18 + colw + 4];
#pragma unroll
                for (int mi = 0; mi < 2; mi++) {
                    mma16816(acc[mi][nj], ah[mi][0], ah[mi][1], ah[mi][2], ah[mi][3], bh0, bh1);
                    mma16816(acc[mi][nj], al[mi][0], al[mi][1], al[mi][2], al[mi][3], bh0, bh1);
                    mma16816(acc[mi][nj], ah[mi][0], ah[mi][1], ah[mi][2], ah[mi][3], bl0, bl1);
                }
            }
        }
        __syncthreads();
        if (kt + 1 < nk) {
            stTile();
            __syncthreads();
        }
    }

    float* C = p.C + (size_t)bb * p.sCb + (size_t)hh * p.sCh +
               (size_t)blockIdx.y * 128 * p.ldC + (size_t)blockIdx.x * 128;
#pragma unroll
    for (int nj = 0; nj < 8; nj++) {
        int c = wn * 64 + nj * 8 + ((lane & 3) << 1);
        float b0 = 0.f, b1 = 0.f;
        if (p.bias) {
            size_t cg = (size_t)blockIdx.x * 128 + c;
            b0 = p.bias[cg];
            b1 = p.bias[cg + 1];
        }
#pragma unroll
        for (int mi = 0; mi < 2; mi++) {
            int r = wm * 32 + mi * 16 + (lane >> 2);
            float2 v0 = make_float2(acc[mi][nj][0] + b0, acc[mi][nj][1] + b1);
            float2 v1 = make_float2(acc[mi][nj][2] + b0, acc[mi][nj][3] + b1);
            *(float2*)&C[(size_t)r * p.ldC + c] = v0;
            *(float2*)&C[(size_t)(r + 8) * p.ldC + c] = v1;
        }
    }
}

// ---------------- host launcher ----------------
extern "C" void kernel_launch(void* const* d_in, const int* in_sizes, int n_in,
                              void* d_out, int out_size) {
    (void)in_sizes; (void)n_in; (void)out_size;
    const float* hid = (const float*)d_in[0];
    const float* ctx = (const float*)d_in[1];
    const float* Wq  = (const float*)d_in[2];
    const float* bq  = (const float*)d_in[3];
    const float* Wkv = (const float*)d_in[4];
    const float* bkv = (const float*)d_in[5];
    const float* gq  = (const float*)d_in[6];
    const float* gk  = (const float*)d_in[7];
    const float* Wo  = (const float*)d_in[8];
    const float* bo  = (const float*)d_in[9];
    float* out = (float*)d_out;

    __nv_bfloat16 *wq_h, *wq_l, *wkv_h, *wkv_l, *wo_h, *wo_l, *k_h, *k_l, *v_h, *v_l;
    float *q, *kv, *sc, *att;
    cudaGetSymbolAddress((void**)&wq_h, g_wq_h);
    cudaGetSymbolAddress((void**)&wq_l, g_wq_l);
    cudaGetSymbolAddress((void**)&wkv_h, g_wkv_h);
    cudaGetSymbolAddress((void**)&wkv_l, g_wkv_l);
    cudaGetSymbolAddress((void**)&wo_h, g_wo_h);
    cudaGetSymbolAddress((void**)&wo_l, g_wo_l);
    cudaGetSymbolAddress((void**)&k_h, g_k_h);
    cudaGetSymbolAddress((void**)&k_l, g_k_l);
    cudaGetSymbolAddress((void**)&v_h, g_v_h);
    cudaGetSymbolAddress((void**)&v_l, g_v_l);
    cudaGetSymbolAddress((void**)&q, g_q);
    cudaGetSymbolAddress((void**)&kv, g_kv);
    cudaGetSymbolAddress((void**)&sc, g_sc);
    cudaGetSymbolAddress((void**)&att, g_att);

    dim3 tb(32, 8);
    transpose_split<<<dim3(CDIM / 32, CDIM / 32), tb>>>(Wq, wq_h, wq_l, CDIM, CDIM);
    transpose_split<<<dim3(CKV / 32, CDIM / 32), tb>>>(Wkv, wkv_h, wkv_l, CDIM, CKV);
    transpose_split<<<dim3(CDIM / 32, CDIM / 32), tb>>>(Wo, wo_h, wo_l, CDIM, CDIM);

    GP p{};

    // Q = hidden @ Wq + bq
    p.A = hid; p.ldA = CDIM; p.sAb = 0; p.sAh = 0;
    p.Bhi = wq_h; p.Blo = wq_l; p.sBb = 0; p.sBh = 0;
    p.C = q; p.ldC = CDIM; p.sCb = 0; p.sCh = 0;
    p.bias = bq; p.K = CDIM; p.Hdiv = 1;
    gemm_bf16x3<<<dim3(CDIM / 128, (CB * CS) / 128, 1), 256>>>(p);

    rmsnorm_rows<<<CB * CS, 256>>>(q, CDIM, gq);

    // KV = context @ Wkv + bkv
    p.A = ctx; p.ldA = CDIM; p.sAb = 0; p.sAh = 0;
    p.Bhi = wkv_h; p.Blo = wkv_l; p.sBb = 0; p.sBh = 0;
    p.C = kv; p.ldC = CKV; p.sCb = 0; p.sCh = 0;
    p.bias = bkv; p.K = CDIM; p.Hdiv = 1;
    gemm_bf16x3<<<dim3(CKV / 128, (CB * CL) / 128, 1), 256>>>(p);

    rmsnorm_rows<<<CB * CL, 256>>>(kv, CKV, gk);

    {
        size_t nK = (size_t)CB * CH * CL * CHD;
        split_k<<<(unsigned)((nK + 255) / 256), 256>>>(kv, k_h, k_l);
        split_v<<<(unsigned)((nK + 255) / 256), 256>>>(kv, v_h, v_l);
    }

    // scores[b,h] = q_bh @ k_bh^T   (M=S, N=L, K=D)
    p.A = q; p.ldA = CDIM; p.sAb = (long)CS * CDIM; p.sAh = CHD;
    p.Bhi = k_h; p.Blo = k_l; p.sBb = (long)CH * CL * CHD; p.sBh = (long)CL * CHD;
    p.C = sc; p.ldC = CL; p.sCb = (long)CH * CS * CL; p.sCh = (long)CS * CL;
    p.bias = nullptr; p.K = CHD; p.Hdiv = CH;
    gemm_bf16x3<<<dim3(CL / 128, CS / 128, CB * CH), 256>>>(p);

    softmax512<<<(CB * CH * CS) / 8, 256>>>(sc);

    // att[b,h] = probs @ v_bh      (M=S, N=D, K=L)
    p.A = sc; p.ldA = CL; p.sAb = (long)CH * CS * CL; p.sAh = (long)CS * CL;
    p.Bhi = v_h; p.Blo = v_l; p.sBb = (long)CH * CHD * CL; p.sBh = (long)CHD * CL;
    p.C = att; p.ldC = CDIM; p.sCb = (long)CS * CDIM; p.sCh = CHD;
    p.bias = nullptr; p.K = CL; p.Hdiv = CH;
    gemm_bf16x3<<<dim3(CHD / 128, CS / 128, CB * CH), 256>>>(p);

    // out = att @ Wo + bo
    p.A = att; p.ldA = CDIM; p.sAb = 0; p.sAh = 0;
    p.Bhi = wo_h; p.Blo = wo_l; p.sBb = 0; p.sBh = 0;
    p.C = out; p.ldC = CDIM; p.sCb = 0; p.sCh = 0;
    p.bias = bo; p.K = CDIM; p.Hdiv = 1;
    gemm_bf16x3<<<dim3(CDIM / 128, (CB * CS) / 128, 1), 256>>>(p);
}

// round 5
// speedup vs baseline: 1.2325x; 1.2325x over previous
#include <cuda_runtime.h>
#include <cuda_bf16.h>
#include <cstdint>
#include <cstddef>

#define CB   2
#define CS   4096
#define CL   512
#define CDIM 5120
#define CH   40
#define CHD  128
#define CKV  (2*CDIM)
#define FSCALE 0.08838834764831845f
#define FEPS 1e-6f

// ---------------- static device scratch ----------------
__device__ __nv_bfloat16 g_wq_h [(size_t)CDIM*CDIM];
__device__ __nv_bfloat16 g_wq_l [(size_t)CDIM*CDIM];
__device__ __nv_bfloat16 g_wkv_h[(size_t)CDIM*CKV];
__device__ __nv_bfloat16 g_wkv_l[(size_t)CDIM*CKV];
__device__ __nv_bfloat16 g_wo_h [(size_t)CDIM*CDIM];
__device__ __nv_bfloat16 g_wo_l [(size_t)CDIM*CDIM];
__device__ float         g_q    [(size_t)CB*CS*CDIM];
__device__ float         g_kv   [(size_t)CB*CL*CKV];
__device__ __nv_bfloat16 g_k_h  [(size_t)CB*CH*CL*CHD];
__device__ __nv_bfloat16 g_k_l  [(size_t)CB*CH*CL*CHD];
__device__ __nv_bfloat16 g_v_h  [(size_t)CB*CH*CHD*CL];
__device__ __nv_bfloat16 g_v_l  [(size_t)CB*CH*CHD*CL];
__device__ float         g_sc   [(size_t)CB*CH*CS*CL];
__device__ float         g_att  [(size_t)CB*CS*CDIM];

// ---------------- helpers ----------------
__device__ __forceinline__ uint32_t smem_u32(const void* p) {
    uint32_t a;
    asm("{ .reg .u64 t; cvta.to.shared.u64 t, %1; cvt.u32.u64 %0, t; }" : "=r"(a) : "l"(p));
    return a;
}

__device__ __forceinline__ void split2(float x, float y, uint32_t& hi, uint32_t& lo) {
    __nv_bfloat162 h = __floats2bfloat162_rn(x, y);
    float2 hf = __bfloat1622float2(h);
    __nv_bfloat162 l = __floats2bfloat162_rn(x - hf.x, y - hf.y);
    hi = *reinterpret_cast<uint32_t*>(&h);
    lo = *reinterpret_cast<uint32_t*>(&l);
}

__device__ __forceinline__ void mma16816(float* c, const uint32_t* a, uint32_t b0, uint32_t b1) {
    asm volatile(
        "mma.sync.aligned.m16n8k16.row.col.f32.bf16.bf16.f32 "
        "{%0,%1,%2,%3},{%4,%5,%6,%7},{%8,%9},{%0,%1,%2,%3};\n"
        : "+f"(c[0]), "+f"(c[1]), "+f"(c[2]), "+f"(c[3])
        : "r"(a[0]), "r"(a[1]), "r"(a[2]), "r"(a[3]), "r"(b0), "r"(b1));
}

#define LDSM_X4(r, addr)                                                              \
    asm volatile("ldmatrix.sync.aligned.m8n8.x4.shared.b16 {%0,%1,%2,%3}, [%4];"      \
                 : "=r"((r)[0]), "=r"((r)[1]), "=r"((r)[2]), "=r"((r)[3]) : "r"(addr))

// ---------------- weight transpose + bf16 split:  T[n][k] = W[k][n] ----------------
__global__ void transpose_split(const float* __restrict__ W, __nv_bfloat16* __restrict__ Thi,
                                __nv_bfloat16* __restrict__ Tlo, int K, int N) {
    __shared__ float t[32][33];
    int n0 = blockIdx.x * 32, k0 = blockIdx.y * 32;
    int tx = threadIdx.x, ty = threadIdx.y;
#pragma unroll
    for (int i = 0; i < 32; i += 8)
        t[ty + i][tx] = W[(size_t)(k0 + ty + i) * N + n0 + tx];
    __syncthreads();
#pragma unroll
    for (int i = 0; i < 32; i += 8) {
        float v = t[tx][ty + i];
        __nv_bfloat16 h = __float2bfloat16(v);
        size_t o = (size_t)(n0 + ty + i) * K + k0 + tx;
        Thi[o] = h;
        Tlo[o] = __float2bfloat16(v - __bfloat162float(h));
    }
}

// ---------------- RMSNorm ----------------
__global__ void rmsnorm_rows(float* __restrict__ X, long ld, const float* __restrict__ g) {
    float* row = X + (size_t)blockIdx.x * ld;
    int tid = threadIdx.x;
    float4* r4 = (float4*)row;
    const float4* g4 = (const float4*)g;
    float s = 0.f;
#pragma unroll 5
    for (int i = tid; i < CDIM / 4; i += 256) {
        float4 v = r4[i];
        s += v.x * v.x + v.y * v.y + v.z * v.z + v.w * v.w;
    }
#pragma unroll
    for (int o = 16; o; o >>= 1) s += __shfl_xor_sync(0xffffffffu, s, o);
    __shared__ float ws[8];
    if ((tid & 31) == 0) ws[tid >> 5] = s;
    __syncthreads();
    if (tid == 0) {
        float x = 0.f;
#pragma unroll
        for (int i = 0; i < 8; i++) x += ws[i];
        ws[0] = rsqrtf(x / (float)CDIM + FEPS);
    }
    __syncthreads();
    float rs = ws[0];
#pragma unroll 5
    for (int i = tid; i < CDIM / 4; i += 256) {
        float4 v = r4[i];
        float4 w = g4[i];
        v.x *= rs * w.x; v.y *= rs * w.y; v.z *= rs * w.z; v.w *= rs * w.w;
        r4[i] = v;
    }
}

// ---------------- K split: per-head [ (b*H+h)*L + l ][ d ] ----------------
__global__ void split_k(const float* __restrict__ kv, __nv_bfloat16* __restrict__ h,
                        __nv_bfloat16* __restrict__ l) {
    size_t i = (size_t)blockIdx.x * 256 + threadIdx.x;
    if (i >= (size_t)CB * CH * CL * CHD) return;
    int d = (int)(i & 127);
    size_t r = i >> 7;
    int ll = (int)(r & 511); r >>= 9;
    int hh = (int)(r % CH);
    int b  = (int)(r / CH);
    float v = kv[((size_t)(b * CL + ll)) * CKV + hh * CHD + d];
    __nv_bfloat16 x = __float2bfloat16(v);
    h[i] = x;
    l[i] = __float2bfloat16(v - __bfloat162float(x));
}

// ---------------- V split transposed: [ (b*H+h)*D + d ][ l ] ----------------
__global__ void split_v(const float* __restrict__ kv, __nv_bfloat16* __restrict__ h,
                        __nv_bfloat16* __restrict__ l) {
    size_t i = (size_t)blockIdx.x * 256 + threadIdx.x;
    if (i >= (size_t)CB * CH * CHD * CL) return;
    int ll = (int)(i & 511);
    size_t r = i >> 9;
    int d = (int)(r & 127); r >>= 7;
    int hh = (int)(r % CH);
    int b  = (int)(r / CH);
    float v = kv[((size_t)(b * CL + ll)) * CKV + CDIM + hh * CHD + d];
    __nv_bfloat16 x = __float2bfloat16(v);
    h[i] = x;
    l[i] = __float2bfloat16(v - __bfloat162float(x));
}

// ---------------- softmax rows of 512 ----------------
__global__ void softmax512(float* __restrict__ X) {
    int warp = threadIdx.x >> 5, lane = threadIdx.x & 31;
    size_t row = (size_t)blockIdx.x * 8 + warp;
    float4* p = (float4*)(X + row * CL);
    float4 v[4];
    float mx = -1e30f;
#pragma unroll
    for (int i = 0; i < 4; i++) {
        v[i] = p[lane + 32 * i];
        v[i].x *= FSCALE; v[i].y *= FSCALE; v[i].z *= FSCALE; v[i].w *= FSCALE;
        mx = fmaxf(mx, fmaxf(fmaxf(v[i].x, v[i].y), fmaxf(v[i].z, v[i].w)));
    }
#pragma unroll
    for (int o = 16; o; o >>= 1) mx = fmaxf(mx, __shfl_xor_sync(0xffffffffu, mx, o));
    float s = 0.f;
#pragma unroll
    for (int i = 0; i < 4; i++) {
        v[i].x = __expf(v[i].x - mx); v[i].y = __expf(v[i].y - mx);
        v[i].z = __expf(v[i].z - mx); v[i].w = __expf(v[i].w - mx);
        s += v[i].x + v[i].y + v[i].z + v[i].w;
    }
#pragma unroll
    for (int o = 16; o; o >>= 1) s += __shfl_xor_sync(0xffffffffu, s, o);
    float inv = 1.f / s;
#pragma unroll
    for (int i = 0; i < 4; i++) {
        v[i].x *= inv; v[i].y *= inv; v[i].z *= inv; v[i].w *= inv;
        p[lane + 32 * i] = v[i];
    }
}

// ---------------- bf16x3 GEMM with ldmatrix feeds + double buffer ----------------
// C = A(fp32) @ B(split bf16 [N][K])^T + bias ; tile 128x128, BK=32.
// smem per buffer: 4 tiles (Ahi,Alo,Bhi,Blo) of 128 rows x 80B (pitch 20 words).
struct GP {
    const float* A;  long ldA, sAb, sAh;
    const __nv_bfloat16 *Bhi, *Blo;  long sBb, sBh;
    float* C;  long ldC, sCb, sCh;
    const float* bias;
    int K, Hdiv;
};

#define TPITCHW 20
#define TILE_B  (128 * 80)          // 10240 bytes per tile
#define BUF_B   (4 * TILE_B)        // 40960 bytes per buffer
#define GEMM_SMEM_BYTES (2 * BUF_B) // 81920

extern __shared__ uint32_t dsm[];

__global__ __launch_bounds__(256) void gemm_tc(GP p) {
    uint32_t sbase = smem_u32(dsm);

    int tid = threadIdx.x, lane = tid & 31, wp = tid >> 5;
    int wm = wp >> 1, wn = wp & 1;
    int arow = tid >> 3, acv = tid & 7;   // A loader
    int brow = tid >> 2, bcv = tid & 3;   // B loader

    int z = blockIdx.z, bb = z / p.Hdiv, hh = z % p.Hdiv;
    const float* A = p.A + (size_t)bb * p.sAb + (size_t)hh * p.sAh +
                     (size_t)blockIdx.y * 128 * p.ldA;
    const __nv_bfloat16* Bh = p.Bhi + (size_t)bb * p.sBb + (size_t)hh * p.sBh +
                              (size_t)blockIdx.x * 128 * p.K;
    const __nv_bfloat16* Bl = p.Blo + (size_t)bb * p.sBb + (size_t)hh * p.sBh +
                              (size_t)blockIdx.x * 128 * p.K;

    float acc[2][8][4];
#pragma unroll
    for (int mi = 0; mi < 2; mi++)
#pragma unroll
        for (int nj = 0; nj < 8; nj++)
#pragma unroll
            for (int q = 0; q < 4; q++) acc[mi][nj][q] = 0.f;

    float4 ra[4];
    uint4 rbh[2], rbl[2];
    int nk = p.K / 32;

    // ldmatrix per-lane address components
    int lrowA = (lane & 7) + ((lane >> 3) & 1) * 8;   // A: lanes 0-15 rows, 16-31 k-half
    int kselA = ((lane >> 4) & 1) * 16;
    int lrowB = (lane & 7) + ((lane >> 4) & 1) * 8;   // B: lanes 0-15 n-blk0, 16-31 n-blk1
    int kselB = ((lane >> 3) & 1) * 16;

    auto ldTile = [&](int kt) {
#pragma unroll
        for (int i = 0; i < 4; i++)
            ra[i] = *(const float4*)(A + (size_t)(arow + 32 * i) * p.ldA + kt * 32 + acv * 4);
#pragma unroll
        for (int i = 0; i < 2; i++) {
            rbh[i] = *(const uint4*)(Bh + (size_t)(brow + 64 * i) * p.K + kt * 32 + bcv * 8);
            rbl[i] = *(const uint4*)(Bl + (size_t)(brow + 64 * i) * p.K + kt * 32 + bcv * 8);
        }
    };
    auto stTile = [&](int buf) {
        uint32_t* wAhi = dsm + (buf * BUF_B) / 4;
        uint32_t* wAlo = wAhi + TILE_B / 4;
        uint32_t* wBhi = wAlo + TILE_B / 4;
        uint32_t* wBlo = wBhi + TILE_B / 4;
#pragma unroll
        for (int i = 0; i < 4; i++) {
            int r = arow + 32 * i;
            uint32_t h0, l0, h1, l1;
            split2(ra[i].x, ra[i].y, h0, l0);
            split2(ra[i].z, ra[i].w, h1, l1);
            wAhi[r * TPITCHW + acv * 2] = h0; wAhi[r * TPITCHW + acv * 2 + 1] = h1;
            wAlo[r * TPITCHW + acv * 2] = l0; wAlo[r * TPITCHW + acv * 2 + 1] = l1;
        }
#pragma unroll
        for (int i = 0; i < 2; i++) {
            int r = brow + 64 * i;
            uint32_t* d0 = &wBhi[r * TPITCHW + bcv * 4];
            d0[0] = rbh[i].x; d0[1] = rbh[i].y; d0[2] = rbh[i].z; d0[3] = rbh[i].w;
            uint32_t* d1 = &wBlo[r * TPITCHW + bcv * 4];
            d1[0] = rbl[i].x; d1[1] = rbl[i].y; d1[2] = rbl[i].z; d1[3] = rbl[i].w;
        }
    };
    auto compute = [&](int buf) {
        uint32_t aHi = sbase + buf * BUF_B;
        uint32_t aLo = aHi + TILE_B;
        uint32_t bHi = aLo + TILE_B;
        uint32_t bLo = bHi + TILE_B;
        uint32_t aAddrH[2], aAddrL[2], bAddrH[4], bAddrL[4];
#pragma unroll
        for (int mi = 0; mi < 2; mi++) {
            uint32_t ro = (uint32_t)(wm * 32 + mi * 16 + lrowA) * 80 + kselA;
            aAddrH[mi] = aHi + ro;
            aAddrL[mi] = aLo + ro;
        }
#pragma unroll
        for (int njp = 0; njp < 4; njp++) {
            uint32_t ro = (uint32_t)(wn * 64 + njp * 16 + lrowB) * 80 + kselB;
            bAddrH[njp] = bHi + ro;
            bAddrL[njp] = bLo + ro;
        }
#pragma unroll
        for (int kk = 0; kk < 2; kk++) {
            uint32_t ko = kk * 32;
            uint32_t ah[2][4], al[2][4], bh[4][4], bl[4][4];
#pragma unroll
            for (int mi = 0; mi < 2; mi++) {
                LDSM_X4(ah[mi], aAddrH[mi] + ko);
                LDSM_X4(al[mi], aAddrL[mi] + ko);
            }
#pragma unroll
            for (int njp = 0; njp < 4; njp++) {
                LDSM_X4(bh[njp], bAddrH[njp] + ko);
                LDSM_X4(bl[njp], bAddrL[njp] + ko);
            }
#pragma unroll
            for (int njp = 0; njp < 4; njp++)
#pragma unroll
                for (int sub = 0; sub < 2; sub++) {
                    int nj = njp * 2 + sub;
                    uint32_t b0h = bh[njp][sub * 2], b1h = bh[njp][sub * 2 + 1];
                    uint32_t b0l = bl[njp][sub * 2], b1l = bl[njp][sub * 2 + 1];
#pragma unroll
                    for (int mi = 0; mi < 2; mi++) {
                        mma16816(acc[mi][nj], ah[mi], b0h, b1h);
                        mma16816(acc[mi][nj], al[mi], b0h, b1h);
                        mma16816(acc[mi][nj], ah[mi], b0l, b1l);
                    }
                }
        }
    };

    ldTile(0);
    stTile(0);
    __syncthreads();

    for (int kt = 0; kt < nk; kt++) {
        if (kt + 1 < nk) ldTile(kt + 1);
        compute(kt & 1);
        if (kt + 1 < nk) stTile((kt + 1) & 1);
        __syncthreads();
    }

    float* C = p.C + (size_t)bb * p.sCb + (size_t)hh * p.sCh +
               (size_t)blockIdx.y * 128 * p.ldC + (size_t)blockIdx.x * 128;
#pragma unroll
    for (int nj = 0; nj < 8; nj++) {
        int c = wn * 64 + nj * 8 + ((lane & 3) << 1);
        float b0 = 0.f, b1 = 0.f;
        if (p.bias) {
            size_t cg = (size_t)blockIdx.x * 128 + c;
            b0 = p.bias[cg];
            b1 = p.bias[cg + 1];
        }
#pragma unroll
        for (int mi = 0; mi < 2; mi++) {
            int r = wm * 32 + mi * 16 + (lane >> 2);
            float2 v0 = make_float2(acc[mi][nj][0] + b0, acc[mi][nj][1] + b1);
            float2 v1 = make_float2(acc[mi][nj][2] + b0, acc[mi][nj][3] + b1);
            *(float2*)&C[(size_t)r * p.ldC + c] = v0;
            *(float2*)&C[(size_t)(r + 8) * p.ldC + c] = v1;
        }
    }
}

// ---------------- host launcher ----------------
extern "C" void kernel_launch(void* const* d_in, const int* in_sizes, int n_in,
                              void* d_out, int out_size) {
    (void)in_sizes; (void)n_in; (void)out_size;
    const float* hid = (const float*)d_in[0];
    const float* ctx = (const float*)d_in[1];
    const float* Wq  = (const float*)d_in[2];
    const float* bq  = (const float*)d_in[3];
    const float* Wkv = (const float*)d_in[4];
    const float* bkv = (const float*)d_in[5];
    const float* gq  = (const float*)d_in[6];
    const float* gk  = (const float*)d_in[7];
    const float* Wo  = (const float*)d_in[8];
    const float* bo  = (const float*)d_in[9];
    float* out = (float*)d_out;

    __nv_bfloat16 *wq_h, *wq_l, *wkv_h, *wkv_l, *wo_h, *wo_l, *k_h, *k_l, *v_h, *v_l;
    float *q, *kv, *sc, *att;
    cudaGetSymbolAddress((void**)&wq_h, g_wq_h);
    cudaGetSymbolAddress((void**)&wq_l, g_wq_l);
    cudaGetSymbolAddress((void**)&wkv_h, g_wkv_h);
    cudaGetSymbolAddress((void**)&wkv_l, g_wkv_l);
    cudaGetSymbolAddress((void**)&wo_h, g_wo_h);
    cudaGetSymbolAddress((void**)&wo_l, g_wo_l);
    cudaGetSymbolAddress((void**)&k_h, g_k_h);
    cudaGetSymbolAddress((void**)&k_l, g_k_l);
    cudaGetSymbolAddress((void**)&v_h, g_v_h);
    cudaGetSymbolAddress((void**)&v_l, g_v_l);
    cudaGetSymbolAddress((void**)&q, g_q);
    cudaGetSymbolAddress((void**)&kv, g_kv);
    cudaGetSymbolAddress((void**)&sc, g_sc);
    cudaGetSymbolAddress((void**)&att, g_att);

    cudaFuncSetAttribute(gemm_tc, cudaFuncAttributeMaxDynamicSharedMemorySize,
                         GEMM_SMEM_BYTES);

    dim3 tb(32, 8);
    transpose_split<<<dim3(CDIM / 32, CDIM / 32), tb>>>(Wq, wq_h, wq_l, CDIM, CDIM);
    transpose_split<<<dim3(CKV / 32, CDIM / 32), tb>>>(Wkv, wkv_h, wkv_l, CDIM, CKV);
    transpose_split<<<dim3(CDIM / 32, CDIM / 32), tb>>>(Wo, wo_h, wo_l, CDIM, CDIM);

    GP p{};

    // Q = hidden @ Wq + bq
    p.A = hid; p.ldA = CDIM; p.sAb = 0; p.sAh = 0;
    p.Bhi = wq_h; p.Blo = wq_l; p.sBb = 0; p.sBh = 0;
    p.C = q; p.ldC = CDIM; p.sCb = 0; p.sCh = 0;
    p.bias = bq; p.K = CDIM; p.Hdiv = 1;
    gemm_tc<<<dim3(CDIM / 128, (CB * CS) / 128, 1), 256, GEMM_SMEM_BYTES>>>(p);

    rmsnorm_rows<<<CB * CS, 256>>>(q, CDIM, gq);

    // KV = context @ Wkv + bkv
    p.A = ctx; p.ldA = CDIM; p.sAb = 0; p.sAh = 0;
    p.Bhi = wkv_h; p.Blo = wkv_l; p.sBb = 0; p.sBh = 0;
    p.C = kv; p.ldC = CKV; p.sCb = 0; p.sCh = 0;
    p.bias = bkv; p.K = CDIM; p.Hdiv = 1;
    gemm_tc<<<dim3(CKV / 128, (CB * CL) / 128, 1), 256, GEMM_SMEM_BYTES>>>(p);

    rmsnorm_rows<<<CB * CL, 256>>>(kv, CKV, gk);

    {
        size_t nK = (size_t)CB * CH * CL * CHD;
        split_k<<<(unsigned)((nK + 255) / 256), 256>>>(kv, k_h, k_l);
        split_v<<<(unsigned)((nK + 255) / 256), 256>>>(kv, v_h, v_l);
    }

    // scores[b,h] = q_bh @ k_bh^T   (M=S, N=L, K=D=128)
    p.A = q; p.ldA = CDIM; p.sAb = (long)CS * CDIM; p.sAh = CHD;
    p.Bhi = k_h; p.Blo = k_l; p.sBb = (long)CH * CL * CHD; p.sBh = (long)CL * CHD;
    p.C = sc; p.ldC = CL; p.sCb = (long)CH * CS * CL; p.sCh = (long)CS * CL;
    p.bias = nullptr; p.K = CHD; p.Hdiv = CH;
    gemm_tc<<<dim3(CL / 128, CS / 128, CB * CH), 256, GEMM_SMEM_BYTES>>>(p);

    softmax512<<<(CB * CH * CS) / 8, 256>>>(sc);

    // att[b,h] = probs @ v_bh      (M=S, N=D=128, K=L=512)
    p.A = sc; p.ldA = CL; p.sAb = (long)CH * CS * CL; p.sAh = (long)CS * CL;
    p.Bhi = v_h; p.Blo = v_l; p.sBb = (long)CH * CHD * CL; p.sBh = (long)CHD * CL;
    p.C = att; p.ldC = CDIM; p.sCb = (long)CS * CDIM; p.sCh = CHD;
    p.bias = nullptr; p.K = CL; p.Hdiv = CH;
    gemm_tc<<<dim3(CHD / 128, CS / 128, CB * CH), 256, GEMM_SMEM_BYTES>>>(p);

    // out = att @ Wo + bo
    p.A = att; p.ldA = CDIM; p.sAb = 0; p.sAh = 0;
    p.Bhi = wo_h; p.Blo = wo_l; p.sBb = 0; p.sBh = 0;
    p.C = out; p.ldC = CDIM; p.sCb = 0; p.sCh = 0;
    p.bias = bo; p.K = CDIM; p.Hdiv = 1;
    gemm_tc<<<dim3(CDIM / 128, (CB * CS) / 128, 1), 256, GEMM_SMEM_BYTES>>>(p);
}

// round 6
// speedup vs baseline: 1.5662x; 1.2707x over previous
#include <cuda_runtime.h>
#include <cuda_bf16.h>
#include <cstdint>
#include <cstddef>

#define CB   2
#define CS   4096
#define CL   512
#define CDIM 5120
#define CH   40
#define CHD  128
#define CKV  (2*CDIM)
#define FSCALE 0.08838834764831845f
#define FEPS 1e-6f

// ---------------- static device scratch ----------------
__device__ __nv_bfloat16 g_wq_h [(size_t)CDIM*CDIM];
__device__ __nv_bfloat16 g_wq_l [(size_t)CDIM*CDIM];
__device__ __nv_bfloat16 g_wkv_h[(size_t)CDIM*CKV];
__device__ __nv_bfloat16 g_wkv_l[(size_t)CDIM*CKV];
__device__ __nv_bfloat16 g_wo_h [(size_t)CDIM*CDIM];
__device__ __nv_bfloat16 g_wo_l [(size_t)CDIM*CDIM];
__device__ float         g_q    [(size_t)CB*CS*CDIM];
__device__ float         g_kv   [(size_t)CB*CL*CKV];
__device__ __nv_bfloat16 g_k_h  [(size_t)CB*CH*CL*CHD];
__device__ __nv_bfloat16 g_k_l  [(size_t)CB*CH*CL*CHD];
__device__ __nv_bfloat16 g_v_h  [(size_t)CB*CH*CHD*CL];
__device__ __nv_bfloat16 g_v_l  [(size_t)CB*CH*CHD*CL];
__device__ float         g_sc   [(size_t)CB*CH*CS*CL];
__device__ float         g_att  [(size_t)CB*CS*CDIM];

// ---------------- helpers ----------------
__device__ __forceinline__ uint32_t smem_u32(const void* p) {
    uint32_t a;
    asm("{ .reg .u64 t; cvta.to.shared.u64 t, %1; cvt.u32.u64 %0, t; }" : "=r"(a) : "l"(p));
    return a;
}

__device__ __forceinline__ void split2(float x, float y, uint32_t& hi, uint32_t& lo) {
    __nv_bfloat162 h = __floats2bfloat162_rn(x, y);
    float2 hf = __bfloat1622float2(h);
    __nv_bfloat162 l = __floats2bfloat162_rn(x - hf.x, y - hf.y);
    hi = *reinterpret_cast<uint32_t*>(&h);
    lo = *reinterpret_cast<uint32_t*>(&l);
}

__device__ __forceinline__ void mma16816(float* c, const uint32_t* a, uint32_t b0, uint32_t b1) {
    asm volatile(
        "mma.sync.aligned.m16n8k16.row.col.f32.bf16.bf16.f32 "
        "{%0,%1,%2,%3},{%4,%5,%6,%7},{%8,%9},{%0,%1,%2,%3};\n"
        : "+f"(c[0]), "+f"(c[1]), "+f"(c[2]), "+f"(c[3])
        : "r"(a[0]), "r"(a[1]), "r"(a[2]), "r"(a[3]), "r"(b0), "r"(b1));
}

#define LDSM_X4(r, addr)                                                              \
    asm volatile("ldmatrix.sync.aligned.m8n8.x4.shared.b16 {%0,%1,%2,%3}, [%4];"      \
                 : "=r"((r)[0]), "=r"((r)[1]), "=r"((r)[2]), "=r"((r)[3]) : "r"(addr))

#define CP_ASYNC16(dst, src) \
    asm volatile("cp.async.ca.shared.global [%0], [%1], 16;\n" :: "r"(dst), "l"(src))
#define CP_COMMIT() asm volatile("cp.async.commit_group;\n" ::: "memory")
#define CP_WAIT0()  asm volatile("cp.async.wait_group 0;\n" ::: "memory")

// ---------------- weight transpose + bf16 split:  T[n][k] = W[k][n] ----------------
__global__ void transpose_split(const float* __restrict__ W, __nv_bfloat16* __restrict__ Thi,
                                __nv_bfloat16* __restrict__ Tlo, int K, int N) {
    __shared__ float t[32][33];
    int n0 = blockIdx.x * 32, k0 = blockIdx.y * 32;
    int tx = threadIdx.x, ty = threadIdx.y;
#pragma unroll
    for (int i = 0; i < 32; i += 8)
        t[ty + i][tx] = W[(size_t)(k0 + ty + i) * N + n0 + tx];
    __syncthreads();
#pragma unroll
    for (int i = 0; i < 32; i += 8) {
        float v = t[tx][ty + i];
        __nv_bfloat16 h = __float2bfloat16(v);
        size_t o = (size_t)(n0 + ty + i) * K + k0 + tx;
        Thi[o] = h;
        Tlo[o] = __float2bfloat16(v - __bfloat162float(h));
    }
}

// ---------------- RMSNorm ----------------
__global__ void rmsnorm_rows(float* __restrict__ X, long ld, const float* __restrict__ g) {
    float* row = X + (size_t)blockIdx.x * ld;
    int tid = threadIdx.x;
    float4* r4 = (float4*)row;
    const float4* g4 = (const float4*)g;
    float s = 0.f;
#pragma unroll 5
    for (int i = tid; i < CDIM / 4; i += 256) {
        float4 v = r4[i];
        s += v.x * v.x + v.y * v.y + v.z * v.z + v.w * v.w;
    }
#pragma unroll
    for (int o = 16; o; o >>= 1) s += __shfl_xor_sync(0xffffffffu, s, o);
    __shared__ float ws[8];
    if ((tid & 31) == 0) ws[tid >> 5] = s;
    __syncthreads();
    if (tid == 0) {
        float x = 0.f;
#pragma unroll
        for (int i = 0; i < 8; i++) x += ws[i];
        ws[0] = rsqrtf(x / (float)CDIM + FEPS);
    }
    __syncthreads();
    float rs = ws[0];
#pragma unroll 5
    for (int i = tid; i < CDIM / 4; i += 256) {
        float4 v = r4[i];
        float4 w = g4[i];
        v.x *= rs * w.x; v.y *= rs * w.y; v.z *= rs * w.z; v.w *= rs * w.w;
        r4[i] = v;
    }
}

// ---------------- K split: per-head [ (b*H+h)*L + l ][ d ] ----------------
__global__ void split_k(const float* __restrict__ kv, __nv_bfloat16* __restrict__ h,
                        __nv_bfloat16* __restrict__ l) {
    size_t i = (size_t)blockIdx.x * 256 + threadIdx.x;
    if (i >= (size_t)CB * CH * CL * CHD) return;
    int d = (int)(i & 127);
    size_t r = i >> 7;
    int ll = (int)(r & 511); r >>= 9;
    int hh = (int)(r % CH);
    int b  = (int)(r / CH);
    float v = kv[((size_t)(b * CL + ll)) * CKV + hh * CHD + d];
    __nv_bfloat16 x = __float2bfloat16(v);
    h[i] = x;
    l[i] = __float2bfloat16(v - __bfloat162float(x));
}

// ---------------- V split transposed: [ (b*H+h)*D + d ][ l ] ----------------
__global__ void split_v(const float* __restrict__ kv, __nv_bfloat16* __restrict__ h,
                        __nv_bfloat16* __restrict__ l) {
    size_t i = (size_t)blockIdx.x * 256 + threadIdx.x;
    if (i >= (size_t)CB * CH * CHD * CL) return;
    int ll = (int)(i & 511);
    size_t r = i >> 9;
    int d = (int)(r & 127); r >>= 7;
    int hh = (int)(r % CH);
    int b  = (int)(r / CH);
    float v = kv[((size_t)(b * CL + ll)) * CKV + CDIM + hh * CHD + d];
    __nv_bfloat16 x = __float2bfloat16(v);
    h[i] = x;
    l[i] = __float2bfloat16(v - __bfloat162float(x));
}

// ---------------- softmax rows of 512 ----------------
__global__ void softmax512(float* __restrict__ X) {
    int warp = threadIdx.x >> 5, lane = threadIdx.x & 31;
    size_t row = (size_t)blockIdx.x * 8 + warp;
    float4* p = (float4*)(X + row * CL);
    float4 v[4];
    float mx = -1e30f;
#pragma unroll
    for (int i = 0; i < 4; i++) {
        v[i] = p[lane + 32 * i];
        v[i].x *= FSCALE; v[i].y *= FSCALE; v[i].z *= FSCALE; v[i].w *= FSCALE;
        mx = fmaxf(mx, fmaxf(fmaxf(v[i].x, v[i].y), fmaxf(v[i].z, v[i].w)));
    }
#pragma unroll
    for (int o = 16; o; o >>= 1) mx = fmaxf(mx, __shfl_xor_sync(0xffffffffu, mx, o));
    float s = 0.f;
#pragma unroll
    for (int i = 0; i < 4; i++) {
        v[i].x = __expf(v[i].x - mx); v[i].y = __expf(v[i].y - mx);
        v[i].z = __expf(v[i].z - mx); v[i].w = __expf(v[i].w - mx);
        s += v[i].x + v[i].y + v[i].z + v[i].w;
    }
#pragma unroll
    for (int o = 16; o; o >>= 1) s += __shfl_xor_sync(0xffffffffu, s, o);
    float inv = 1.f / s;
#pragma unroll
    for (int i = 0; i < 4; i++) {
        v[i].x *= inv; v[i].y *= inv; v[i].z *= inv; v[i].w *= inv;
        p[lane + 32 * i] = v[i];
    }
}

// ---------------- bf16x3 GEMM: ldmatrix feeds, cp.async B, 2 CTAs/SM ----------------
struct GP {
    const float* A;  long ldA, sAb, sAh;
    const __nv_bfloat16 *Bhi, *Blo;  long sBb, sBh;
    float* C;  long ldC, sCb, sCh;
    const float* bias;
    int K, Hdiv;
};

#define TPITCHW 20
#define TILE_B  (128 * 80)          // 10240 bytes per tile
#define BUF_B   (4 * TILE_B)        // 40960 bytes per buffer
#define GEMM_SMEM_BYTES (2 * BUF_B) // 81920

extern __shared__ uint32_t dsm[];

__global__ __launch_bounds__(256, 2) void gemm_tc(GP p) {
    uint32_t sbase = smem_u32(dsm);

    int tid = threadIdx.x, lane = tid & 31, wp = tid >> 5;
    int wm = wp >> 1, wn = wp & 1;
    int arow = tid >> 3, acv = tid & 7;   // A loader
    int brow = tid >> 2, bch = tid & 3;   // B cp.async: row brow(+64), 16B chunk bch

    int z = blockIdx.z, bb = z / p.Hdiv, hh = z % p.Hdiv;
    const float* A = p.A + (size_t)bb * p.sAb + (size_t)hh * p.sAh +
                     (size_t)blockIdx.y * 128 * p.ldA;
    const __nv_bfloat16* Bh = p.Bhi + (size_t)bb * p.sBb + (size_t)hh * p.sBh +
                              (size_t)blockIdx.x * 128 * p.K;
    const __nv_bfloat16* Bl = p.Blo + (size_t)bb * p.sBb + (size_t)hh * p.sBh +
                              (size_t)blockIdx.x * 128 * p.K;

    float acc[2][8][4];
#pragma unroll
    for (int mi = 0; mi < 2; mi++)
#pragma unroll
        for (int nj = 0; nj < 8; nj++)
#pragma unroll
            for (int q = 0; q < 4; q++) acc[mi][nj][q] = 0.f;

    float4 ra[4];
    int nk = p.K / 32;

    // ldmatrix per-lane address components
    int lrowA = (lane & 7) + ((lane >> 3) & 1) * 8;
    int kselA = ((lane >> 4) & 1) * 16;
    int lrowB = (lane & 7) + ((lane >> 4) & 1) * 8;
    int kselB = ((lane >> 3) & 1) * 16;

    auto ldA = [&](int kt) {
#pragma unroll
        for (int i = 0; i < 4; i++)
            ra[i] = *(const float4*)(A + (size_t)(arow + 32 * i) * p.ldA + kt * 32 + acv * 4);
    };
    auto stA = [&](int buf) {
        uint32_t* wAhi = dsm + (buf * BUF_B) / 4;
        uint32_t* wAlo = wAhi + TILE_B / 4;
#pragma unroll
        for (int i = 0; i < 4; i++) {
            int r = arow + 32 * i;
            uint32_t h0, l0, h1, l1;
            split2(ra[i].x, ra[i].y, h0, l0);
            split2(ra[i].z, ra[i].w, h1, l1);
            wAhi[r * TPITCHW + acv * 2] = h0; wAhi[r * TPITCHW + acv * 2 + 1] = h1;
            wAlo[r * TPITCHW + acv * 2] = l0; wAlo[r * TPITCHW + acv * 2 + 1] = l1;
        }
    };
    auto cpB = [&](int kt, int buf) {
        uint32_t bHi = sbase + buf * BUF_B + 2 * TILE_B;
        uint32_t bLo = bHi + TILE_B;
        const __nv_bfloat16* Bhk = Bh + kt * 32;
        const __nv_bfloat16* Blk = Bl + kt * 32;
#pragma unroll
        for (int i = 0; i < 2; i++) {
            int r = brow + 64 * i;
            uint32_t doff = (uint32_t)r * 80 + bch * 16;
            size_t soff = (size_t)r * p.K + bch * 8;
            CP_ASYNC16(bHi + doff, Bhk + soff);
            CP_ASYNC16(bLo + doff, Blk + soff);
        }
    };
    auto compute = [&](int buf) {
        uint32_t aHi = sbase + buf * BUF_B;
        uint32_t aLo = aHi + TILE_B;
        uint32_t bHi = aLo + TILE_B;
        uint32_t bLo = bHi + TILE_B;
        uint32_t aAddrH[2], aAddrL[2], bAddrH[4], bAddrL[4];
#pragma unroll
        for (int mi = 0; mi < 2; mi++) {
            uint32_t ro = (uint32_t)(wm * 32 + mi * 16 + lrowA) * 80 + kselA;
            aAddrH[mi] = aHi + ro;
            aAddrL[mi] = aLo + ro;
        }
#pragma unroll
        for (int njp = 0; njp < 4; njp++) {
            uint32_t ro = (uint32_t)(wn * 64 + njp * 16 + lrowB) * 80 + kselB;
            bAddrH[njp] = bHi + ro;
            bAddrL[njp] = bLo + ro;
        }
#pragma unroll
        for (int kk = 0; kk < 2; kk++) {
            uint32_t ko = kk * 32;
            uint32_t ah[2][4], al[2][4];
#pragma unroll
            for (int mi = 0; mi < 2; mi++) {
                LDSM_X4(ah[mi], aAddrH[mi] + ko);
                LDSM_X4(al[mi], aAddrL[mi] + ko);
            }
#pragma unroll
            for (int njp = 0; njp < 4; njp++) {
                uint32_t bhf[4], blf[4];
                LDSM_X4(bhf, bAddrH[njp] + ko);
                LDSM_X4(blf, bAddrL[njp] + ko);
#pragma unroll
                for (int sub = 0; sub < 2; sub++) {
                    int nj = njp * 2 + sub;
                    uint32_t b0h = bhf[sub * 2], b1h = bhf[sub * 2 + 1];
                    uint32_t b0l = blf[sub * 2], b1l = blf[sub * 2 + 1];
#pragma unroll
                    for (int mi = 0; mi < 2; mi++) {
                        mma16816(acc[mi][nj], ah[mi], b0h, b1h);
                        mma16816(acc[mi][nj], al[mi], b0h, b1h);
                        mma16816(acc[mi][nj], ah[mi], b0l, b1l);
                    }
                }
            }
        }
    };

    ldA(0);
    cpB(0, 0);
    CP_COMMIT();
    stA(0);
    CP_WAIT0();
    __syncthreads();

    for (int kt = 0; kt < nk; kt++) {
        if (kt + 1 < nk) {
            ldA(kt + 1);
            cpB(kt + 1, (kt + 1) & 1);
            CP_COMMIT();
        }
        compute(kt & 1);
        if (kt + 1 < nk) stA((kt + 1) & 1);
        CP_WAIT0();
        __syncthreads();
    }

    float* C = p.C + (size_t)bb * p.sCb + (size_t)hh * p.sCh +
               (size_t)blockIdx.y * 128 * p.ldC + (size_t)blockIdx.x * 128;
#pragma unroll
    for (int nj = 0; nj < 8; nj++) {
        int c = wn * 64 + nj * 8 + ((lane & 3) << 1);
        float b0 = 0.f, b1 = 0.f;
        if (p.bias) {
            size_t cg = (size_t)blockIdx.x * 128 + c;
            b0 = p.bias[cg];
            b1 = p.bias[cg + 1];
        }
#pragma unroll
        for (int mi = 0; mi < 2; mi++) {
            int r = wm * 32 + mi * 16 + (lane >> 2);
            float2 v0 = make_float2(acc[mi][nj][0] + b0, acc[mi][nj][1] + b1);
            float2 v1 = make_float2(acc[mi][nj][2] + b0, acc[mi][nj][3] + b1);
            *(float2*)&C[(size_t)r * p.ldC + c] = v0;
            *(float2*)&C[(size_t)(r + 8) * p.ldC + c] = v1;
        }
    }
}

// ---------------- host launcher ----------------
extern "C" void kernel_launch(void* const* d_in, const int* in_sizes, int n_in,
                              void* d_out, int out_size) {
    (void)in_sizes; (void)n_in; (void)out_size;
    const float* hid = (const float*)d_in[0];
    const float* ctx = (const float*)d_in[1];
    const float* Wq  = (const float*)d_in[2];
    const float* bq  = (const float*)d_in[3];
    const float* Wkv = (const float*)d_in[4];
    const float* bkv = (const float*)d_in[5];
    const float* gq  = (const float*)d_in[6];
    const float* gk  = (const float*)d_in[7];
    const float* Wo  = (const float*)d_in[8];
    const float* bo  = (const float*)d_in[9];
    float* out = (float*)d_out;

    __nv_bfloat16 *wq_h, *wq_l, *wkv_h, *wkv_l, *wo_h, *wo_l, *k_h, *k_l, *v_h, *v_l;
    float *q, *kv, *sc, *att;
    cudaGetSymbolAddress((void**)&wq_h, g_wq_h);
    cudaGetSymbolAddress((void**)&wq_l, g_wq_l);
    cudaGetSymbolAddress((void**)&wkv_h, g_wkv_h);
    cudaGetSymbolAddress((void**)&wkv_l, g_wkv_l);
    cudaGetSymbolAddress((void**)&wo_h, g_wo_h);
    cudaGetSymbolAddress((void**)&wo_l, g_wo_l);
    cudaGetSymbolAddress((void**)&k_h, g_k_h);
    cudaGetSymbolAddress((void**)&k_l, g_k_l);
    cudaGetSymbolAddress((void**)&v_h, g_v_h);
    cudaGetSymbolAddress((void**)&v_l, g_v_l);
    cudaGetSymbolAddress((void**)&q, g_q);
    cudaGetSymbolAddress((void**)&kv, g_kv);
    cudaGetSymbolAddress((void**)&sc, g_sc);
    cudaGetSymbolAddress((void**)&att, g_att);

    cudaFuncSetAttribute(gemm_tc, cudaFuncAttributeMaxDynamicSharedMemorySize,
                         GEMM_SMEM_BYTES);

    dim3 tb(32, 8);
    transpose_split<<<dim3(CDIM / 32, CDIM / 32), tb>>>(Wq, wq_h, wq_l, CDIM, CDIM);
    transpose_split<<<dim3(CKV / 32, CDIM / 32), tb>>>(Wkv, wkv_h, wkv_l, CDIM, CKV);
    transpose_split<<<dim3(CDIM / 32, CDIM / 32), tb>>>(Wo, wo_h, wo_l, CDIM, CDIM);

    GP p{};

    // Q = hidden @ Wq + bq
    p.A = hid; p.ldA = CDIM; p.sAb = 0; p.sAh = 0;
    p.Bhi = wq_h; p.Blo = wq_l; p.sBb = 0; p.sBh = 0;
    p.C = q; p.ldC = CDIM; p.sCb = 0; p.sCh = 0;
    p.bias = bq; p.K = CDIM; p.Hdiv = 1;
    gemm_tc<<<dim3(CDIM / 128, (CB * CS) / 128, 1), 256, GEMM_SMEM_BYTES>>>(p);

    rmsnorm_rows<<<CB * CS, 256>>>(q, CDIM, gq);

    // KV = context @ Wkv + bkv
    p.A = ctx; p.ldA = CDIM; p.sAb = 0; p.sAh = 0;
    p.Bhi = wkv_h; p.Blo = wkv_l; p.sBb = 0; p.sBh = 0;
    p.C = kv; p.ldC = CKV; p.sCb = 0; p.sCh = 0;
    p.bias = bkv; p.K = CDIM; p.Hdiv = 1;
    gemm_tc<<<dim3(CKV / 128, (CB * CL) / 128, 1), 256, GEMM_SMEM_BYTES>>>(p);

    rmsnorm_rows<<<CB * CL, 256>>>(kv, CKV, gk);

    {
        size_t nK = (size_t)CB * CH * CL * CHD;
        split_k<<<(unsigned)((nK + 255) / 256), 256>>>(kv, k_h, k_l);
        split_v<<<(unsigned)((nK + 255) / 256), 256>>>(kv, v_h, v_l);
    }

    // scores[b,h] = q_bh @ k_bh^T   (M=S, N=L, K=D=128)
    p.A = q; p.ldA = CDIM; p.sAb = (long)CS * CDIM; p.sAh = CHD;
    p.Bhi = k_h; p.Blo = k_l; p.sBb = (long)CH * CL * CHD; p.sBh = (long)CL * CHD;
    p.C = sc; p.ldC = CL; p.sCb = (long)CH * CS * CL; p.sCh = (long)CS * CL;
    p.bias = nullptr; p.K = CHD; p.Hdiv = CH;
    gemm_tc<<<dim3(CL / 128, CS / 128, CB * CH), 256, GEMM_SMEM_BYTES>>>(p);

    softmax512<<<(CB * CH * CS) / 8, 256>>>(sc);

    // att[b,h] = probs @ v_bh      (M=S, N=D=128, K=L=512)
    p.A = sc; p.ldA = CL; p.sAb = (long)CH * CS * CL; p.sAh = (long)CS * CL;
    p.Bhi = v_h; p.Blo = v_l; p.sBb = (long)CH * CHD * CL; p.sBh = (long)CHD * CL;
    p.C = att; p.ldC = CDIM; p.sCb = (long)CS * CDIM; p.sCh = CHD;
    p.bias = nullptr; p.K = CL; p.Hdiv = CH;
    gemm_tc<<<dim3(CHD / 128, CS / 128, CB * CH), 256, GEMM_SMEM_BYTES>>>(p);

    // out = att @ Wo + bo
    p.A = att; p.ldA = CDIM; p.sAb = 0; p.sAh = 0;
    p.Bhi = wo_h; p.Blo = wo_l; p.sBb = 0; p.sBh = 0;
    p.C = out; p.ldC = CDIM; p.sCb = 0; p.sCh = 0;
    p.bias = bo; p.K = CDIM; p.Hdiv = 1;
    gemm_tc<<<dim3(CDIM / 128, (CB * CS) / 128, 1), 256, GEMM_SMEM_BYTES>>>(p);
}

// round 7
// speedup vs baseline: 1.6246x; 1.0373x over previous
#include <cuda_runtime.h>
#include <cuda_bf16.h>
#include <cstdint>
#include <cstddef>

#define CB   2
#define CS   4096
#define CL   512
#define CDIM 5120
#define CH   40
#define CHD  128
#define CKV  (2*CDIM)
#define FSCALE 0.08838834764831845f
#define FEPS 1e-6f

// ---------------- static device scratch ----------------
__device__ __nv_bfloat16 g_wq_h [(size_t)CDIM*CDIM];
__device__ __nv_bfloat16 g_wq_l [(size_t)CDIM*CDIM];
__device__ __nv_bfloat16 g_wkv_h[(size_t)CDIM*CKV];
__device__ __nv_bfloat16 g_wkv_l[(size_t)CDIM*CKV];
__device__ __nv_bfloat16 g_wo_h [(size_t)CDIM*CDIM];
__device__ __nv_bfloat16 g_wo_l [(size_t)CDIM*CDIM];
__device__ __nv_bfloat16 g_hid_h[(size_t)CB*CS*CDIM];
__device__ __nv_bfloat16 g_hid_l[(size_t)CB*CS*CDIM];
__device__ __nv_bfloat16 g_ctx_h[(size_t)CB*CL*CDIM];
__device__ __nv_bfloat16 g_ctx_l[(size_t)CB*CL*CDIM];
__device__ float         g_q    [(size_t)CB*CS*CDIM];
__device__ __nv_bfloat16 g_qs_h [(size_t)CB*CS*CDIM];
__device__ __nv_bfloat16 g_qs_l [(size_t)CB*CS*CDIM];
__device__ float         g_kv   [(size_t)CB*CL*CKV];
__device__ __nv_bfloat16 g_k_h  [(size_t)CB*CH*CL*CHD];
__device__ __nv_bfloat16 g_k_l  [(size_t)CB*CH*CL*CHD];
__device__ __nv_bfloat16 g_v_h  [(size_t)CB*CH*CHD*CL];
__device__ __nv_bfloat16 g_v_l  [(size_t)CB*CH*CHD*CL];
__device__ float         g_sc   [(size_t)CB*CH*CS*CL];
__device__ __nv_bfloat16 g_pr_h [(size_t)CB*CH*CS*CL];
__device__ __nv_bfloat16 g_pr_l [(size_t)CB*CH*CS*CL];
__device__ __nv_bfloat16 g_att_h[(size_t)CB*CS*CDIM];
__device__ __nv_bfloat16 g_att_l[(size_t)CB*CS*CDIM];

// ---------------- helpers ----------------
__device__ __forceinline__ uint32_t smem_u32(const void* p) {
    uint32_t a;
    asm("{ .reg .u64 t; cvta.to.shared.u64 t, %1; cvt.u32.u64 %0, t; }" : "=r"(a) : "l"(p));
    return a;
}

__device__ __forceinline__ void split2(float x, float y, uint32_t& hi, uint32_t& lo) {
    __nv_bfloat162 h = __floats2bfloat162_rn(x, y);
    float2 hf = __bfloat1622float2(h);
    __nv_bfloat162 l = __floats2bfloat162_rn(x - hf.x, y - hf.y);
    hi = *reinterpret_cast<uint32_t*>(&h);
    lo = *reinterpret_cast<uint32_t*>(&l);
}

__device__ __forceinline__ void mma16816(float* c, const uint32_t* a, uint32_t b0, uint32_t b1) {
    asm volatile(
        "mma.sync.aligned.m16n8k16.row.col.f32.bf16.bf16.f32 "
        "{%0,%1,%2,%3},{%4,%5,%6,%7},{%8,%9},{%0,%1,%2,%3};\n"
        : "+f"(c[0]), "+f"(c[1]), "+f"(c[2]), "+f"(c[3])
        : "r"(a[0]), "r"(a[1]), "r"(a[2]), "r"(a[3]), "r"(b0), "r"(b1));
}

#define LDSM_X4(r, addr)                                                              \
    asm volatile("ldmatrix.sync.aligned.m8n8.x4.shared.b16 {%0,%1,%2,%3}, [%4];"      \
                 : "=r"((r)[0]), "=r"((r)[1]), "=r"((r)[2]), "=r"((r)[3]) : "r"(addr))

#define CP_ASYNC16(dst, src) \
    asm volatile("cp.async.ca.shared.global [%0], [%1], 16;\n" :: "r"(dst), "l"(src))
#define CP_COMMIT() asm volatile("cp.async.commit_group;\n" ::: "memory")
#define CP_WAIT0()  asm volatile("cp.async.wait_group 0;\n" ::: "memory")

// ---------------- weight transpose + bf16 split:  T[n][k] = W[k][n] ----------------
__global__ void transpose_split(const float* __restrict__ W, __nv_bfloat16* __restrict__ Thi,
                                __nv_bfloat16* __restrict__ Tlo, int K, int N) {
    __shared__ float t[32][33];
    int n0 = blockIdx.x * 32, k0 = blockIdx.y * 32;
    int tx = threadIdx.x, ty = threadIdx.y;
#pragma unroll
    for (int i = 0; i < 32; i += 8)
        t[ty + i][tx] = W[(size_t)(k0 + ty + i) * N + n0 + tx];
    __syncthreads();
#pragma unroll
    for (int i = 0; i < 32; i += 8) {
        float v = t[tx][ty + i];
        __nv_bfloat16 h = __float2bfloat16(v);
        size_t o = (size_t)(n0 + ty + i) * K + k0 + tx;
        Thi[o] = h;
        Tlo[o] = __float2bfloat16(v - __bfloat162float(h));
    }
}

// ---------------- elementwise fp32 -> bf16 hi/lo split ----------------
__global__ void split_plain(const float* __restrict__ X, __nv_bfloat16* __restrict__ H,
                            __nv_bfloat16* __restrict__ L, size_t n4) {
    size_t i = (size_t)blockIdx.x * 256 + threadIdx.x;
    if (i >= n4) return;
    float4 v = ((const float4*)X)[i];
    uint32_t h0, l0, h1, l1;
    split2(v.x, v.y, h0, l0);
    split2(v.z, v.w, h1, l1);
    ((uint2*)H)[i] = make_uint2(h0, h1);
    ((uint2*)L)[i] = make_uint2(l0, l1);
}

// ---------------- RMSNorm in place (fp32) ----------------
__global__ void rmsnorm_rows(float* __restrict__ X, long ld, const float* __restrict__ g) {
    float* row = X + (size_t)blockIdx.x * ld;
    int tid = threadIdx.x;
    float4* r4 = (float4*)row;
    const float4* g4 = (const float4*)g;
    float s = 0.f;
#pragma unroll 5
    for (int i = tid; i < CDIM / 4; i += 256) {
        float4 v = r4[i];
        s += v.x * v.x + v.y * v.y + v.z * v.z + v.w * v.w;
    }
#pragma unroll
    for (int o = 16; o; o >>= 1) s += __shfl_xor_sync(0xffffffffu, s, o);
    __shared__ float ws[8];
    if ((tid & 31) == 0) ws[tid >> 5] = s;
    __syncthreads();
    if (tid == 0) {
        float x = 0.f;
#pragma unroll
        for (int i = 0; i < 8; i++) x += ws[i];
        ws[0] = rsqrtf(x / (float)CDIM + FEPS);
    }
    __syncthreads();
    float rs = ws[0];
#pragma unroll 5
    for (int i = tid; i < CDIM / 4; i += 256) {
        float4 v = r4[i];
        float4 w = g4[i];
        v.x *= rs * w.x; v.y *= rs * w.y; v.z *= rs * w.z; v.w *= rs * w.w;
        r4[i] = v;
    }
}

// ---------------- RMSNorm reading fp32, writing split bf16 hi/lo ----------------
__global__ void rmsnorm_split(const float* __restrict__ X, const float* __restrict__ g,
                              __nv_bfloat16* __restrict__ H, __nv_bfloat16* __restrict__ L) {
    const float* row = X + (size_t)blockIdx.x * CDIM;
    int tid = threadIdx.x;
    const float4* r4 = (const float4*)row;
    const float4* g4 = (const float4*)g;
    float s = 0.f;
#pragma unroll 5
    for (int i = tid; i < CDIM / 4; i += 256) {
        float4 v = r4[i];
        s += v.x * v.x + v.y * v.y + v.z * v.z + v.w * v.w;
    }
#pragma unroll
    for (int o = 16; o; o >>= 1) s += __shfl_xor_sync(0xffffffffu, s, o);
    __shared__ float ws[8];
    if ((tid & 31) == 0) ws[tid >> 5] = s;
    __syncthreads();
    if (tid == 0) {
        float x = 0.f;
#pragma unroll
        for (int i = 0; i < 8; i++) x += ws[i];
        ws[0] = rsqrtf(x / (float)CDIM + FEPS);
    }
    __syncthreads();
    float rs = ws[0];
    uint2* Hr = (uint2*)(H + (size_t)blockIdx.x * CDIM);
    uint2* Lr = (uint2*)(L + (size_t)blockIdx.x * CDIM);
#pragma unroll 5
    for (int i = tid; i < CDIM / 4; i += 256) {
        float4 v = r4[i];
        float4 w = g4[i];
        v.x *= rs * w.x; v.y *= rs * w.y; v.z *= rs * w.z; v.w *= rs * w.w;
        uint32_t h0, l0, h1, l1;
        split2(v.x, v.y, h0, l0);
        split2(v.z, v.w, h1, l1);
        Hr[i] = make_uint2(h0, h1);
        Lr[i] = make_uint2(l0, l1);
    }
}

// ---------------- K split: per-head [ (b*H+h)*L + l ][ d ] ----------------
__global__ void split_k(const float* __restrict__ kv, __nv_bfloat16* __restrict__ h,
                        __nv_bfloat16* __restrict__ l) {
    size_t i = (size_t)blockIdx.x * 256 + threadIdx.x;
    if (i >= (size_t)CB * CH * CL * CHD) return;
    int d = (int)(i & 127);
    size_t r = i >> 7;
    int ll = (int)(r & 511); r >>= 9;
    int hh = (int)(r % CH);
    int b  = (int)(r / CH);
    float v = kv[((size_t)(b * CL + ll)) * CKV + hh * CHD + d];
    __nv_bfloat16 x = __float2bfloat16(v);
    h[i] = x;
    l[i] = __float2bfloat16(v - __bfloat162float(x));
}

// ---------------- V split transposed: [ (b*H+h)*D + d ][ l ] ----------------
__global__ void split_v(const float* __restrict__ kv, __nv_bfloat16* __restrict__ h,
                        __nv_bfloat16* __restrict__ l) {
    size_t i = (size_t)blockIdx.x * 256 + threadIdx.x;
    if (i >= (size_t)CB * CH * CHD * CL) return;
    int ll = (int)(i & 511);
    size_t r = i >> 9;
    int d = (int)(r & 127); r >>= 7;
    int hh = (int)(r % CH);
    int b  = (int)(r / CH);
    float v = kv[((size_t)(b * CL + ll)) * CKV + CDIM + hh * CHD + d];
    __nv_bfloat16 x = __float2bfloat16(v);
    h[i] = x;
    l[i] = __float2bfloat16(v - __bfloat162float(x));
}

// ---------------- softmax rows of 512, writes split bf16 probs ----------------
__global__ void softmax512(const float* __restrict__ X, __nv_bfloat16* __restrict__ PH,
                           __nv_bfloat16* __restrict__ PL) {
    int warp = threadIdx.x >> 5, lane = threadIdx.x & 31;
    size_t row = (size_t)blockIdx.x * 8 + warp;
    const float4* p = (const float4*)(X + row * CL);
    float4 v[4];
    float mx = -1e30f;
#pragma unroll
    for (int i = 0; i < 4; i++) {
        v[i] = p[lane + 32 * i];
        v[i].x *= FSCALE; v[i].y *= FSCALE; v[i].z *= FSCALE; v[i].w *= FSCALE;
        mx = fmaxf(mx, fmaxf(fmaxf(v[i].x, v[i].y), fmaxf(v[i].z, v[i].w)));
    }
#pragma unroll
    for (int o = 16; o; o >>= 1) mx = fmaxf(mx, __shfl_xor_sync(0xffffffffu, mx, o));
    float s = 0.f;
#pragma unroll
    for (int i = 0; i < 4; i++) {
        v[i].x = __expf(v[i].x - mx); v[i].y = __expf(v[i].y - mx);
        v[i].z = __expf(v[i].z - mx); v[i].w = __expf(v[i].w - mx);
        s += v[i].x + v[i].y + v[i].z + v[i].w;
    }
#pragma unroll
    for (int o = 16; o; o >>= 1) s += __shfl_xor_sync(0xffffffffu, s, o);
    float inv = 1.f / s;
    uint2* Hr = (uint2*)(PH + row * CL);
    uint2* Lr = (uint2*)(PL + row * CL);
#pragma unroll
    for (int i = 0; i < 4; i++) {
        v[i].x *= inv; v[i].y *= inv; v[i].z *= inv; v[i].w *= inv;
        uint32_t h0, l0, h1, l1;
        split2(v[i].x, v[i].y, h0, l0);
        split2(v[i].z, v[i].w, h1, l1);
        Hr[lane + 32 * i] = make_uint2(h0, h1);
        Lr[lane + 32 * i] = make_uint2(l0, l1);
    }
}

// ---------------- bf16x3 GEMM: all-operand cp.async + ldmatrix, 2 CTAs/SM ----------------
struct GP {
    const __nv_bfloat16 *Ahi, *Alo;  long ldA, sAb, sAh;
    const __nv_bfloat16 *Bhi, *Blo;  long sBb, sBh;
    float* C;  __nv_bfloat16 *Chi, *Clo;  long ldC, sCb, sCh;
    const float* bias;
    int K, Hdiv, splitOut;
};

#define TPITCHW 20
#define TILE_B  (128 * 80)          // 10240 bytes per tile
#define BUF_B   (4 * TILE_B)        // 40960 bytes per buffer
#define GEMM_SMEM_BYTES (2 * BUF_B) // 81920

extern __shared__ uint32_t dsm[];

__global__ __launch_bounds__(256, 2) void gemm_tc(GP p) {
    uint32_t sbase = smem_u32(dsm);

    int tid = threadIdx.x, lane = tid & 31, wp = tid >> 5;
    int wm = wp >> 1, wn = wp & 1;

    int z = blockIdx.z, bb = z / p.Hdiv, hh = z % p.Hdiv;
    const __nv_bfloat16* Ah = p.Ahi + (size_t)bb * p.sAb + (size_t)hh * p.sAh +
                              (size_t)blockIdx.y * 128 * p.ldA;
    const __nv_bfloat16* Al = p.Alo + (size_t)bb * p.sAb + (size_t)hh * p.sAh +
                              (size_t)blockIdx.y * 128 * p.ldA;
    const __nv_bfloat16* Bh = p.Bhi + (size_t)bb * p.sBb + (size_t)hh * p.sBh +
                              (size_t)blockIdx.x * 128 * p.K;
    const __nv_bfloat16* Bl = p.Blo + (size_t)bb * p.sBb + (size_t)hh * p.sBh +
                              (size_t)blockIdx.x * 128 * p.K;

    float acc[2][8][4];
#pragma unroll
    for (int mi = 0; mi < 2; mi++)
#pragma unroll
        for (int nj = 0; nj < 8; nj++)
#pragma unroll
            for (int q = 0; q < 4; q++) acc[mi][nj][q] = 0.f;

    int nk = p.K / 32;

    // loader mapping: 512 16B-chunks per tile; thread handles chunk tid and tid+256
    int r0 = tid >> 2, c0 = tid & 3;          // chunk tid
    int r1 = (tid + 256) >> 2;                // chunk tid+256 (c same)

    // ldmatrix per-lane address components
    int lrowA = (lane & 7) + ((lane >> 3) & 1) * 8;
    int kselA = ((lane >> 4) & 1) * 16;
    int lrowB = (lane & 7) + ((lane >> 4) & 1) * 8;
    int kselB = ((lane >> 3) & 1) * 16;

    auto cpAll = [&](int kt, int buf) {
        uint32_t base = sbase + buf * BUF_B;
        long ka = (long)kt * 32 + c0 * 8;
        uint32_t d0 = (uint32_t)r0 * 80 + c0 * 16;
        uint32_t d1 = (uint32_t)r1 * 80 + c0 * 16;
        CP_ASYNC16(base + d0,              Ah + (size_t)r0 * p.ldA + ka);
        CP_ASYNC16(base + d1,              Ah + (size_t)r1 * p.ldA + ka);
        CP_ASYNC16(base + TILE_B + d0,     Al + (size_t)r0 * p.ldA + ka);
        CP_ASYNC16(base + TILE_B + d1,     Al + (size_t)r1 * p.ldA + ka);
        CP_ASYNC16(base + 2 * TILE_B + d0, Bh + (size_t)r0 * p.K + ka);
        CP_ASYNC16(base + 2 * TILE_B + d1, Bh + (size_t)r1 * p.K + ka);
        CP_ASYNC16(base + 3 * TILE_B + d0, Bl + (size_t)r0 * p.K + ka);
        CP_ASYNC16(base + 3 * TILE_B + d1, Bl + (size_t)r1 * p.K + ka);
    };

    auto compute = [&](int buf) {
        uint32_t aHi = sbase + buf * BUF_B;
        uint32_t aLo = aHi + TILE_B;
        uint32_t bHi = aLo + TILE_B;
        uint32_t bLo = bHi + TILE_B;
        uint32_t aAddrH[2], aAddrL[2], bAddrH[4], bAddrL[4];
#pragma unroll
        for (int mi = 0; mi < 2; mi++) {
            uint32_t ro = (uint32_t)(wm * 32 + mi * 16 + lrowA) * 80 + kselA;
            aAddrH[mi] = aHi + ro;
            aAddrL[mi] = aLo + ro;
        }
#pragma unroll
        for (int njp = 0; njp < 4; njp++) {
            uint32_t ro = (uint32_t)(wn * 64 + njp * 16 + lrowB) * 80 + kselB;
            bAddrH[njp] = bHi + ro;
            bAddrL[njp] = bLo + ro;
        }
#pragma unroll
        for (int kk = 0; kk < 2; kk++) {
            uint32_t ko = kk * 32;
            uint32_t ah[2][4], al[2][4];
#pragma unroll
            for (int mi = 0; mi < 2; mi++) {
                LDSM_X4(ah[mi], aAddrH[mi] + ko);
                LDSM_X4(al[mi], aAddrL[mi] + ko);
            }
#pragma unroll
            for (int njp = 0; njp < 4; njp++) {
                uint32_t bhf[4], blf[4];
                LDSM_X4(bhf, bAddrH[njp] + ko);
                LDSM_X4(blf, bAddrL[njp] + ko);
#pragma unroll
                for (int sub = 0; sub < 2; sub++) {
                    int nj = njp * 2 + sub;
                    uint32_t b0h = bhf[sub * 2], b1h = bhf[sub * 2 + 1];
                    uint32_t b0l = blf[sub * 2], b1l = blf[sub * 2 + 1];
#pragma unroll
                    for (int mi = 0; mi < 2; mi++) {
                        mma16816(acc[mi][nj], ah[mi], b0h, b1h);
                        mma16816(acc[mi][nj], al[mi], b0h, b1h);
                        mma16816(acc[mi][nj], ah[mi], b0l, b1l);
                    }
                }
            }
        }
    };

    cpAll(0, 0);
    CP_COMMIT();
    CP_WAIT0();
    __syncthreads();

    for (int kt = 0; kt < nk; kt++) {
        if (kt + 1 < nk) {
            cpAll(kt + 1, (kt + 1) & 1);
            CP_COMMIT();
        }
        compute(kt & 1);
        CP_WAIT0();
        __syncthreads();
    }

    size_t cbase = (size_t)bb * p.sCb + (size_t)hh * p.sCh +
                   (size_t)blockIdx.y * 128 * p.ldC + (size_t)blockIdx.x * 128;
    if (!p.splitOut) {
        float* C = p.C + cbase;
#pragma unroll
        for (int nj = 0; nj < 8; nj++) {
            int c = wn * 64 + nj * 8 + ((lane & 3) << 1);
            float b0 = 0.f, b1 = 0.f;
            if (p.bias) {
                size_t cg = (size_t)blockIdx.x * 128 + c;
                b0 = p.bias[cg];
                b1 = p.bias[cg + 1];
            }
#pragma unroll
            for (int mi = 0; mi < 2; mi++) {
                int r = wm * 32 + mi * 16 + (lane >> 2);
                *(float2*)&C[(size_t)r * p.ldC + c] =
                    make_float2(acc[mi][nj][0] + b0, acc[mi][nj][1] + b1);
                *(float2*)&C[(size_t)(r + 8) * p.ldC + c] =
                    make_float2(acc[mi][nj][2] + b0, acc[mi][nj][3] + b1);
            }
        }
    } else {
        __nv_bfloat16* Ch = p.Chi + cbase;
        __nv_bfloat16* Cl = p.Clo + cbase;
#pragma unroll
        for (int nj = 0; nj < 8; nj++) {
            int c = wn * 64 + nj * 8 + ((lane & 3) << 1);
#pragma unroll
            for (int mi = 0; mi < 2; mi++) {
                int r = wm * 32 + mi * 16 + (lane >> 2);
                uint32_t h0, l0, h1, l1;
                split2(acc[mi][nj][0], acc[mi][nj][1], h0, l0);
                split2(acc[mi][nj][2], acc[mi][nj][3], h1, l1);
                *(uint32_t*)&Ch[(size_t)r * p.ldC + c] = h0;
                *(uint32_t*)&Cl[(size_t)r * p.ldC + c] = l0;
                *(uint32_t*)&Ch[(size_t)(r + 8) * p.ldC + c] = h1;
                *(uint32_t*)&Cl[(size_t)(r + 8) * p.ldC + c] = l1;
            }
        }
    }
}

// ---------------- host launcher ----------------
extern "C" void kernel_launch(void* const* d_in, const int* in_sizes, int n_in,
                              void* d_out, int out_size) {
    (void)in_sizes; (void)n_in; (void)out_size;
    const float* hid = (const float*)d_in[0];
    const float* ctx = (const float*)d_in[1];
    const float* Wq  = (const float*)d_in[2];
    const float* bq  = (const float*)d_in[3];
    const float* Wkv = (const float*)d_in[4];
    const float* bkv = (const float*)d_in[5];
    const float* gq  = (const float*)d_in[6];
    const float* gk  = (const float*)d_in[7];
    const float* Wo  = (const float*)d_in[8];
    const float* bo  = (const float*)d_in[9];
    float* out = (float*)d_out;

    __nv_bfloat16 *wq_h, *wq_l, *wkv_h, *wkv_l, *wo_h, *wo_l;
    __nv_bfloat16 *hid_h, *hid_l, *ctx_h, *ctx_l, *qs_h, *qs_l;
    __nv_bfloat16 *k_h, *k_l, *v_h, *v_l, *pr_h, *pr_l, *att_h, *att_l;
    float *q, *kv, *sc;
    cudaGetSymbolAddress((void**)&wq_h, g_wq_h);
    cudaGetSymbolAddress((void**)&wq_l, g_wq_l);
    cudaGetSymbolAddress((void**)&wkv_h, g_wkv_h);
    cudaGetSymbolAddress((void**)&wkv_l, g_wkv_l);
    cudaGetSymbolAddress((void**)&wo_h, g_wo_h);
    cudaGetSymbolAddress((void**)&wo_l, g_wo_l);
    cudaGetSymbolAddress((void**)&hid_h, g_hid_h);
    cudaGetSymbolAddress((void**)&hid_l, g_hid_l);
    cudaGetSymbolAddress((void**)&ctx_h, g_ctx_h);
    cudaGetSymbolAddress((void**)&ctx_l, g_ctx_l);
    cudaGetSymbolAddress((void**)&qs_h, g_qs_h);
    cudaGetSymbolAddress((void**)&qs_l, g_qs_l);
    cudaGetSymbolAddress((void**)&k_h, g_k_h);
    cudaGetSymbolAddress((void**)&k_l, g_k_l);
    cudaGetSymbolAddress((void**)&v_h, g_v_h);
    cudaGetSymbolAddress((void**)&v_l, g_v_l);
    cudaGetSymbolAddress((void**)&pr_h, g_pr_h);
    cudaGetSymbolAddress((void**)&pr_l, g_pr_l);
    cudaGetSymbolAddress((void**)&att_h, g_att_h);
    cudaGetSymbolAddress((void**)&att_l, g_att_l);
    cudaGetSymbolAddress((void**)&q, g_q);
    cudaGetSymbolAddress((void**)&kv, g_kv);
    cudaGetSymbolAddress((void**)&sc, g_sc);

    cudaFuncSetAttribute(gemm_tc, cudaFuncAttributeMaxDynamicSharedMemorySize,
                         GEMM_SMEM_BYTES);

    dim3 tb(32, 8);
    transpose_split<<<dim3(CDIM / 32, CDIM / 32), tb>>>(Wq, wq_h, wq_l, CDIM, CDIM);
    transpose_split<<<dim3(CKV / 32, CDIM / 32), tb>>>(Wkv, wkv_h, wkv_l, CDIM, CKV);
    transpose_split<<<dim3(CDIM / 32, CDIM / 32), tb>>>(Wo, wo_h, wo_l, CDIM, CDIM);

    {
        size_t n4 = (size_t)CB * CS * CDIM / 4;
        split_plain<<<(unsigned)((n4 + 255) / 256), 256>>>(hid, hid_h, hid_l, n4);
        size_t m4 = (size_t)CB * CL * CDIM / 4;
        split_plain<<<(unsigned)((m4 + 255) / 256), 256>>>(ctx, ctx_h, ctx_l, m4);
    }

    GP p{};

    // Q = hidden @ Wq + bq  -> fp32 q
    p.Ahi = hid_h; p.Alo = hid_l; p.ldA = CDIM; p.sAb = 0; p.sAh = 0;
    p.Bhi = wq_h; p.Blo = wq_l; p.sBb = 0; p.sBh = 0;
    p.C = q; p.Chi = nullptr; p.Clo = nullptr; p.ldC = CDIM; p.sCb = 0; p.sCh = 0;
    p.bias = bq; p.K = CDIM; p.Hdiv = 1; p.splitOut = 0;
    gemm_tc<<<dim3(CDIM / 128, (CB * CS) / 128, 1), 256, GEMM_SMEM_BYTES>>>(p);

    rmsnorm_split<<<CB * CS, 256>>>(q, gq, qs_h, qs_l);

    // KV = context @ Wkv + bkv -> fp32 kv
    p.Ahi = ctx_h; p.Alo = ctx_l; p.ldA = CDIM; p.sAb = 0; p.sAh = 0;
    p.Bhi = wkv_h; p.Blo = wkv_l; p.sBb = 0; p.sBh = 0;
    p.C = kv; p.ldC = CKV; p.sCb = 0; p.sCh = 0;
    p.bias = bkv; p.K = CDIM; p.Hdiv = 1; p.splitOut = 0;
    gemm_tc<<<dim3(CKV / 128, (CB * CL) / 128, 1), 256, GEMM_SMEM_BYTES>>>(p);

    rmsnorm_rows<<<CB * CL, 256>>>(kv, CKV, gk);

    {
        size_t nK = (size_t)CB * CH * CL * CHD;
        split_k<<<(unsigned)((nK + 255) / 256), 256>>>(kv, k_h, k_l);
        split_v<<<(unsigned)((nK + 255) / 256), 256>>>(kv, v_h, v_l);
    }

    // scores = q @ k^T  (M=S, N=L, K=128) -> fp32 sc
    p.Ahi = qs_h; p.Alo = qs_l; p.ldA = CDIM; p.sAb = (long)CS * CDIM; p.sAh = CHD;
    p.Bhi = k_h; p.Blo = k_l; p.sBb = (long)CH * CL * CHD; p.sBh = (long)CL * CHD;
    p.C = sc; p.ldC = CL; p.sCb = (long)CH * CS * CL; p.sCh = (long)CS * CL;
    p.bias = nullptr; p.K = CHD; p.Hdiv = CH; p.splitOut = 0;
    gemm_tc<<<dim3(CL / 128, CS / 128, CB * CH), 256, GEMM_SMEM_BYTES>>>(p);

    softmax512<<<(CB * CH * CS) / 8, 256>>>(sc, pr_h, pr_l);

    // att = probs @ v  (M=S, N=128, K=L) -> split bf16 att
    p.Ahi = pr_h; p.Alo = pr_l; p.ldA = CL; p.sAb = (long)CH * CS * CL; p.sAh = (long)CS * CL;
    p.Bhi = v_h; p.Blo = v_l; p.sBb = (long)CH * CHD * CL; p.sBh = (long)CHD * CL;
    p.C = nullptr; p.Chi = att_h; p.Clo = att_l;
    p.ldC = CDIM; p.sCb = (long)CS * CDIM; p.sCh = CHD;
    p.bias = nullptr; p.K = CL; p.Hdiv = CH; p.splitOut = 1;
    gemm_tc<<<dim3(CHD / 128, CS / 128, CB * CH), 256, GEMM_SMEM_BYTES>>>(p);

    // out = att @ Wo + bo
    p.Ahi = att_h; p.Alo = att_l; p.ldA = CDIM; p.sAb = 0; p.sAh = 0;
    p.Bhi = wo_h; p.Blo = wo_l; p.sBb = 0; p.sBh = 0;
    p.C = out; p.Chi = nullptr; p.Clo = nullptr; p.ldC = CDIM; p.sCb = 0; p.sCh = 0;
    p.bias = bo; p.K = CDIM; p.Hdiv = 1; p.splitOut = 0;
    gemm_tc<<<dim3(CDIM / 128, (CB * CS) / 128, 1), 256, GEMM_SMEM_BYTES>>>(p);
}

// round 8
// speedup vs baseline: 1.6639x; 1.0242x over previous
#include <cuda_runtime.h>
#include <cuda_bf16.h>
#include <cstdint>
#include <cstddef>

#define CB   2
#define CS   4096
#define CL   512
#define CDIM 5120
#define CH   40
#define CHD  128
#define CKV  (2*CDIM)
#define FSCALE 0.08838834764831845f
#define FEPS 1e-6f

// ---------------- static device scratch ----------------
__device__ __nv_bfloat16 g_wq_h [(size_t)CDIM*CDIM];
__device__ __nv_bfloat16 g_wq_l [(size_t)CDIM*CDIM];
__device__ __nv_bfloat16 g_wkv_h[(size_t)CDIM*CKV];
__device__ __nv_bfloat16 g_wkv_l[(size_t)CDIM*CKV];
__device__ __nv_bfloat16 g_wo_h [(size_t)CDIM*CDIM];
__device__ __nv_bfloat16 g_wo_l [(size_t)CDIM*CDIM];
__device__ __nv_bfloat16 g_hid_h[(size_t)CB*CS*CDIM];
__device__ __nv_bfloat16 g_hid_l[(size_t)CB*CS*CDIM];
__device__ __nv_bfloat16 g_ctx_h[(size_t)CB*CL*CDIM];
__device__ __nv_bfloat16 g_ctx_l[(size_t)CB*CL*CDIM];
__device__ float         g_q    [(size_t)CB*CS*CDIM];
__device__ __nv_bfloat16 g_qs_h [(size_t)CB*CS*CDIM];
__device__ __nv_bfloat16 g_qs_l [(size_t)CB*CS*CDIM];
__device__ float         g_kv   [(size_t)CB*CL*CKV];
__device__ __nv_bfloat16 g_k_h  [(size_t)CB*CH*CL*CHD];
__device__ __nv_bfloat16 g_k_l  [(size_t)CB*CH*CL*CHD];
__device__ __nv_bfloat16 g_v_h  [(size_t)CB*CH*CHD*CL];
__device__ __nv_bfloat16 g_v_l  [(size_t)CB*CH*CHD*CL];
__device__ __nv_bfloat16 g_att_h[(size_t)CB*CS*CDIM];
__device__ __nv_bfloat16 g_att_l[(size_t)CB*CS*CDIM];

// ---------------- helpers ----------------
__device__ __forceinline__ uint32_t smem_u32(const void* p) {
    uint32_t a;
    asm("{ .reg .u64 t; cvta.to.shared.u64 t, %1; cvt.u32.u64 %0, t; }" : "=r"(a) : "l"(p));
    return a;
}

__device__ __forceinline__ void split2(float x, float y, uint32_t& hi, uint32_t& lo) {
    __nv_bfloat162 h = __floats2bfloat162_rn(x, y);
    float2 hf = __bfloat1622float2(h);
    __nv_bfloat162 l = __floats2bfloat162_rn(x - hf.x, y - hf.y);
    hi = *reinterpret_cast<uint32_t*>(&h);
    lo = *reinterpret_cast<uint32_t*>(&l);
}

__device__ __forceinline__ void mma16816(float* c, const uint32_t* a, uint32_t b0, uint32_t b1) {
    asm volatile(
        "mma.sync.aligned.m16n8k16.row.col.f32.bf16.bf16.f32 "
        "{%0,%1,%2,%3},{%4,%5,%6,%7},{%8,%9},{%0,%1,%2,%3};\n"
        : "+f"(c[0]), "+f"(c[1]), "+f"(c[2]), "+f"(c[3])
        : "r"(a[0]), "r"(a[1]), "r"(a[2]), "r"(a[3]), "r"(b0), "r"(b1));
}

#define LDSM_X4(r, addr)                                                              \
    asm volatile("ldmatrix.sync.aligned.m8n8.x4.shared.b16 {%0,%1,%2,%3}, [%4];"      \
                 : "=r"((r)[0]), "=r"((r)[1]), "=r"((r)[2]), "=r"((r)[3]) : "r"(addr))

#define CP_ASYNC16(dst, src) \
    asm volatile("cp.async.ca.shared.global [%0], [%1], 16;\n" :: "r"(dst), "l"(src))
#define CP_COMMIT() asm volatile("cp.async.commit_group;\n" ::: "memory")
#define CP_WAIT0()  asm volatile("cp.async.wait_group 0;\n" ::: "memory")
#define CP_WAIT1()  asm volatile("cp.async.wait_group 1;\n" ::: "memory")

// ---------------- weight transpose + bf16 split:  T[n][k] = W[k][n] ----------------
__global__ void transpose_split(const float* __restrict__ W, __nv_bfloat16* __restrict__ Thi,
                                __nv_bfloat16* __restrict__ Tlo, int K, int N) {
    __shared__ float t[32][33];
    int n0 = blockIdx.x * 32, k0 = blockIdx.y * 32;
    int tx = threadIdx.x, ty = threadIdx.y;
#pragma unroll
    for (int i = 0; i < 32; i += 8)
        t[ty + i][tx] = W[(size_t)(k0 + ty + i) * N + n0 + tx];
    __syncthreads();
#pragma unroll
    for (int i = 0; i < 32; i += 8) {
        float v = t[tx][ty + i];
        __nv_bfloat16 h = __float2bfloat16(v);
        size_t o = (size_t)(n0 + ty + i) * K + k0 + tx;
        Thi[o] = h;
        Tlo[o] = __float2bfloat16(v - __bfloat162float(h));
    }
}

// ---------------- elementwise fp32 -> bf16 hi/lo split ----------------
__global__ void split_plain(const float* __restrict__ X, __nv_bfloat16* __restrict__ H,
                            __nv_bfloat16* __restrict__ L, size_t n4) {
    size_t i = (size_t)blockIdx.x * 256 + threadIdx.x;
    if (i >= n4) return;
    float4 v = ((const float4*)X)[i];
    uint32_t h0, l0, h1, l1;
    split2(v.x, v.y, h0, l0);
    split2(v.z, v.w, h1, l1);
    ((uint2*)H)[i] = make_uint2(h0, h1);
    ((uint2*)L)[i] = make_uint2(l0, l1);
}

// ---------------- RMSNorm in place (fp32) ----------------
__global__ void rmsnorm_rows(float* __restrict__ X, long ld, const float* __restrict__ g) {
    float* row = X + (size_t)blockIdx.x * ld;
    int tid = threadIdx.x;
    float4* r4 = (float4*)row;
    const float4* g4 = (const float4*)g;
    float s = 0.f;
#pragma unroll 5
    for (int i = tid; i < CDIM / 4; i += 256) {
        float4 v = r4[i];
        s += v.x * v.x + v.y * v.y + v.z * v.z + v.w * v.w;
    }
#pragma unroll
    for (int o = 16; o; o >>= 1) s += __shfl_xor_sync(0xffffffffu, s, o);
    __shared__ float ws[8];
    if ((tid & 31) == 0) ws[tid >> 5] = s;
    __syncthreads();
    if (tid == 0) {
        float x = 0.f;
#pragma unroll
        for (int i = 0; i < 8; i++) x += ws[i];
        ws[0] = rsqrtf(x / (float)CDIM + FEPS);
    }
    __syncthreads();
    float rs = ws[0];
#pragma unroll 5
    for (int i = tid; i < CDIM / 4; i += 256) {
        float4 v = r4[i];
        float4 w = g4[i];
        v.x *= rs * w.x; v.y *= rs * w.y; v.z *= rs * w.z; v.w *= rs * w.w;
        r4[i] = v;
    }
}

// ---------------- RMSNorm reading fp32, writing split bf16 hi/lo ----------------
__global__ void rmsnorm_split(const float* __restrict__ X, const float* __restrict__ g,
                              __nv_bfloat16* __restrict__ H, __nv_bfloat16* __restrict__ L) {
    const float* row = X + (size_t)blockIdx.x * CDIM;
    int tid = threadIdx.x;
    const float4* r4 = (const float4*)row;
    const float4* g4 = (const float4*)g;
    float s = 0.f;
#pragma unroll 5
    for (int i = tid; i < CDIM / 4; i += 256) {
        float4 v = r4[i];
        s += v.x * v.x + v.y * v.y + v.z * v.z + v.w * v.w;
    }
#pragma unroll
    for (int o = 16; o; o >>= 1) s += __shfl_xor_sync(0xffffffffu, s, o);
    __shared__ float ws[8];
    if ((tid & 31) == 0) ws[tid >> 5] = s;
    __syncthreads();
    if (tid == 0) {
        float x = 0.f;
#pragma unroll
        for (int i = 0; i < 8; i++) x += ws[i];
        ws[0] = rsqrtf(x / (float)CDIM + FEPS);
    }
    __syncthreads();
    float rs = ws[0];
    uint2* Hr = (uint2*)(H + (size_t)blockIdx.x * CDIM);
    uint2* Lr = (uint2*)(L + (size_t)blockIdx.x * CDIM);
#pragma unroll 5
    for (int i = tid; i < CDIM / 4; i += 256) {
        float4 v = r4[i];
        float4 w = g4[i];
        v.x *= rs * w.x; v.y *= rs * w.y; v.z *= rs * w.z; v.w *= rs * w.w;
        uint32_t h0, l0, h1, l1;
        split2(v.x, v.y, h0, l0);
        split2(v.z, v.w, h1, l1);
        Hr[i] = make_uint2(h0, h1);
        Lr[i] = make_uint2(l0, l1);
    }
}

// ---------------- K split: per-head [ (b*H+h)*L + l ][ d ] ----------------
__global__ void split_k(const float* __restrict__ kv, __nv_bfloat16* __restrict__ h,
                        __nv_bfloat16* __restrict__ l) {
    size_t i = (size_t)blockIdx.x * 256 + threadIdx.x;
    if (i >= (size_t)CB * CH * CL * CHD) return;
    int d = (int)(i & 127);
    size_t r = i >> 7;
    int ll = (int)(r & 511); r >>= 9;
    int hh = (int)(r % CH);
    int b  = (int)(r / CH);
    float v = kv[((size_t)(b * CL + ll)) * CKV + hh * CHD + d];
    __nv_bfloat16 x = __float2bfloat16(v);
    h[i] = x;
    l[i] = __float2bfloat16(v - __bfloat162float(x));
}

// ---------------- V split transposed: [ (b*H+h)*D + d ][ l ] ----------------
__global__ void split_v(const float* __restrict__ kv, __nv_bfloat16* __restrict__ h,
                        __nv_bfloat16* __restrict__ l) {
    size_t i = (size_t)blockIdx.x * 256 + threadIdx.x;
    if (i >= (size_t)CB * CH * CHD * CL) return;
    int ll = (int)(i & 511);
    size_t r = i >> 9;
    int d = (int)(r & 127); r >>= 7;
    int hh = (int)(r % CH);
    int b  = (int)(r / CH);
    float v = kv[((size_t)(b * CL + ll)) * CKV + CDIM + hh * CHD + d];
    __nv_bfloat16 x = __float2bfloat16(v);
    h[i] = x;
    l[i] = __float2bfloat16(v - __bfloat162float(x));
}

// ---------------- bf16x3 GEMM: all-operand cp.async + ldmatrix, 2 CTAs/SM ----------------
struct GP {
    const __nv_bfloat16 *Ahi, *Alo;  long ldA, sAb, sAh;
    const __nv_bfloat16 *Bhi, *Blo;  long sBb, sBh;
    float* C;  __nv_bfloat16 *Chi, *Clo;  long ldC, sCb, sCh;
    const float* bias;
    int K, Hdiv, splitOut;
};

#define TILE_B  (128 * 80)
#define BUF_B   (4 * TILE_B)
#define GEMM_SMEM_BYTES (2 * BUF_B)

extern __shared__ uint32_t dsm[];

__global__ __launch_bounds__(256, 2) void gemm_tc(GP p) {
    uint32_t sbase = smem_u32(dsm);

    int tid = threadIdx.x, lane = tid & 31, wp = tid >> 5;
    int wm = wp >> 1, wn = wp & 1;

    int z = blockIdx.z, bb = z / p.Hdiv, hh = z % p.Hdiv;
    const __nv_bfloat16* Ah = p.Ahi + (size_t)bb * p.sAb + (size_t)hh * p.sAh +
                              (size_t)blockIdx.y * 128 * p.ldA;
    const __nv_bfloat16* Al = p.Alo + (size_t)bb * p.sAb + (size_t)hh * p.sAh +
                              (size_t)blockIdx.y * 128 * p.ldA;
    const __nv_bfloat16* Bh = p.Bhi + (size_t)bb * p.sBb + (size_t)hh * p.sBh +
                              (size_t)blockIdx.x * 128 * p.K;
    const __nv_bfloat16* Bl = p.Blo + (size_t)bb * p.sBb + (size_t)hh * p.sBh +
                              (size_t)blockIdx.x * 128 * p.K;

    float acc[2][8][4];
#pragma unroll
    for (int mi = 0; mi < 2; mi++)
#pragma unroll
        for (int nj = 0; nj < 8; nj++)
#pragma unroll
            for (int q = 0; q < 4; q++) acc[mi][nj][q] = 0.f;

    int nk = p.K / 32;

    int r0 = tid >> 2, c0 = tid & 3;
    int r1 = (tid + 256) >> 2;

    int lrowA = (lane & 7) + ((lane >> 3) & 1) * 8;
    int kselA = ((lane >> 4) & 1) * 16;
    int lrowB = (lane & 7) + ((lane >> 4) & 1) * 8;
    int kselB = ((lane >> 3) & 1) * 16;

    auto cpAll = [&](int kt, int buf) {
        uint32_t base = sbase + buf * BUF_B;
        long ka = (long)kt * 32 + c0 * 8;
        uint32_t d0 = (uint32_t)r0 * 80 + c0 * 16;
        uint32_t d1 = (uint32_t)r1 * 80 + c0 * 16;
        CP_ASYNC16(base + d0,              Ah + (size_t)r0 * p.ldA + ka);
        CP_ASYNC16(base + d1,              Ah + (size_t)r1 * p.ldA + ka);
        CP_ASYNC16(base + TILE_B + d0,     Al + (size_t)r0 * p.ldA + ka);
        CP_ASYNC16(base + TILE_B + d1,     Al + (size_t)r1 * p.ldA + ka);
        CP_ASYNC16(base + 2 * TILE_B + d0, Bh + (size_t)r0 * p.K + ka);
        CP_ASYNC16(base + 2 * TILE_B + d1, Bh + (size_t)r1 * p.K + ka);
        CP_ASYNC16(base + 3 * TILE_B + d0, Bl + (size_t)r0 * p.K + ka);
        CP_ASYNC16(base + 3 * TILE_B + d1, Bl + (size_t)r1 * p.K + ka);
    };

    auto compute = [&](int buf) {
        uint32_t aHi = sbase + buf * BUF_B;
        uint32_t aLo = aHi + TILE_B;
        uint32_t bHi = aLo + TILE_B;
        uint32_t bLo = bHi + TILE_B;
        uint32_t aAddrH[2], aAddrL[2], bAddrH[4], bAddrL[4];
#pragma unroll
        for (int mi = 0; mi < 2; mi++) {
            uint32_t ro = (uint32_t)(wm * 32 + mi * 16 + lrowA) * 80 + kselA;
            aAddrH[mi] = aHi + ro;
            aAddrL[mi] = aLo + ro;
        }
#pragma unroll
        for (int njp = 0; njp < 4; njp++) {
            uint32_t ro = (uint32_t)(wn * 64 + njp * 16 + lrowB) * 80 + kselB;
            bAddrH[njp] = bHi + ro;
            bAddrL[njp] = bLo + ro;
        }
#pragma unroll
        for (int kk = 0; kk < 2; kk++) {
            uint32_t ko = kk * 32;
            uint32_t ah[2][4], al[2][4];
#pragma unroll
            for (int mi = 0; mi < 2; mi++) {
                LDSM_X4(ah[mi], aAddrH[mi] + ko);
                LDSM_X4(al[mi], aAddrL[mi] + ko);
            }
#pragma unroll
            for (int njp = 0; njp < 4; njp++) {
                uint32_t bhf[4], blf[4];
                LDSM_X4(bhf, bAddrH[njp] + ko);
                LDSM_X4(blf, bAddrL[njp] + ko);
#pragma unroll
                for (int sub = 0; sub < 2; sub++) {
                    int nj = njp * 2 + sub;
                    uint32_t b0h = bhf[sub * 2], b1h = bhf[sub * 2 + 1];
                    uint32_t b0l = blf[sub * 2], b1l = blf[sub * 2 + 1];
#pragma unroll
                    for (int mi = 0; mi < 2; mi++) {
                        mma16816(acc[mi][nj], ah[mi], b0h, b1h);
                        mma16816(acc[mi][nj], al[mi], b0h, b1h);
                        mma16816(acc[mi][nj], ah[mi], b0l, b1l);
                    }
                }
            }
        }
    };

    cpAll(0, 0);
    CP_COMMIT();
    CP_WAIT0();
    __syncthreads();

    for (int kt = 0; kt < nk; kt++) {
        if (kt + 1 < nk) {
            cpAll(kt + 1, (kt + 1) & 1);
            CP_COMMIT();
        }
        compute(kt & 1);
        CP_WAIT0();
        __syncthreads();
    }

    size_t cbase = (size_t)bb * p.sCb + (size_t)hh * p.sCh +
                   (size_t)blockIdx.y * 128 * p.ldC + (size_t)blockIdx.x * 128;
    if (!p.splitOut) {
        float* C = p.C + cbase;
#pragma unroll
        for (int nj = 0; nj < 8; nj++) {
            int c = wn * 64 + nj * 8 + ((lane & 3) << 1);
            float b0 = 0.f, b1 = 0.f;
            if (p.bias) {
                size_t cg = (size_t)blockIdx.x * 128 + c;
                b0 = p.bias[cg];
                b1 = p.bias[cg + 1];
            }
#pragma unroll
            for (int mi = 0; mi < 2; mi++) {
                int r = wm * 32 + mi * 16 + (lane >> 2);
                *(float2*)&C[(size_t)r * p.ldC + c] =
                    make_float2(acc[mi][nj][0] + b0, acc[mi][nj][1] + b1);
                *(float2*)&C[(size_t)(r + 8) * p.ldC + c] =
                    make_float2(acc[mi][nj][2] + b0, acc[mi][nj][3] + b1);
            }
        }
    } else {
        __nv_bfloat16* Ch = p.Chi + cbase;
        __nv_bfloat16* Cl = p.Clo + cbase;
#pragma unroll
        for (int nj = 0; nj < 8; nj++) {
            int c = wn * 64 + nj * 8 + ((lane & 3) << 1);
#pragma unroll
            for (int mi = 0; mi < 2; mi++) {
                int r = wm * 32 + mi * 16 + (lane >> 2);
                uint32_t h0, l0, h1, l1;
                split2(acc[mi][nj][0], acc[mi][nj][1], h0, l0);
                split2(acc[mi][nj][2], acc[mi][nj][3], h1, l1);
                *(uint32_t*)&Ch[(size_t)r * p.ldC + c] = h0;
                *(uint32_t*)&Cl[(size_t)r * p.ldC + c] = l0;
                *(uint32_t*)&Ch[(size_t)(r + 8) * p.ldC + c] = h1;
                *(uint32_t*)&Cl[(size_t)(r + 8) * p.ldC + c] = l1;
            }
        }
    }
}

// ---------------- fused flash attention: QK^T -> online softmax -> PV ----------------
// CTA: 128 q-rows x 1 head. L processed in 4 chunks of 128.
// smem tiles pitch 272B (17x16B, conflict-free LDSM). P overwrites the K buffer.
#define FPITCH 272
#define FT_Q   (128 * FPITCH)        // 34816 per tile
#define FK_OFF (2 * FT_Q)            // K hi (then P hi); +FT_Q = lo
#define FV_OFF (4 * FT_Q)
#define FSTF   ((6 * FT_Q) / 4)      // float index of stats
#define F_M    (FSTF)
#define F_L    (FSTF + 128)
#define F_A    (FSTF + 256)
#define F_RMAX (FSTF + 384)          // [128][2]
#define F_RSUM (FSTF + 640)          // [128][2]
#define FLASH_SMEM (6 * FT_Q + 3584)

__global__ __launch_bounds__(256, 1) void flash_attn() {
    uint32_t sb = smem_u32(dsm);
    float* fs = (float*)dsm;
    int tid = threadIdx.x, lane = tid & 31, wp = tid >> 5;
    int wm = wp >> 1, wn = wp & 1;
    int bh = blockIdx.y, b = bh / CH, hh = bh % CH;
    size_t qrow0 = (size_t)b * CS + (size_t)blockIdx.x * 128;

    const __nv_bfloat16* Qh = g_qs_h + qrow0 * CDIM + hh * CHD;
    const __nv_bfloat16* Ql = g_qs_l + qrow0 * CDIM + hh * CHD;
    const __nv_bfloat16* Kh = g_k_h + (size_t)bh * CL * CHD;
    const __nv_bfloat16* Kl = g_k_l + (size_t)bh * CL * CHD;
    const __nv_bfloat16* Vh = g_v_h + (size_t)bh * CHD * CL;
    const __nv_bfloat16* Vl = g_v_l + (size_t)bh * CHD * CL;

    if (tid < 128) {
        fs[F_M + tid] = -1e30f;
        fs[F_L + tid] = 0.f;
    }

    float O[2][8][4];
#pragma unroll
    for (int mi = 0; mi < 2; mi++)
#pragma unroll
        for (int nj = 0; nj < 8; nj++)
#pragma unroll
            for (int q = 0; q < 4; q++) O[mi][nj][q] = 0.f;

    int lrA = (lane & 7) + ((lane >> 3) & 1) * 8;
    int ksA = ((lane >> 4) & 1) * 16;
    int lrB = (lane & 7) + ((lane >> 4) & 1) * 8;
    int ksB = ((lane >> 3) & 1) * 16;

    // load one 128x256B tile (hi or lo) via cp.async
    auto cpT = [&](uint32_t dst, const __nv_bfloat16* src, long stride) {
#pragma unroll
        for (int i = 0; i < 8; i++) {
            int idx = tid + 256 * i;
            int row = idx >> 4, ch = idx & 15;
            CP_ASYNC16(dst + (uint32_t)row * FPITCH + ch * 16,
                       src + (size_t)row * stride + ch * 8);
        }
    };

    cpT(sb, Qh, CDIM);
    cpT(sb + FT_Q, Ql, CDIM);
    cpT(sb + FK_OFF, Kh, CHD);
    cpT(sb + FK_OFF + FT_Q, Kl, CHD);
    CP_COMMIT();
    cpT(sb + FV_OFF, Vh, CL);
    cpT(sb + FV_OFF + FT_Q, Vl, CL);
    CP_COMMIT();

    uint32_t qAH[2], qAL[2];
#pragma unroll
    for (int mi = 0; mi < 2; mi++) {
        uint32_t ro = (uint32_t)(wm * 32 + mi * 16 + lrA) * FPITCH + ksA;
        qAH[mi] = sb + ro;
        qAL[mi] = sb + FT_Q + ro;
    }
    uint32_t nBH[4], nBL[4];   // row offsets for B-side (K or V), base added per use
#pragma unroll
    for (int njp = 0; njp < 4; njp++) {
        uint32_t ro = (uint32_t)(wn * 64 + njp * 16 + lrB) * FPITCH + ksB;
        nBH[njp] = ro;
        nBL[njp] = ro;
    }

    for (int j = 0; j < 4; j++) {
        CP_WAIT1();          // K_j (and Q on j=0) ready; V_j may be in flight
        __syncthreads();

        // ---- QK^T chunk ----
        float acc[2][8][4];
#pragma unroll
        for (int mi = 0; mi < 2; mi++)
#pragma unroll
            for (int nj = 0; nj < 8; nj++)
#pragma unroll
                for (int q = 0; q < 4; q++) acc[mi][nj][q] = 0.f;

#pragma unroll
        for (int ks = 0; ks < 8; ks++) {
            uint32_t ko = ks * 32;
            uint32_t ah[2][4], al[2][4];
#pragma unroll
            for (int mi = 0; mi < 2; mi++) {
                LDSM_X4(ah[mi], qAH[mi] + ko);
                LDSM_X4(al[mi], qAL[mi] + ko);
            }
#pragma unroll
            for (int njp = 0; njp < 4; njp++) {
                uint32_t bhf[4], blf[4];
                LDSM_X4(bhf, sb + FK_OFF + nBH[njp] + ko);
                LDSM_X4(blf, sb + FK_OFF + FT_Q + nBL[njp] + ko);
#pragma unroll
                for (int sub = 0; sub < 2; sub++) {
                    int nj = njp * 2 + sub;
                    uint32_t b0h = bhf[sub * 2], b1h = bhf[sub * 2 + 1];
                    uint32_t b0l = blf[sub * 2], b1l = blf[sub * 2 + 1];
#pragma unroll
                    for (int mi = 0; mi < 2; mi++) {
                        mma16816(acc[mi][nj], ah[mi], b0h, b1h);
                        mma16816(acc[mi][nj], al[mi], b0h, b1h);
                        mma16816(acc[mi][nj], ah[mi], b0l, b1l);
                    }
                }
            }
        }
        // scale
#pragma unroll
        for (int mi = 0; mi < 2; mi++)
#pragma unroll
            for (int nj = 0; nj < 8; nj++)
#pragma unroll
                for (int q = 0; q < 4; q++) acc[mi][nj][q] *= FSCALE;

        __syncthreads();   // all warps done reading K smem (P will overwrite)

        // ---- row max (partial per warp-half, combined via smem) ----
#pragma unroll
        for (int mi = 0; mi < 2; mi++)
#pragma unroll
            for (int h = 0; h < 2; h++) {
                float mx = -1e30f;
#pragma unroll
                for (int nj = 0; nj < 8; nj++)
                    mx = fmaxf(mx, fmaxf(acc[mi][nj][2 * h], acc[mi][nj][2 * h + 1]));
                mx = fmaxf(mx, __shfl_xor_sync(0xffffffffu, mx, 1));
                mx = fmaxf(mx, __shfl_xor_sync(0xffffffffu, mx, 2));
                if ((lane & 3) == 0) {
                    int row = wm * 32 + mi * 16 + (lane >> 2) + h * 8;
                    fs[F_RMAX + row * 2 + wn] = mx;
                }
            }
        __syncthreads();
        if (tid < 128) {
            float mc = fmaxf(fs[F_RMAX + tid * 2], fs[F_RMAX + tid * 2 + 1]);
            float mo = fs[F_M + tid];
            float mn = fmaxf(mo, mc);
            fs[F_M + tid] = mn;
            fs[F_A + tid] = __expf(mo - mn);
        }
        __syncthreads();

        // ---- p = exp(s - m), write P (into K buffer), partial sums, rescale O ----
#pragma unroll
        for (int mi = 0; mi < 2; mi++)
#pragma unroll
            for (int h = 0; h < 2; h++) {
                int row = wm * 32 + mi * 16 + (lane >> 2) + h * 8;
                float mn = fs[F_M + row];
                float al = fs[F_A + row];
                float s = 0.f;
#pragma unroll
                for (int nj = 0; nj < 8; nj++) {
                    float p0 = __expf(acc[mi][nj][2 * h] - mn);
                    float p1 = __expf(acc[mi][nj][2 * h + 1] - mn);
                    s += p0 + p1;
                    uint32_t hw, lw;
                    split2(p0, p1, hw, lw);
                    int c = wn * 64 + nj * 8 + 2 * (lane & 3);
                    uint32_t off = ((uint32_t)row * FPITCH + c * 2) >> 2;
                    dsm[(FK_OFF >> 2) + off] = hw;
                    dsm[((FK_OFF + FT_Q) >> 2) + off] = lw;
                    O[mi][nj][2 * h] *= al;
                    O[mi][nj][2 * h + 1] *= al;
                }
                s += __shfl_xor_sync(0xffffffffu, s, 1);
                s += __shfl_xor_sync(0xffffffffu, s, 2);
                if ((lane & 3) == 0) fs[F_RSUM + row * 2 + wn] = s;
            }
        __syncthreads();
        if (tid < 128)
            fs[F_L + tid] = fs[F_L + tid] * fs[F_A + tid] +
                            fs[F_RSUM + tid * 2] + fs[F_RSUM + tid * 2 + 1];

        CP_WAIT0();          // V_j ready
        __syncthreads();

        // ---- PV chunk: A = P (K buffer), B = V ----
#pragma unroll
        for (int ks = 0; ks < 8; ks++) {
            uint32_t ko = ks * 32;
            uint32_t ah[2][4], al[2][4];
#pragma unroll
            for (int mi = 0; mi < 2; mi++) {
                uint32_t ro = (uint32_t)(wm * 32 + mi * 16 + lrA) * FPITCH + ksA;
                LDSM_X4(ah[mi], sb + FK_OFF + ro + ko);
                LDSM_X4(al[mi], sb + FK_OFF + FT_Q + ro + ko);
            }
#pragma unroll
            for (int njp = 0; njp < 4; njp++) {
                uint32_t bhf[4], blf[4];
                LDSM_X4(bhf, sb + FV_OFF + nBH[njp] + ko);
                LDSM_X4(blf, sb + FV_OFF + FT_Q + nBL[njp] + ko);
#pragma unroll
                for (int sub = 0; sub < 2; sub++) {
                    int nj = njp * 2 + sub;
                    uint32_t b0h = bhf[sub * 2], b1h = bhf[sub * 2 + 1];
                    uint32_t b0l = blf[sub * 2], b1l = blf[sub * 2 + 1];
#pragma unroll
                    for (int mi = 0; mi < 2; mi++) {
                        mma16816(O[mi][nj], ah[mi], b0h, b1h);
                        mma16816(O[mi][nj], al[mi], b0h, b1h);
                        mma16816(O[mi][nj], ah[mi], b0l, b1l);
                    }
                }
            }
        }
        __syncthreads();     // done reading P (K buf) and V before next loads

        if (j < 3) {
            cpT(sb + FK_OFF, Kh + (size_t)(j + 1) * 128 * CHD, CHD);
            cpT(sb + FK_OFF + FT_Q, Kl + (size_t)(j + 1) * 128 * CHD, CHD);
            CP_COMMIT();
            cpT(sb + FV_OFF, Vh + (j + 1) * 128, CL);
            cpT(sb + FV_OFF + FT_Q, Vl + (j + 1) * 128, CL);
            CP_COMMIT();
        }
    }
    __syncthreads();

    // ---- epilogue: att = O / l, split bf16 hi/lo ----
    __nv_bfloat16* Ah = g_att_h + qrow0 * CDIM + hh * CHD;
    __nv_bfloat16* Al = g_att_l + qrow0 * CDIM + hh * CHD;
#pragma unroll
    for (int nj = 0; nj < 8; nj++) {
        int c = wn * 64 + nj * 8 + 2 * (lane & 3);
#pragma unroll
        for (int mi = 0; mi < 2; mi++) {
#pragma unroll
            for (int h = 0; h < 2; h++) {
                int row = wm * 32 + mi * 16 + (lane >> 2) + h * 8;
                float inv = 1.f / fs[F_L + row];
                uint32_t hw, lw;
                split2(O[mi][nj][2 * h] * inv, O[mi][nj][2 * h + 1] * inv, hw, lw);
                *(uint32_t*)&Ah[(size_t)row * CDIM + c] = hw;
                *(uint32_t*)&Al[(size_t)row * CDIM + c] = lw;
            }
        }
    }
}

// ---------------- host launcher ----------------
extern "C" void kernel_launch(void* const* d_in, const int* in_sizes, int n_in,
                              void* d_out, int out_size) {
    (void)in_sizes; (void)n_in; (void)out_size;
    const float* hid = (const float*)d_in[0];
    const float* ctx = (const float*)d_in[1];
    const float* Wq  = (const float*)d_in[2];
    const float* bq  = (const float*)d_in[3];
    const float* Wkv = (const float*)d_in[4];
    const float* bkv = (const float*)d_in[5];
    const float* gq  = (const float*)d_in[6];
    const float* gk  = (const float*)d_in[7];
    const float* Wo  = (const float*)d_in[8];
    const float* bo  = (const float*)d_in[9];
    float* out = (float*)d_out;

    __nv_bfloat16 *wq_h, *wq_l, *wkv_h, *wkv_l, *wo_h, *wo_l;
    __nv_bfloat16 *hid_h, *hid_l, *ctx_h, *ctx_l, *qs_h, *qs_l;
    __nv_bfloat16 *k_h, *k_l, *v_h, *v_l, *att_h, *att_l;
    float *q, *kv;
    cudaGetSymbolAddress((void**)&wq_h, g_wq_h);
    cudaGetSymbolAddress((void**)&wq_l, g_wq_l);
    cudaGetSymbolAddress((void**)&wkv_h, g_wkv_h);
    cudaGetSymbolAddress((void**)&wkv_l, g_wkv_l);
    cudaGetSymbolAddress((void**)&wo_h, g_wo_h);
    cudaGetSymbolAddress((void**)&wo_l, g_wo_l);
    cudaGetSymbolAddress((void**)&hid_h, g_hid_h);
    cudaGetSymbolAddress((void**)&hid_l, g_hid_l);
    cudaGetSymbolAddress((void**)&ctx_h, g_ctx_h);
    cudaGetSymbolAddress((void**)&ctx_l, g_ctx_l);
    cudaGetSymbolAddress((void**)&qs_h, g_qs_h);
    cudaGetSymbolAddress((void**)&qs_l, g_qs_l);
    cudaGetSymbolAddress((void**)&k_h, g_k_h);
    cudaGetSymbolAddress((void**)&k_l, g_k_l);
    cudaGetSymbolAddress((void**)&v_h, g_v_h);
    cudaGetSymbolAddress((void**)&v_l, g_v_l);
    cudaGetSymbolAddress((void**)&att_h, g_att_h);
    cudaGetSymbolAddress((void**)&att_l, g_att_l);
    cudaGetSymbolAddress((void**)&q, g_q);
    cudaGetSymbolAddress((void**)&kv, g_kv);

    cudaFuncSetAttribute(gemm_tc, cudaFuncAttributeMaxDynamicSharedMemorySize,
                         GEMM_SMEM_BYTES);
    cudaFuncSetAttribute(flash_attn, cudaFuncAttributeMaxDynamicSharedMemorySize,
                         FLASH_SMEM);

    dim3 tb(32, 8);
    transpose_split<<<dim3(CDIM / 32, CDIM / 32), tb>>>(Wq, wq_h, wq_l, CDIM, CDIM);
    transpose_split<<<dim3(CKV / 32, CDIM / 32), tb>>>(Wkv, wkv_h, wkv_l, CDIM, CKV);
    transpose_split<<<dim3(CDIM / 32, CDIM / 32), tb>>>(Wo, wo_h, wo_l, CDIM, CDIM);

    {
        size_t n4 = (size_t)CB * CS * CDIM / 4;
        split_plain<<<(unsigned)((n4 + 255) / 256), 256>>>(hid, hid_h, hid_l, n4);
        size_t m4 = (size_t)CB * CL * CDIM / 4;
        split_plain<<<(unsigned)((m4 + 255) / 256), 256>>>(ctx, ctx_h, ctx_l, m4);
    }

    GP p{};

    // Q = hidden @ Wq + bq  -> fp32 q
    p.Ahi = hid_h; p.Alo = hid_l; p.ldA = CDIM; p.sAb = 0; p.sAh = 0;
    p.Bhi = wq_h; p.Blo = wq_l; p.sBb = 0; p.sBh = 0;
    p.C = q; p.Chi = nullptr; p.Clo = nullptr; p.ldC = CDIM; p.sCb = 0; p.sCh = 0;
    p.bias = bq; p.K = CDIM; p.Hdiv = 1; p.splitOut = 0;
    gemm_tc<<<dim3(CDIM / 128, (CB * CS) / 128, 1), 256, GEMM_SMEM_BYTES>>>(p);

    rmsnorm_split<<<CB * CS, 256>>>(q, gq, qs_h, qs_l);

    // KV = context @ Wkv + bkv -> fp32 kv
    p.Ahi = ctx_h; p.Alo = ctx_l; p.ldA = CDIM; p.sAb = 0; p.sAh = 0;
    p.Bhi = wkv_h; p.Blo = wkv_l; p.sBb = 0; p.sBh = 0;
    p.C = kv; p.ldC = CKV; p.sCb = 0; p.sCh = 0;
    p.bias = bkv; p.K = CDIM; p.Hdiv = 1; p.splitOut = 0;
    gemm_tc<<<dim3(CKV / 128, (CB * CL) / 128, 1), 256, GEMM_SMEM_BYTES>>>(p);

    rmsnorm_rows<<<CB * CL, 256>>>(kv, CKV, gk);

    {
        size_t nK = (size_t)CB * CH * CL * CHD;
        split_k<<<(unsigned)((nK + 255) / 256), 256>>>(kv, k_h, k_l);
        split_v<<<(unsigned)((nK + 255) / 256), 256>>>(kv, v_h, v_l);
    }

    // fused attention -> split bf16 att
    flash_attn<<<dim3(CS / 128, CB * CH), 256, FLASH_SMEM>>>();

    // out = att @ Wo + bo
    p.Ahi = att_h; p.Alo = att_l; p.ldA = CDIM; p.sAb = 0; p.sAh = 0;
    p.Bhi = wo_h; p.Blo = wo_l; p.sBb = 0; p.sBh = 0;
    p.C = out; p.Chi = nullptr; p.Clo = nullptr; p.ldC = CDIM; p.sCb = 0; p.sCh = 0;
    p.bias = bo; p.K = CDIM; p.Hdiv = 1; p.splitOut = 0;
    gemm_tc<<<dim3(CDIM / 128, (CB * CS) / 128, 1), 256, GEMM_SMEM_BYTES>>>(p);
}

// round 9
// speedup vs baseline: 1.6939x; 1.0181x over previous
#include <cuda_runtime.h>
#include <cuda_bf16.h>
#include <cstdint>
#include <cstddef>

#define CB   2
#define CS   4096
#define CL   512
#define CDIM 5120
#define CH   40
#define CHD  128
#define CKV  (2*CDIM)
#define FSCALE 0.08838834764831845f
#define FEPS 1e-6f

// ---------------- static device scratch ----------------
__device__ __nv_bfloat16 g_wq_h [(size_t)CDIM*CDIM];
__device__ __nv_bfloat16 g_wq_l [(size_t)CDIM*CDIM];
__device__ __nv_bfloat16 g_wkv_h[(size_t)CDIM*CKV];
__device__ __nv_bfloat16 g_wkv_l[(size_t)CDIM*CKV];
__device__ __nv_bfloat16 g_wo_h [(size_t)CDIM*CDIM];
__device__ __nv_bfloat16 g_wo_l [(size_t)CDIM*CDIM];
__device__ __nv_bfloat16 g_hid_h[(size_t)CB*CS*CDIM];
__device__ __nv_bfloat16 g_hid_l[(size_t)CB*CS*CDIM];
__device__ __nv_bfloat16 g_ctx_h[(size_t)CB*CL*CDIM];
__device__ __nv_bfloat16 g_ctx_l[(size_t)CB*CL*CDIM];
__device__ float         g_q    [(size_t)CB*CS*CDIM];
__device__ __nv_bfloat16 g_qs_h [(size_t)CB*CS*CDIM];
__device__ __nv_bfloat16 g_qs_l [(size_t)CB*CS*CDIM];
__device__ float         g_kv   [(size_t)CB*CL*CKV];
__device__ __nv_bfloat16 g_k_h  [(size_t)CB*CH*CL*CHD];
__device__ __nv_bfloat16 g_k_l  [(size_t)CB*CH*CL*CHD];
__device__ __nv_bfloat16 g_v_h  [(size_t)CB*CH*CHD*CL];
__device__ __nv_bfloat16 g_v_l  [(size_t)CB*CH*CHD*CL];
__device__ __nv_bfloat16 g_att_h[(size_t)CB*CS*CDIM];
__device__ __nv_bfloat16 g_att_l[(size_t)CB*CS*CDIM];

// ---------------- helpers ----------------
__device__ __forceinline__ uint32_t smem_u32(const void* p) {
    uint32_t a;
    asm("{ .reg .u64 t; cvta.to.shared.u64 t, %1; cvt.u32.u64 %0, t; }" : "=r"(a) : "l"(p));
    return a;
}

__device__ __forceinline__ void split2(float x, float y, uint32_t& hi, uint32_t& lo) {
    __nv_bfloat162 h = __floats2bfloat162_rn(x, y);
    float2 hf = __bfloat1622float2(h);
    __nv_bfloat162 l = __floats2bfloat162_rn(x - hf.x, y - hf.y);
    hi = *reinterpret_cast<uint32_t*>(&h);
    lo = *reinterpret_cast<uint32_t*>(&l);
}

__device__ __forceinline__ void mma16816(float* c, const uint32_t* a, uint32_t b0, uint32_t b1) {
    asm volatile(
        "mma.sync.aligned.m16n8k16.row.col.f32.bf16.bf16.f32 "
        "{%0,%1,%2,%3},{%4,%5,%6,%7},{%8,%9},{%0,%1,%2,%3};\n"
        : "+f"(c[0]), "+f"(c[1]), "+f"(c[2]), "+f"(c[3])
        : "r"(a[0]), "r"(a[1]), "r"(a[2]), "r"(a[3]), "r"(b0), "r"(b1));
}

#define LDSM_X4(r, addr)                                                              \
    asm volatile("ldmatrix.sync.aligned.m8n8.x4.shared.b16 {%0,%1,%2,%3}, [%4];"      \
                 : "=r"((r)[0]), "=r"((r)[1]), "=r"((r)[2]), "=r"((r)[3]) : "r"(addr))

#define CP_ASYNC16(dst, src) \
    asm volatile("cp.async.ca.shared.global [%0], [%1], 16;\n" :: "r"(dst), "l"(src))
#define CP_COMMIT() asm volatile("cp.async.commit_group;\n" ::: "memory")
#define CP_WAIT0()  asm volatile("cp.async.wait_group 0;\n" ::: "memory")
#define CP_WAIT1()  asm volatile("cp.async.wait_group 1;\n" ::: "memory")

// ---------------- weight transpose + bf16 split:  T[n][k] = W[k][n] ----------------
__global__ void transpose_split(const float* __restrict__ W, __nv_bfloat16* __restrict__ Thi,
                                __nv_bfloat16* __restrict__ Tlo, int K, int N) {
    __shared__ float t[32][33];
    int n0 = blockIdx.x * 32, k0 = blockIdx.y * 32;
    int tx = threadIdx.x, ty = threadIdx.y;
#pragma unroll
    for (int i = 0; i < 32; i += 8)
        t[ty + i][tx] = W[(size_t)(k0 + ty + i) * N + n0 + tx];
    __syncthreads();
#pragma unroll
    for (int i = 0; i < 32; i += 8) {
        float v = t[tx][ty + i];
        __nv_bfloat16 h = __float2bfloat16(v);
        size_t o = (size_t)(n0 + ty + i) * K + k0 + tx;
        Thi[o] = h;
        Tlo[o] = __float2bfloat16(v - __bfloat162float(h));
    }
}

// ---------------- elementwise fp32 -> bf16 hi/lo split ----------------
__global__ void split_plain(const float* __restrict__ X, __nv_bfloat16* __restrict__ H,
                            __nv_bfloat16* __restrict__ L, size_t n4) {
    size_t i = (size_t)blockIdx.x * 256 + threadIdx.x;
    if (i >= n4) return;
    float4 v = ((const float4*)X)[i];
    uint32_t h0, l0, h1, l1;
    split2(v.x, v.y, h0, l0);
    split2(v.z, v.w, h1, l1);
    ((uint2*)H)[i] = make_uint2(h0, h1);
    ((uint2*)L)[i] = make_uint2(l0, l1);
}

// ---------------- RMSNorm in place (fp32) ----------------
__global__ void rmsnorm_rows(float* __restrict__ X, long ld, const float* __restrict__ g) {
    float* row = X + (size_t)blockIdx.x * ld;
    int tid = threadIdx.x;
    float4* r4 = (float4*)row;
    const float4* g4 = (const float4*)g;
    float s = 0.f;
#pragma unroll 5
    for (int i = tid; i < CDIM / 4; i += 256) {
        float4 v = r4[i];
        s += v.x * v.x + v.y * v.y + v.z * v.z + v.w * v.w;
    }
#pragma unroll
    for (int o = 16; o; o >>= 1) s += __shfl_xor_sync(0xffffffffu, s, o);
    __shared__ float ws[8];
    if ((tid & 31) == 0) ws[tid >> 5] = s;
    __syncthreads();
    if (tid == 0) {
        float x = 0.f;
#pragma unroll
        for (int i = 0; i < 8; i++) x += ws[i];
        ws[0] = rsqrtf(x / (float)CDIM + FEPS);
    }
    __syncthreads();
    float rs = ws[0];
#pragma unroll 5
    for (int i = tid; i < CDIM / 4; i += 256) {
        float4 v = r4[i];
        float4 w = g4[i];
        v.x *= rs * w.x; v.y *= rs * w.y; v.z *= rs * w.z; v.w *= rs * w.w;
        r4[i] = v;
    }
}

// ---------------- RMSNorm reading fp32, writing split bf16 hi/lo ----------------
__global__ void rmsnorm_split(const float* __restrict__ X, const float* __restrict__ g,
                              __nv_bfloat16* __restrict__ H, __nv_bfloat16* __restrict__ L) {
    const float* row = X + (size_t)blockIdx.x * CDIM;
    int tid = threadIdx.x;
    const float4* r4 = (const float4*)row;
    const float4* g4 = (const float4*)g;
    float s = 0.f;
#pragma unroll 5
    for (int i = tid; i < CDIM / 4; i += 256) {
        float4 v = r4[i];
        s += v.x * v.x + v.y * v.y + v.z * v.z + v.w * v.w;
    }
#pragma unroll
    for (int o = 16; o; o >>= 1) s += __shfl_xor_sync(0xffffffffu, s, o);
    __shared__ float ws[8];
    if ((tid & 31) == 0) ws[tid >> 5] = s;
    __syncthreads();
    if (tid == 0) {
        float x = 0.f;
#pragma unroll
        for (int i = 0; i < 8; i++) x += ws[i];
        ws[0] = rsqrtf(x / (float)CDIM + FEPS);
    }
    __syncthreads();
    float rs = ws[0];
    uint2* Hr = (uint2*)(H + (size_t)blockIdx.x * CDIM);
    uint2* Lr = (uint2*)(L + (size_t)blockIdx.x * CDIM);
#pragma unroll 5
    for (int i = tid; i < CDIM / 4; i += 256) {
        float4 v = r4[i];
        float4 w = g4[i];
        v.x *= rs * w.x; v.y *= rs * w.y; v.z *= rs * w.z; v.w *= rs * w.w;
        uint32_t h0, l0, h1, l1;
        split2(v.x, v.y, h0, l0);
        split2(v.z, v.w, h1, l1);
        Hr[i] = make_uint2(h0, h1);
        Lr[i] = make_uint2(l0, l1);
    }
}

// ---------------- K split: per-head [ (b*H+h)*L + l ][ d ] ----------------
__global__ void split_k(const float* __restrict__ kv, __nv_bfloat16* __restrict__ h,
                        __nv_bfloat16* __restrict__ l) {
    size_t i = (size_t)blockIdx.x * 256 + threadIdx.x;
    if (i >= (size_t)CB * CH * CL * CHD) return;
    int d = (int)(i & 127);
    size_t r = i >> 7;
    int ll = (int)(r & 511); r >>= 9;
    int hh = (int)(r % CH);
    int b  = (int)(r / CH);
    float v = kv[((size_t)(b * CL + ll)) * CKV + hh * CHD + d];
    __nv_bfloat16 x = __float2bfloat16(v);
    h[i] = x;
    l[i] = __float2bfloat16(v - __bfloat162float(x));
}

// ---------------- V split transposed: [ (b*H+h)*D + d ][ l ] ----------------
__global__ void split_v(const float* __restrict__ kv, __nv_bfloat16* __restrict__ h,
                        __nv_bfloat16* __restrict__ l) {
    size_t i = (size_t)blockIdx.x * 256 + threadIdx.x;
    if (i >= (size_t)CB * CH * CHD * CL) return;
    int ll = (int)(i & 511);
    size_t r = i >> 9;
    int d = (int)(r & 127); r >>= 7;
    int hh = (int)(r % CH);
    int b  = (int)(r / CH);
    float v = kv[((size_t)(b * CL + ll)) * CKV + CDIM + hh * CHD + d];
    __nv_bfloat16 x = __float2bfloat16(v);
    h[i] = x;
    l[i] = __float2bfloat16(v - __bfloat162float(x));
}

// ---------------- bf16x3 GEMM: 4 warps, 64x64 warp tiles, 2 CTAs/SM ----------------
struct GP {
    const __nv_bfloat16 *Ahi, *Alo;  long ldA, sAb, sAh;
    const __nv_bfloat16 *Bhi, *Blo;  long sBb, sBh;
    float* C;  __nv_bfloat16 *Chi, *Clo;  long ldC, sCb, sCh;
    const float* bias;
    int K, Hdiv, splitOut;
};

#define TILE_B  (128 * 80)
#define BUF_B   (4 * TILE_B)
#define GEMM_SMEM_BYTES (2 * BUF_B)

extern __shared__ uint32_t dsm[];

__global__ __launch_bounds__(128, 2) void gemm_tc(GP p) {
    uint32_t sbase = smem_u32(dsm);

    int tid = threadIdx.x, lane = tid & 31, wp = tid >> 5;
    int wm = wp >> 1, wn = wp & 1;

    int z = blockIdx.z, bb = z / p.Hdiv, hh = z % p.Hdiv;
    const __nv_bfloat16* Ah = p.Ahi + (size_t)bb * p.sAb + (size_t)hh * p.sAh +
                              (size_t)blockIdx.y * 128 * p.ldA;
    const __nv_bfloat16* Al = p.Alo + (size_t)bb * p.sAb + (size_t)hh * p.sAh +
                              (size_t)blockIdx.y * 128 * p.ldA;
    const __nv_bfloat16* Bh = p.Bhi + (size_t)bb * p.sBb + (size_t)hh * p.sBh +
                              (size_t)blockIdx.x * 128 * p.K;
    const __nv_bfloat16* Bl = p.Blo + (size_t)bb * p.sBb + (size_t)hh * p.sBh +
                              (size_t)blockIdx.x * 128 * p.K;

    float acc[4][8][4];
#pragma unroll
    for (int mi = 0; mi < 4; mi++)
#pragma unroll
        for (int nj = 0; nj < 8; nj++)
#pragma unroll
            for (int q = 0; q < 4; q++) acc[mi][nj][q] = 0.f;

    int nk = p.K / 32;

    int r0 = tid >> 2, c0 = tid & 3;   // loader: rows r0+32i, 16B chunk c0

    int lrowA = (lane & 7) + ((lane >> 3) & 1) * 8;
    int kselA = ((lane >> 4) & 1) * 16;
    int lrowB = (lane & 7) + ((lane >> 4) & 1) * 8;
    int kselB = ((lane >> 3) & 1) * 16;

    auto cpAll = [&](int kt, int buf) {
        uint32_t base = sbase + buf * BUF_B;
        long ka = (long)kt * 32 + c0 * 8;
#pragma unroll
        for (int i = 0; i < 4; i++) {
            int r = r0 + 32 * i;
            uint32_t d = (uint32_t)r * 80 + c0 * 16;
            CP_ASYNC16(base + d,              Ah + (size_t)r * p.ldA + ka);
            CP_ASYNC16(base + TILE_B + d,     Al + (size_t)r * p.ldA + ka);
            CP_ASYNC16(base + 2 * TILE_B + d, Bh + (size_t)r * p.K + ka);
            CP_ASYNC16(base + 3 * TILE_B + d, Bl + (size_t)r * p.K + ka);
        }
    };

    auto compute = [&](int buf) {
        uint32_t aHi = sbase + buf * BUF_B;
        uint32_t aLo = aHi + TILE_B;
        uint32_t bHi = aLo + TILE_B;
        uint32_t bLo = bHi + TILE_B;
        uint32_t aAddrH[4], aAddrL[4], bAddrH[4], bAddrL[4];
#pragma unroll
        for (int mi = 0; mi < 4; mi++) {
            uint32_t ro = (uint32_t)(wm * 64 + mi * 16 + lrowA) * 80 + kselA;
            aAddrH[mi] = aHi + ro;
            aAddrL[mi] = aLo + ro;
        }
#pragma unroll
        for (int njp = 0; njp < 4; njp++) {
            uint32_t ro = (uint32_t)(wn * 64 + njp * 16 + lrowB) * 80 + kselB;
            bAddrH[njp] = bHi + ro;
            bAddrL[njp] = bLo + ro;
        }
#pragma unroll
        for (int kk = 0; kk < 2; kk++) {
            uint32_t ko = kk * 32;
            uint32_t ah[4][4], al[4][4];
#pragma unroll
            for (int mi = 0; mi < 4; mi++) {
                LDSM_X4(ah[mi], aAddrH[mi] + ko);
                LDSM_X4(al[mi], aAddrL[mi] + ko);
            }
#pragma unroll
            for (int njp = 0; njp < 4; njp++) {
                uint32_t bhf[4], blf[4];
                LDSM_X4(bhf, bAddrH[njp] + ko);
                LDSM_X4(blf, bAddrL[njp] + ko);
#pragma unroll
                for (int sub = 0; sub < 2; sub++) {
                    int nj = njp * 2 + sub;
                    uint32_t b0h = bhf[sub * 2], b1h = bhf[sub * 2 + 1];
                    uint32_t b0l = blf[sub * 2], b1l = blf[sub * 2 + 1];
#pragma unroll
                    for (int mi = 0; mi < 4; mi++) {
                        mma16816(acc[mi][nj], ah[mi], b0h, b1h);
                        mma16816(acc[mi][nj], al[mi], b0h, b1h);
                        mma16816(acc[mi][nj], ah[mi], b0l, b1l);
                    }
                }
            }
        }
    };

    cpAll(0, 0);
    CP_COMMIT();
    CP_WAIT0();
    __syncthreads();

    for (int kt = 0; kt < nk; kt++) {
        if (kt + 1 < nk) {
            cpAll(kt + 1, (kt + 1) & 1);
            CP_COMMIT();
        }
        compute(kt & 1);
        CP_WAIT0();
        __syncthreads();
    }

    size_t cbase = (size_t)bb * p.sCb + (size_t)hh * p.sCh +
                   (size_t)blockIdx.y * 128 * p.ldC + (size_t)blockIdx.x * 128;
    if (!p.splitOut) {
        float* C = p.C + cbase;
#pragma unroll
        for (int nj = 0; nj < 8; nj++) {
            int c = wn * 64 + nj * 8 + ((lane & 3) << 1);
            float b0 = 0.f, b1 = 0.f;
            if (p.bias) {
                size_t cg = (size_t)blockIdx.x * 128 + c;
                b0 = p.bias[cg];
                b1 = p.bias[cg + 1];
            }
#pragma unroll
            for (int mi = 0; mi < 4; mi++) {
                int r = wm * 64 + mi * 16 + (lane >> 2);
                *(float2*)&C[(size_t)r * p.ldC + c] =
                    make_float2(acc[mi][nj][0] + b0, acc[mi][nj][1] + b1);
                *(float2*)&C[(size_t)(r + 8) * p.ldC + c] =
                    make_float2(acc[mi][nj][2] + b0, acc[mi][nj][3] + b1);
            }
        }
    } else {
        __nv_bfloat16* Ch = p.Chi + cbase;
        __nv_bfloat16* Cl = p.Clo + cbase;
#pragma unroll
        for (int nj = 0; nj < 8; nj++) {
            int c = wn * 64 + nj * 8 + ((lane & 3) << 1);
#pragma unroll
            for (int mi = 0; mi < 4; mi++) {
                int r = wm * 64 + mi * 16 + (lane >> 2);
                uint32_t h0, l0, h1, l1;
                split2(acc[mi][nj][0], acc[mi][nj][1], h0, l0);
                split2(acc[mi][nj][2], acc[mi][nj][3], h1, l1);
                *(uint32_t*)&Ch[(size_t)r * p.ldC + c] = h0;
                *(uint32_t*)&Cl[(size_t)r * p.ldC + c] = l0;
                *(uint32_t*)&Ch[(size_t)(r + 8) * p.ldC + c] = h1;
                *(uint32_t*)&Cl[(size_t)(r + 8) * p.ldC + c] = l1;
            }
        }
    }
}

// ---------------- fused flash attention: QK^T -> online softmax -> PV ----------------
#define FPITCH 272
#define FT_Q   (128 * FPITCH)
#define FK_OFF (2 * FT_Q)
#define FV_OFF (4 * FT_Q)
#define FSTF   ((6 * FT_Q) / 4)
#define F_M    (FSTF)
#define F_L    (FSTF + 128)
#define F_A    (FSTF + 256)
#define F_RMAX (FSTF + 384)
#define F_RSUM (FSTF + 640)
#define FLASH_SMEM (6 * FT_Q + 3584)

__global__ __launch_bounds__(256, 1) void flash_attn() {
    uint32_t sb = smem_u32(dsm);
    float* fs = (float*)dsm;
    int tid = threadIdx.x, lane = tid & 31, wp = tid >> 5;
    int wm = wp >> 1, wn = wp & 1;
    int bh = blockIdx.y, b = bh / CH, hh = bh % CH;
    size_t qrow0 = (size_t)b * CS + (size_t)blockIdx.x * 128;

    const __nv_bfloat16* Qh = g_qs_h + qrow0 * CDIM + hh * CHD;
    const __nv_bfloat16* Ql = g_qs_l + qrow0 * CDIM + hh * CHD;
    const __nv_bfloat16* Kh = g_k_h + (size_t)bh * CL * CHD;
    const __nv_bfloat16* Kl = g_k_l + (size_t)bh * CL * CHD;
    const __nv_bfloat16* Vh = g_v_h + (size_t)bh * CHD * CL;
    const __nv_bfloat16* Vl = g_v_l + (size_t)bh * CHD * CL;

    if (tid < 128) {
        fs[F_M + tid] = -1e30f;
        fs[F_L + tid] = 0.f;
    }

    float O[2][8][4];
#pragma unroll
    for (int mi = 0; mi < 2; mi++)
#pragma unroll
        for (int nj = 0; nj < 8; nj++)
#pragma unroll
            for (int q = 0; q < 4; q++) O[mi][nj][q] = 0.f;

    int lrA = (lane & 7) + ((lane >> 3) & 1) * 8;
    int ksA = ((lane >> 4) & 1) * 16;
    int lrB = (lane & 7) + ((lane >> 4) & 1) * 8;
    int ksB = ((lane >> 3) & 1) * 16;

    auto cpT = [&](uint32_t dst, const __nv_bfloat16* src, long stride) {
#pragma unroll
        for (int i = 0; i < 8; i++) {
            int idx = tid + 256 * i;
            int row = idx >> 4, ch = idx & 15;
            CP_ASYNC16(dst + (uint32_t)row * FPITCH + ch * 16,
                       src + (size_t)row * stride + ch * 8);
        }
    };

    cpT(sb, Qh, CDIM);
    cpT(sb + FT_Q, Ql, CDIM);
    cpT(sb + FK_OFF, Kh, CHD);
    cpT(sb + FK_OFF + FT_Q, Kl, CHD);
    CP_COMMIT();
    cpT(sb + FV_OFF, Vh, CL);
    cpT(sb + FV_OFF + FT_Q, Vl, CL);
    CP_COMMIT();

    uint32_t qAH[2], qAL[2];
#pragma unroll
    for (int mi = 0; mi < 2; mi++) {
        uint32_t ro = (uint32_t)(wm * 32 + mi * 16 + lrA) * FPITCH + ksA;
        qAH[mi] = sb + ro;
        qAL[mi] = sb + FT_Q + ro;
    }
    uint32_t nBH[4], nBL[4];
#pragma unroll
    for (int njp = 0; njp < 4; njp++) {
        uint32_t ro = (uint32_t)(wn * 64 + njp * 16 + lrB) * FPITCH + ksB;
        nBH[njp] = ro;
        nBL[njp] = ro;
    }

    for (int j = 0; j < 4; j++) {
        CP_WAIT1();
        __syncthreads();

        float acc[2][8][4];
#pragma unroll
        for (int mi = 0; mi < 2; mi++)
#pragma unroll
            for (int nj = 0; nj < 8; nj++)
#pragma unroll
                for (int q = 0; q < 4; q++) acc[mi][nj][q] = 0.f;

#pragma unroll
        for (int ks = 0; ks < 8; ks++) {
            uint32_t ko = ks * 32;
            uint32_t ah[2][4], al[2][4];
#pragma unroll
            for (int mi = 0; mi < 2; mi++) {
                LDSM_X4(ah[mi], qAH[mi] + ko);
                LDSM_X4(al[mi], qAL[mi] + ko);
            }
#pragma unroll
            for (int njp = 0; njp < 4; njp++) {
                uint32_t bhf[4], blf[4];
                LDSM_X4(bhf, sb + FK_OFF + nBH[njp] + ko);
                LDSM_X4(blf, sb + FK_OFF + FT_Q + nBL[njp] + ko);
#pragma unroll
                for (int sub = 0; sub < 2; sub++) {
                    int nj = njp * 2 + sub;
                    uint32_t b0h = bhf[sub * 2], b1h = bhf[sub * 2 + 1];
                    uint32_t b0l = blf[sub * 2], b1l = blf[sub * 2 + 1];
#pragma unroll
                    for (int mi = 0; mi < 2; mi++) {
                        mma16816(acc[mi][nj], ah[mi], b0h, b1h);
                        mma16816(acc[mi][nj], al[mi], b0h, b1h);
                        mma16816(acc[mi][nj], ah[mi], b0l, b1l);
                    }
                }
            }
        }
#pragma unroll
        for (int mi = 0; mi < 2; mi++)
#pragma unroll
            for (int nj = 0; nj < 8; nj++)
#pragma unroll
                for (int q = 0; q < 4; q++) acc[mi][nj][q] *= FSCALE;

        __syncthreads();

#pragma unroll
        for (int mi = 0; mi < 2; mi++)
#pragma unroll
            for (int h = 0; h < 2; h++) {
                float mx = -1e30f;
#pragma unroll
                for (int nj = 0; nj < 8; nj++)
                    mx = fmaxf(mx, fmaxf(acc[mi][nj][2 * h], acc[mi][nj][2 * h + 1]));
                mx = fmaxf(mx, __shfl_xor_sync(0xffffffffu, mx, 1));
                mx = fmaxf(mx, __shfl_xor_sync(0xffffffffu, mx, 2));
                if ((lane & 3) == 0) {
                    int row = wm * 32 + mi * 16 + (lane >> 2) + h * 8;
                    fs[F_RMAX + row * 2 + wn] = mx;
                }
            }
        __syncthreads();
        if (tid < 128) {
            float mc = fmaxf(fs[F_RMAX + tid * 2], fs[F_RMAX + tid * 2 + 1]);
            float mo = fs[F_M + tid];
            float mn = fmaxf(mo, mc);
            fs[F_M + tid] = mn;
            fs[F_A + tid] = __expf(mo - mn);
        }
        __syncthreads();

#pragma unroll
        for (int mi = 0; mi < 2; mi++)
#pragma unroll
            for (int h = 0; h < 2; h++) {
                int row = wm * 32 + mi * 16 + (lane >> 2) + h * 8;
                float mn = fs[F_M + row];
                float al = fs[F_A + row];
                float s = 0.f;
#pragma unroll
                for (int nj = 0; nj < 8; nj++) {
                    float p0 = __expf(acc[mi][nj][2 * h] - mn);
                    float p1 = __expf(acc[mi][nj][2 * h + 1] - mn);
                    s += p0 + p1;
                    uint32_t hw, lw;
                    split2(p0, p1, hw, lw);
                    int c = wn * 64 + nj * 8 + 2 * (lane & 3);
                    uint32_t off = ((uint32_t)row * FPITCH + c * 2) >> 2;
                    dsm[(FK_OFF >> 2) + off] = hw;
                    dsm[((FK_OFF + FT_Q) >> 2) + off] = lw;
                    O[mi][nj][2 * h] *= al;
                    O[mi][nj][2 * h + 1] *= al;
                }
                s += __shfl_xor_sync(0xffffffffu, s, 1);
                s += __shfl_xor_sync(0xffffffffu, s, 2);
                if ((lane & 3) == 0) fs[F_RSUM + row * 2 + wn] = s;
            }
        __syncthreads();
        if (tid < 128)
            fs[F_L + tid] = fs[F_L + tid] * fs[F_A + tid] +
                            fs[F_RSUM + tid * 2] + fs[F_RSUM + tid * 2 + 1];

        CP_WAIT0();
        __syncthreads();

#pragma unroll
        for (int ks = 0; ks < 8; ks++) {
            uint32_t ko = ks * 32;
            uint32_t ah[2][4], al[2][4];
#pragma unroll
            for (int mi = 0; mi < 2; mi++) {
                uint32_t ro = (uint32_t)(wm * 32 + mi * 16 + lrA) * FPITCH + ksA;
                LDSM_X4(ah[mi], sb + FK_OFF + ro + ko);
                LDSM_X4(al[mi], sb + FK_OFF + FT_Q + ro + ko);
            }
#pragma unroll
            for (int njp = 0; njp < 4; njp++) {
                uint32_t bhf[4], blf[4];
                LDSM_X4(bhf, sb + FV_OFF + nBH[njp] + ko);
                LDSM_X4(blf, sb + FV_OFF + FT_Q + nBL[njp] + ko);
#pragma unroll
                for (int sub = 0; sub < 2; sub++) {
                    int nj = njp * 2 + sub;
                    uint32_t b0h = bhf[sub * 2], b1h = bhf[sub * 2 + 1];
                    uint32_t b0l = blf[sub * 2], b1l = blf[sub * 2 + 1];
#pragma unroll
                    for (int mi = 0; mi < 2; mi++) {
                        mma16816(O[mi][nj], ah[mi], b0h, b1h);
                        mma16816(O[mi][nj], al[mi], b0h, b1h);
                        mma16816(O[mi][nj], ah[mi], b0l, b1l);
                    }
                }
            }
        }
        __syncthreads();

        if (j < 3) {
            cpT(sb + FK_OFF, Kh + (size_t)(j + 1) * 128 * CHD, CHD);
            cpT(sb + FK_OFF + FT_Q, Kl + (size_t)(j + 1) * 128 * CHD, CHD);
            CP_COMMIT();
            cpT(sb + FV_OFF, Vh + (j + 1) * 128, CL);
            cpT(sb + FV_OFF + FT_Q, Vl + (j + 1) * 128, CL);
            CP_COMMIT();
        }
    }
    __syncthreads();

    __nv_bfloat16* Ah = g_att_h + qrow0 * CDIM + hh * CHD;
    __nv_bfloat16* Al = g_att_l + qrow0 * CDIM + hh * CHD;
#pragma unroll
    for (int nj = 0; nj < 8; nj++) {
        int c = wn * 64 + nj * 8 + 2 * (lane & 3);
#pragma unroll
        for (int mi = 0; mi < 2; mi++) {
#pragma unroll
            for (int h = 0; h < 2; h++) {
                int row = wm * 32 + mi * 16 + (lane >> 2) + h * 8;
                float inv = 1.f / fs[F_L + row];
                uint32_t hw, lw;
                split2(O[mi][nj][2 * h] * inv, O[mi][nj][2 * h + 1] * inv, hw, lw);
                *(uint32_t*)&Ah[(size_t)row * CDIM + c] = hw;
                *(uint32_t*)&Al[(size_t)row * CDIM + c] = lw;
            }
        }
    }
}

// ---------------- host launcher ----------------
extern "C" void kernel_launch(void* const* d_in, const int* in_sizes, int n_in,
                              void* d_out, int out_size) {
    (void)in_sizes; (void)n_in; (void)out_size;
    const float* hid = (const float*)d_in[0];
    const float* ctx = (const float*)d_in[1];
    const float* Wq  = (const float*)d_in[2];
    const float* bq  = (const float*)d_in[3];
    const float* Wkv = (const float*)d_in[4];
    const float* bkv = (const float*)d_in[5];
    const float* gq  = (const float*)d_in[6];
    const float* gk  = (const float*)d_in[7];
    const float* Wo  = (const float*)d_in[8];
    const float* bo  = (const float*)d_in[9];
    float* out = (float*)d_out;

    __nv_bfloat16 *wq_h, *wq_l, *wkv_h, *wkv_l, *wo_h, *wo_l;
    __nv_bfloat16 *hid_h, *hid_l, *ctx_h, *ctx_l, *qs_h, *qs_l;
    __nv_bfloat16 *k_h, *k_l, *v_h, *v_l, *att_h, *att_l;
    float *q, *kv;
    cudaGetSymbolAddress((void**)&wq_h, g_wq_h);
    cudaGetSymbolAddress((void**)&wq_l, g_wq_l);
    cudaGetSymbolAddress((void**)&wkv_h, g_wkv_h);
    cudaGetSymbolAddress((void**)&wkv_l, g_wkv_l);
    cudaGetSymbolAddress((void**)&wo_h, g_wo_h);
    cudaGetSymbolAddress((void**)&wo_l, g_wo_l);
    cudaGetSymbolAddress((void**)&hid_h, g_hid_h);
    cudaGetSymbolAddress((void**)&hid_l, g_hid_l);
    cudaGetSymbolAddress((void**)&ctx_h, g_ctx_h);
    cudaGetSymbolAddress((void**)&ctx_l, g_ctx_l);
    cudaGetSymbolAddress((void**)&qs_h, g_qs_h);
    cudaGetSymbolAddress((void**)&qs_l, g_qs_l);
    cudaGetSymbolAddress((void**)&k_h, g_k_h);
    cudaGetSymbolAddress((void**)&k_l, g_k_l);
    cudaGetSymbolAddress((void**)&v_h, g_v_h);
    cudaGetSymbolAddress((void**)&v_l, g_v_l);
    cudaGetSymbolAddress((void**)&att_h, g_att_h);
    cudaGetSymbolAddress((void**)&att_l, g_att_l);
    cudaGetSymbolAddress((void**)&q, g_q);
    cudaGetSymbolAddress((void**)&kv, g_kv);

    cudaFuncSetAttribute(gemm_tc, cudaFuncAttributeMaxDynamicSharedMemorySize,
                         GEMM_SMEM_BYTES);
    cudaFuncSetAttribute(flash_attn, cudaFuncAttributeMaxDynamicSharedMemorySize,
                         FLASH_SMEM);

    dim3 tb(32, 8);
    transpose_split<<<dim3(CDIM / 32, CDIM / 32), tb>>>(Wq, wq_h, wq_l, CDIM, CDIM);
    transpose_split<<<dim3(CKV / 32, CDIM / 32), tb>>>(Wkv, wkv_h, wkv_l, CDIM, CKV);
    transpose_split<<<dim3(CDIM / 32, CDIM / 32), tb>>>(Wo, wo_h, wo_l, CDIM, CDIM);

    {
        size_t n4 = (size_t)CB * CS * CDIM / 4;
        split_plain<<<(unsigned)((n4 + 255) / 256), 256>>>(hid, hid_h, hid_l, n4);
        size_t m4 = (size_t)CB * CL * CDIM / 4;
        split_plain<<<(unsigned)((m4 + 255) / 256), 256>>>(ctx, ctx_h, ctx_l, m4);
    }

    GP p{};

    // Q = hidden @ Wq + bq  -> fp32 q
    p.Ahi = hid_h; p.Alo = hid_l; p.ldA = CDIM; p.sAb = 0; p.sAh = 0;
    p.Bhi = wq_h; p.Blo = wq_l; p.sBb = 0; p.sBh = 0;
    p.C = q; p.Chi = nullptr; p.Clo = nullptr; p.ldC = CDIM; p.sCb = 0; p.sCh = 0;
    p.bias = bq; p.K = CDIM; p.Hdiv = 1; p.splitOut = 0;
    gemm_tc<<<dim3(CDIM / 128, (CB * CS) / 128, 1), 128, GEMM_SMEM_BYTES>>>(p);

    rmsnorm_split<<<CB * CS, 256>>>(q, gq, qs_h, qs_l);

    // KV = context @ Wkv + bkv -> fp32 kv
    p.Ahi = ctx_h; p.Alo = ctx_l; p.ldA = CDIM; p.sAb = 0; p.sAh = 0;
    p.Bhi = wkv_h; p.Blo = wkv_l; p.sBb = 0; p.sBh = 0;
    p.C = kv; p.ldC = CKV; p.sCb = 0; p.sCh = 0;
    p.bias = bkv; p.K = CDIM; p.Hdiv = 1; p.splitOut = 0;
    gemm_tc<<<dim3(CKV / 128, (CB * CL) / 128, 1), 128, GEMM_SMEM_BYTES>>>(p);

    rmsnorm_rows<<<CB * CL, 256>>>(kv, CKV, gk);

    {
        size_t nK = (size_t)CB * CH * CL * CHD;
        split_k<<<(unsigned)((nK + 255) / 256), 256>>>(kv, k_h, k_l);
        split_v<<<(unsigned)((nK + 255) / 256), 256>>>(kv, v_h, v_l);
    }

    // fused attention -> split bf16 att
    flash_attn<<<dim3(CS / 128, CB * CH), 256, FLASH_SMEM>>>();

    // out = att @ Wo + bo
    p.Ahi = att_h; p.Alo = att_l; p.ldA = CDIM; p.sAb = 0; p.sAh = 0;
    p.Bhi = wo_h; p.Blo = wo_l; p.sBb = 0; p.sBh = 0;
    p.C = out; p.Chi = nullptr; p.Clo = nullptr; p.ldC = CDIM; p.sCb = 0; p.sCh = 0;
    p.bias = bo; p.K = CDIM; p.Hdiv = 1; p.splitOut = 0;
    gemm_tc<<<dim3(CDIM / 128, (CB * CS) / 128, 1), 128, GEMM_SMEM_BYTES>>>(p);
}

// round 10
// speedup vs baseline: 2.4714x; 1.4590x over previous
#include <cuda_runtime.h>
#include <cuda_fp16.h>
#include <cstdint>
#include <cstddef>

#define CB   2
#define CS   4096
#define CL   512
#define CDIM 5120
#define CH   40
#define CHD  128
#define CKV  (2*CDIM)
#define FSCALE 0.08838834764831845f
#define FEPS 1e-6f

// ---------------- static device scratch ----------------
// B-side operands: fp16 hi/lo pairs
__device__ __half g_wq_h [(size_t)CDIM*CDIM];
__device__ __half g_wq_l [(size_t)CDIM*CDIM];
__device__ __half g_wkv_h[(size_t)CDIM*CKV];
__device__ __half g_wkv_l[(size_t)CDIM*CKV];
__device__ __half g_wo_h [(size_t)CDIM*CDIM];
__device__ __half g_wo_l [(size_t)CDIM*CDIM];
__device__ __half g_k_h  [(size_t)CB*CH*CL*CHD];
__device__ __half g_k_l  [(size_t)CB*CH*CL*CHD];
__device__ __half g_v_h  [(size_t)CB*CH*CHD*CL];
__device__ __half g_v_l  [(size_t)CB*CH*CHD*CL];
// A-side operands: plain fp16
__device__ __half g_hid  [(size_t)CB*CS*CDIM];
__device__ __half g_ctx  [(size_t)CB*CL*CDIM];
__device__ __half g_qs   [(size_t)CB*CS*CDIM];
__device__ __half g_att  [(size_t)CB*CS*CDIM];
// fp32 intermediates
__device__ float  g_q    [(size_t)CB*CS*CDIM];
__device__ float  g_kv   [(size_t)CB*CL*CKV];

// ---------------- helpers ----------------
__device__ __forceinline__ uint32_t smem_u32(const void* p) {
    uint32_t a;
    asm("{ .reg .u64 t; cvta.to.shared.u64 t, %1; cvt.u32.u64 %0, t; }" : "=r"(a) : "l"(p));
    return a;
}

// fp16 hi/lo split of a float pair
__device__ __forceinline__ void split2h(float x, float y, uint32_t& hi, uint32_t& lo) {
    __half2 h = __floats2half2_rn(x, y);
    float2 hf = __half22float2(h);
    __half2 l = __floats2half2_rn(x - hf.x, y - hf.y);
    hi = *reinterpret_cast<uint32_t*>(&h);
    lo = *reinterpret_cast<uint32_t*>(&l);
}
__device__ __forceinline__ uint32_t pack2h(float x, float y) {
    __half2 h = __floats2half2_rn(x, y);
    return *reinterpret_cast<uint32_t*>(&h);
}

__device__ __forceinline__ void mma16816(float* c, const uint32_t* a, uint32_t b0, uint32_t b1) {
    asm volatile(
        "mma.sync.aligned.m16n8k16.row.col.f32.f16.f16.f32 "
        "{%0,%1,%2,%3},{%4,%5,%6,%7},{%8,%9},{%0,%1,%2,%3};\n"
        : "+f"(c[0]), "+f"(c[1]), "+f"(c[2]), "+f"(c[3])
        : "r"(a[0]), "r"(a[1]), "r"(a[2]), "r"(a[3]), "r"(b0), "r"(b1));
}

#define LDSM_X4(r, addr)                                                              \
    asm volatile("ldmatrix.sync.aligned.m8n8.x4.shared.b16 {%0,%1,%2,%3}, [%4];"      \
                 : "=r"((r)[0]), "=r"((r)[1]), "=r"((r)[2]), "=r"((r)[3]) : "r"(addr))

#define CP_ASYNC16(dst, src) \
    asm volatile("cp.async.ca.shared.global [%0], [%1], 16;\n" :: "r"(dst), "l"(src))
#define CP_COMMIT() asm volatile("cp.async.commit_group;\n" ::: "memory")
#define CP_WAIT0()  asm volatile("cp.async.wait_group 0;\n" ::: "memory")
#define CP_WAIT1()  asm volatile("cp.async.wait_group 1;\n" ::: "memory")

// ---------------- weight transpose + fp16 split:  T[n][k] = W[k][n] ----------------
__global__ void transpose_split(const float* __restrict__ W, __half* __restrict__ Thi,
                                __half* __restrict__ Tlo, int K, int N) {
    __shared__ float t[32][33];
    int n0 = blockIdx.x * 32, k0 = blockIdx.y * 32;
    int tx = threadIdx.x, ty = threadIdx.y;
#pragma unroll
    for (int i = 0; i < 32; i += 8)
        t[ty + i][tx] = W[(size_t)(k0 + ty + i) * N + n0 + tx];
    __syncthreads();
#pragma unroll
    for (int i = 0; i < 32; i += 8) {
        float v = t[tx][ty + i];
        __half h = __float2half_rn(v);
        size_t o = (size_t)(n0 + ty + i) * K + k0 + tx;
        Thi[o] = h;
        Tlo[o] = __float2half_rn(v - __half2float(h));
    }
}

// ---------------- elementwise fp32 -> plain fp16 ----------------
__global__ void tofp16(const float* __restrict__ X, __half* __restrict__ H, size_t n4) {
    size_t i = (size_t)blockIdx.x * 256 + threadIdx.x;
    if (i >= n4) return;
    float4 v = ((const float4*)X)[i];
    ((uint2*)H)[i] = make_uint2(pack2h(v.x, v.y), pack2h(v.z, v.w));
}

// ---------------- RMSNorm in place (fp32) ----------------
__global__ void rmsnorm_rows(float* __restrict__ X, long ld, const float* __restrict__ g) {
    float* row = X + (size_t)blockIdx.x * ld;
    int tid = threadIdx.x;
    float4* r4 = (float4*)row;
    const float4* g4 = (const float4*)g;
    float s = 0.f;
#pragma unroll 5
    for (int i = tid; i < CDIM / 4; i += 256) {
        float4 v = r4[i];
        s += v.x * v.x + v.y * v.y + v.z * v.z + v.w * v.w;
    }
#pragma unroll
    for (int o = 16; o; o >>= 1) s += __shfl_xor_sync(0xffffffffu, s, o);
    __shared__ float ws[8];
    if ((tid & 31) == 0) ws[tid >> 5] = s;
    __syncthreads();
    if (tid == 0) {
        float x = 0.f;
#pragma unroll
        for (int i = 0; i < 8; i++) x += ws[i];
        ws[0] = rsqrtf(x / (float)CDIM + FEPS);
    }
    __syncthreads();
    float rs = ws[0];
#pragma unroll 5
    for (int i = tid; i < CDIM / 4; i += 256) {
        float4 v = r4[i];
        float4 w = g4[i];
        v.x *= rs * w.x; v.y *= rs * w.y; v.z *= rs * w.z; v.w *= rs * w.w;
        r4[i] = v;
    }
}

// ---------------- RMSNorm reading fp32, writing plain fp16 ----------------
__global__ void rmsnorm_h(const float* __restrict__ X, const float* __restrict__ g,
                          __half* __restrict__ H) {
    const float* row = X + (size_t)blockIdx.x * CDIM;
    int tid = threadIdx.x;
    const float4* r4 = (const float4*)row;
    const float4* g4 = (const float4*)g;
    float s = 0.f;
#pragma unroll 5
    for (int i = tid; i < CDIM / 4; i += 256) {
        float4 v = r4[i];
        s += v.x * v.x + v.y * v.y + v.z * v.z + v.w * v.w;
    }
#pragma unroll
    for (int o = 16; o; o >>= 1) s += __shfl_xor_sync(0xffffffffu, s, o);
    __shared__ float ws[8];
    if ((tid & 31) == 0) ws[tid >> 5] = s;
    __syncthreads();
    if (tid == 0) {
        float x = 0.f;
#pragma unroll
        for (int i = 0; i < 8; i++) x += ws[i];
        ws[0] = rsqrtf(x / (float)CDIM + FEPS);
    }
    __syncthreads();
    float rs = ws[0];
    uint2* Hr = (uint2*)(H + (size_t)blockIdx.x * CDIM);
#pragma unroll 5
    for (int i = tid; i < CDIM / 4; i += 256) {
        float4 v = r4[i];
        float4 w = g4[i];
        v.x *= rs * w.x; v.y *= rs * w.y; v.z *= rs * w.z; v.w *= rs * w.w;
        Hr[i] = make_uint2(pack2h(v.x, v.y), pack2h(v.z, v.w));
    }
}

// ---------------- K split: per-head [ (b*H+h)*L + l ][ d ], fp16 hi/lo ----------------
__global__ void split_k(const float* __restrict__ kv, __half* __restrict__ h,
                        __half* __restrict__ l) {
    size_t i = (size_t)blockIdx.x * 256 + threadIdx.x;
    if (i >= (size_t)CB * CH * CL * CHD) return;
    int d = (int)(i & 127);
    size_t r = i >> 7;
    int ll = (int)(r & 511); r >>= 9;
    int hh = (int)(r % CH);
    int b  = (int)(r / CH);
    float v = kv[((size_t)(b * CL + ll)) * CKV + hh * CHD + d];
    __half x = __float2half_rn(v);
    h[i] = x;
    l[i] = __float2half_rn(v - __half2float(x));
}

// ---------------- V split transposed: [ (b*H+h)*D + d ][ l ], fp16 hi/lo ----------------
__global__ void split_v(const float* __restrict__ kv, __half* __restrict__ h,
                        __half* __restrict__ l) {
    size_t i = (size_t)blockIdx.x * 256 + threadIdx.x;
    if (i >= (size_t)CB * CH * CHD * CL) return;
    int ll = (int)(i & 511);
    size_t r = i >> 9;
    int d = (int)(r & 127); r >>= 7;
    int hh = (int)(r % CH);
    int b  = (int)(r / CH);
    float v = kv[((size_t)(b * CL + ll)) * CKV + CDIM + hh * CHD + d];
    __half x = __float2half_rn(v);
    h[i] = x;
    l[i] = __float2half_rn(v - __half2float(x));
}

// ---------------- fp16x2 GEMM: A plain fp16, B split hi/lo; C = A@B^T + bias ----------------
struct GP {
    const __half* A;  long ldA, sAb, sAh;
    const __half *Bhi, *Blo;  long sBb, sBh;
    float* C;  long ldC, sCb, sCh;
    const float* bias;
    int K, Hdiv;
};

#define TILE_B  (128 * 80)          // 10240 bytes
#define BUF_B   (3 * TILE_B)        // A, Bhi, Blo
#define GEMM_SMEM_BYTES (2 * BUF_B) // 61440

extern __shared__ uint32_t dsm[];

__global__ __launch_bounds__(128, 2) void gemm_tc(GP p) {
    uint32_t sbase = smem_u32(dsm);

    int tid = threadIdx.x, lane = tid & 31, wp = tid >> 5;
    int wm = wp >> 1, wn = wp & 1;

    int z = blockIdx.z, bb = z / p.Hdiv, hh = z % p.Hdiv;
    const __half* A  = p.A + (size_t)bb * p.sAb + (size_t)hh * p.sAh +
                       (size_t)blockIdx.y * 128 * p.ldA;
    const __half* Bh = p.Bhi + (size_t)bb * p.sBb + (size_t)hh * p.sBh +
                       (size_t)blockIdx.x * 128 * p.K;
    const __half* Bl = p.Blo + (size_t)bb * p.sBb + (size_t)hh * p.sBh +
                       (size_t)blockIdx.x * 128 * p.K;

    float acc[4][8][4];
#pragma unroll
    for (int mi = 0; mi < 4; mi++)
#pragma unroll
        for (int nj = 0; nj < 8; nj++)
#pragma unroll
            for (int q = 0; q < 4; q++) acc[mi][nj][q] = 0.f;

    int nk = p.K / 32;
    int r0 = tid >> 2, c0 = tid & 3;

    int lrowA = (lane & 7) + ((lane >> 3) & 1) * 8;
    int kselA = ((lane >> 4) & 1) * 16;
    int lrowB = (lane & 7) + ((lane >> 4) & 1) * 8;
    int kselB = ((lane >> 3) & 1) * 16;

    auto cpAll = [&](int kt, int buf) {
        uint32_t base = sbase + buf * BUF_B;
        long ka = (long)kt * 32 + c0 * 8;
#pragma unroll
        for (int i = 0; i < 4; i++) {
            int r = r0 + 32 * i;
            uint32_t d = (uint32_t)r * 80 + c0 * 16;
            CP_ASYNC16(base + d,              A  + (size_t)r * p.ldA + ka);
            CP_ASYNC16(base + TILE_B + d,     Bh + (size_t)r * p.K + ka);
            CP_ASYNC16(base + 2 * TILE_B + d, Bl + (size_t)r * p.K + ka);
        }
    };

    auto compute = [&](int buf) {
        uint32_t aB = sbase + buf * BUF_B;
        uint32_t bHi = aB + TILE_B;
        uint32_t bLo = bHi + TILE_B;
        uint32_t aAddr[4], bAddrH[4], bAddrL[4];
#pragma unroll
        for (int mi = 0; mi < 4; mi++)
            aAddr[mi] = aB + (uint32_t)(wm * 64 + mi * 16 + lrowA) * 80 + kselA;
#pragma unroll
        for (int njp = 0; njp < 4; njp++) {
            uint32_t ro = (uint32_t)(wn * 64 + njp * 16 + lrowB) * 80 + kselB;
            bAddrH[njp] = bHi + ro;
            bAddrL[njp] = bLo + ro;
        }
#pragma unroll
        for (int kk = 0; kk < 2; kk++) {
            uint32_t ko = kk * 32;
            uint32_t ah[4][4];
#pragma unroll
            for (int mi = 0; mi < 4; mi++) LDSM_X4(ah[mi], aAddr[mi] + ko);
#pragma unroll
            for (int njp = 0; njp < 4; njp++) {
                uint32_t bhf[4], blf[4];
                LDSM_X4(bhf, bAddrH[njp] + ko);
                LDSM_X4(blf, bAddrL[njp] + ko);
#pragma unroll
                for (int sub = 0; sub < 2; sub++) {
                    int nj = njp * 2 + sub;
                    uint32_t b0h = bhf[sub * 2], b1h = bhf[sub * 2 + 1];
                    uint32_t b0l = blf[sub * 2], b1l = blf[sub * 2 + 1];
#pragma unroll
                    for (int mi = 0; mi < 4; mi++) {
                        mma16816(acc[mi][nj], ah[mi], b0h, b1h);
                        mma16816(acc[mi][nj], ah[mi], b0l, b1l);
                    }
                }
            }
        }
    };

    cpAll(0, 0);
    CP_COMMIT();
    CP_WAIT0();
    __syncthreads();

    for (int kt = 0; kt < nk; kt++) {
        if (kt + 1 < nk) {
            cpAll(kt + 1, (kt + 1) & 1);
            CP_COMMIT();
        }
        compute(kt & 1);
        CP_WAIT0();
        __syncthreads();
    }

    float* C = p.C + (size_t)bb * p.sCb + (size_t)hh * p.sCh +
               (size_t)blockIdx.y * 128 * p.ldC + (size_t)blockIdx.x * 128;
#pragma unroll
    for (int nj = 0; nj < 8; nj++) {
        int c = wn * 64 + nj * 8 + ((lane & 3) << 1);
        float b0 = 0.f, b1 = 0.f;
        if (p.bias) {
            size_t cg = (size_t)blockIdx.x * 128 + c;
            b0 = p.bias[cg];
            b1 = p.bias[cg + 1];
        }
#pragma unroll
        for (int mi = 0; mi < 4; mi++) {
            int r = wm * 64 + mi * 16 + (lane >> 2);
            *(float2*)&C[(size_t)r * p.ldC + c] =
                make_float2(acc[mi][nj][0] + b0, acc[mi][nj][1] + b1);
            *(float2*)&C[(size_t)(r + 8) * p.ldC + c] =
                make_float2(acc[mi][nj][2] + b0, acc[mi][nj][3] + b1);
        }
    }
}

// ---------------- fused flash attention: Q plain fp16; K,V split; P plain fp16 ----------------
#define FPITCH 272
#define FT     (128 * FPITCH)        // 34816 per tile
#define FQ_OFF 0                     // Q (1 tile)
#define FK_OFF (1 * FT)              // K hi (P overwrites), K lo at 2*FT
#define FV_OFF (3 * FT)              // V hi, lo at 4*FT
#define FSTF   ((5 * FT) / 4)
#define F_M    (FSTF)
#define F_L    (FSTF + 128)
#define F_A    (FSTF + 256)
#define F_RMAX (FSTF + 384)
#define F_RSUM (FSTF + 640)
#define FLASH_SMEM (5 * FT + 3584)

__global__ __launch_bounds__(256, 1) void flash_attn() {
    uint32_t sb = smem_u32(dsm);
    float* fs = (float*)dsm;
    int tid = threadIdx.x, lane = tid & 31, wp = tid >> 5;
    int wm = wp >> 1, wn = wp & 1;
    int bh = blockIdx.y, b = bh / CH, hh = bh % CH;
    size_t qrow0 = (size_t)b * CS + (size_t)blockIdx.x * 128;

    const __half* Q  = g_qs + qrow0 * CDIM + hh * CHD;
    const __half* Kh = g_k_h + (size_t)bh * CL * CHD;
    const __half* Kl = g_k_l + (size_t)bh * CL * CHD;
    const __half* Vh = g_v_h + (size_t)bh * CHD * CL;
    const __half* Vl = g_v_l + (size_t)bh * CHD * CL;

    if (tid < 128) {
        fs[F_M + tid] = -1e30f;
        fs[F_L + tid] = 0.f;
    }

    float O[2][8][4];
#pragma unroll
    for (int mi = 0; mi < 2; mi++)
#pragma unroll
        for (int nj = 0; nj < 8; nj++)
#pragma unroll
            for (int q = 0; q < 4; q++) O[mi][nj][q] = 0.f;

    int lrA = (lane & 7) + ((lane >> 3) & 1) * 8;
    int ksA = ((lane >> 4) & 1) * 16;
    int lrB = (lane & 7) + ((lane >> 4) & 1) * 8;
    int ksB = ((lane >> 3) & 1) * 16;

    auto cpT = [&](uint32_t dst, const __half* src, long stride) {
#pragma unroll
        for (int i = 0; i < 8; i++) {
            int idx = tid + 256 * i;
            int row = idx >> 4, ch = idx & 15;
            CP_ASYNC16(dst + (uint32_t)row * FPITCH + ch * 16,
                       src + (size_t)row * stride + ch * 8);
        }
    };

    cpT(sb + FQ_OFF, Q, CDIM);
    cpT(sb + FK_OFF, Kh, CHD);
    cpT(sb + 2 * FT, Kl, CHD);
    CP_COMMIT();
    cpT(sb + FV_OFF, Vh, CL);
    cpT(sb + 4 * FT, Vl, CL);
    CP_COMMIT();

    uint32_t qA[2];
#pragma unroll
    for (int mi = 0; mi < 2; mi++)
        qA[mi] = sb + (uint32_t)(wm * 32 + mi * 16 + lrA) * FPITCH + ksA;
    uint32_t nB[4];
#pragma unroll
    for (int njp = 0; njp < 4; njp++)
        nB[njp] = (uint32_t)(wn * 64 + njp * 16 + lrB) * FPITCH + ksB;

    for (int j = 0; j < 4; j++) {
        CP_WAIT1();
        __syncthreads();

        // ---- S = Q K^T (2 mma per fragment: Q*Kh + Q*Kl) ----
        float acc[2][8][4];
#pragma unroll
        for (int mi = 0; mi < 2; mi++)
#pragma unroll
            for (int nj = 0; nj < 8; nj++)
#pragma unroll
                for (int q = 0; q < 4; q++) acc[mi][nj][q] = 0.f;

#pragma unroll
        for (int ks = 0; ks < 8; ks++) {
            uint32_t ko = ks * 32;
            uint32_t aq[2][4];
#pragma unroll
            for (int mi = 0; mi < 2; mi++) LDSM_X4(aq[mi], qA[mi] + ko);
#pragma unroll
            for (int njp = 0; njp < 4; njp++) {
                uint32_t bhf[4], blf[4];
                LDSM_X4(bhf, sb + FK_OFF + nB[njp] + ko);
                LDSM_X4(blf, sb + 2 * FT + nB[njp] + ko);
#pragma unroll
                for (int sub = 0; sub < 2; sub++) {
                    int nj = njp * 2 + sub;
                    uint32_t b0h = bhf[sub * 2], b1h = bhf[sub * 2 + 1];
                    uint32_t b0l = blf[sub * 2], b1l = blf[sub * 2 + 1];
#pragma unroll
                    for (int mi = 0; mi < 2; mi++) {
                        mma16816(acc[mi][nj], aq[mi], b0h, b1h);
                        mma16816(acc[mi][nj], aq[mi], b0l, b1l);
                    }
                }
            }
        }
#pragma unroll
        for (int mi = 0; mi < 2; mi++)
#pragma unroll
            for (int nj = 0; nj < 8; nj++)
#pragma unroll
                for (int q = 0; q < 4; q++) acc[mi][nj][q] *= FSCALE;

        __syncthreads();

        // ---- row max ----
#pragma unroll
        for (int mi = 0; mi < 2; mi++)
#pragma unroll
            for (int h = 0; h < 2; h++) {
                float mx = -1e30f;
#pragma unroll
                for (int nj = 0; nj < 8; nj++)
                    mx = fmaxf(mx, fmaxf(acc[mi][nj][2 * h], acc[mi][nj][2 * h + 1]));
                mx = fmaxf(mx, __shfl_xor_sync(0xffffffffu, mx, 1));
                mx = fmaxf(mx, __shfl_xor_sync(0xffffffffu, mx, 2));
                if ((lane & 3) == 0) {
                    int row = wm * 32 + mi * 16 + (lane >> 2) + h * 8;
                    fs[F_RMAX + row * 2 + wn] = mx;
                }
            }
        __syncthreads();
        if (tid < 128) {
            float mc = fmaxf(fs[F_RMAX + tid * 2], fs[F_RMAX + tid * 2 + 1]);
            float mo = fs[F_M + tid];
            float mn = fmaxf(mo, mc);
            fs[F_M + tid] = mn;
            fs[F_A + tid] = __expf(mo - mn);
        }
        __syncthreads();

        // ---- P = exp(S-m) -> plain fp16 into K-hi buffer; sums; rescale O ----
#pragma unroll
        for (int mi = 0; mi < 2; mi++)
#pragma unroll
            for (int h = 0; h < 2; h++) {
                int row = wm * 32 + mi * 16 + (lane >> 2) + h * 8;
                float mn = fs[F_M + row];
                float al = fs[F_A + row];
                float s = 0.f;
#pragma unroll
                for (int nj = 0; nj < 8; nj++) {
                    float p0 = __expf(acc[mi][nj][2 * h] - mn);
                    float p1 = __expf(acc[mi][nj][2 * h + 1] - mn);
                    s += p0 + p1;
                    int c = wn * 64 + nj * 8 + 2 * (lane & 3);
                    uint32_t off = ((uint32_t)row * FPITCH + c * 2) >> 2;
                    dsm[(FK_OFF >> 2) + off] = pack2h(p0, p1);
                    O[mi][nj][2 * h] *= al;
                    O[mi][nj][2 * h + 1] *= al;
                }
                s += __shfl_xor_sync(0xffffffffu, s, 1);
                s += __shfl_xor_sync(0xffffffffu, s, 2);
                if ((lane & 3) == 0) fs[F_RSUM + row * 2 + wn] = s;
            }
        __syncthreads();
        if (tid < 128)
            fs[F_L + tid] = fs[F_L + tid] * fs[F_A + tid] +
                            fs[F_RSUM + tid * 2] + fs[F_RSUM + tid * 2 + 1];

        CP_WAIT0();
        __syncthreads();

        // ---- O += P V (2 mma: P*Vh + P*Vl) ----
#pragma unroll
        for (int ks = 0; ks < 8; ks++) {
            uint32_t ko = ks * 32;
            uint32_t ap[2][4];
#pragma unroll
            for (int mi = 0; mi < 2; mi++) {
                uint32_t ro = (uint32_t)(wm * 32 + mi * 16 + lrA) * FPITCH + ksA;
                LDSM_X4(ap[mi], sb + FK_OFF + ro + ko);
            }
#pragma unroll
            for (int njp = 0; njp < 4; njp++) {
                uint32_t bhf[4], blf[4];
                LDSM_X4(bhf, sb + FV_OFF + nB[njp] + ko);
                LDSM_X4(blf, sb + 4 * FT + nB[njp] + ko);
#pragma unroll
                for (int sub = 0; sub < 2; sub++) {
                    int nj = njp * 2 + sub;
                    uint32_t b0h = bhf[sub * 2], b1h = bhf[sub * 2 + 1];
                    uint32_t b0l = blf[sub * 2], b1l = blf[sub * 2 + 1];
#pragma unroll
                    for (int mi = 0; mi < 2; mi++) {
                        mma16816(O[mi][nj], ap[mi], b0h, b1h);
                        mma16816(O[mi][nj], ap[mi], b0l, b1l);
                    }
                }
            }
        }
        __syncthreads();

        if (j < 3) {
            cpT(sb + FK_OFF, Kh + (size_t)(j + 1) * 128 * CHD, CHD);
            cpT(sb + 2 * FT, Kl + (size_t)(j + 1) * 128 * CHD, CHD);
            CP_COMMIT();
            cpT(sb + FV_OFF, Vh + (j + 1) * 128, CL);
            cpT(sb + 4 * FT, Vl + (j + 1) * 128, CL);
            CP_COMMIT();
        }
    }
    __syncthreads();

    // ---- epilogue: att = O / l -> plain fp16 ----
    __half* Att = g_att + qrow0 * CDIM + hh * CHD;
#pragma unroll
    for (int nj = 0; nj < 8; nj++) {
        int c = wn * 64 + nj * 8 + 2 * (lane & 3);
#pragma unroll
        for (int mi = 0; mi < 2; mi++) {
#pragma unroll
            for (int h = 0; h < 2; h++) {
                int row = wm * 32 + mi * 16 + (lane >> 2) + h * 8;
                float inv = 1.f / fs[F_L + row];
                *(uint32_t*)&Att[(size_t)row * CDIM + c] =
                    pack2h(O[mi][nj][2 * h] * inv, O[mi][nj][2 * h + 1] * inv);
            }
        }
    }
}

// ---------------- host launcher ----------------
extern "C" void kernel_launch(void* const* d_in, const int* in_sizes, int n_in,
                              void* d_out, int out_size) {
    (void)in_sizes; (void)n_in; (void)out_size;
    const float* hid = (const float*)d_in[0];
    const float* ctx = (const float*)d_in[1];
    const float* Wq  = (const float*)d_in[2];
    const float* bq  = (const float*)d_in[3];
    const float* Wkv = (const float*)d_in[4];
    const float* bkv = (const float*)d_in[5];
    const float* gq  = (const float*)d_in[6];
    const float* gk  = (const float*)d_in[7];
    const float* Wo  = (const float*)d_in[8];
    const float* bo  = (const float*)d_in[9];
    float* out = (float*)d_out;

    __half *wq_h, *wq_l, *wkv_h, *wkv_l, *wo_h, *wo_l;
    __half *hidh, *ctxh, *qs, *att, *k_h, *k_l, *v_h, *v_l;
    float *q, *kv;
    cudaGetSymbolAddress((void**)&wq_h, g_wq_h);
    cudaGetSymbolAddress((void**)&wq_l, g_wq_l);
    cudaGetSymbolAddress((void**)&wkv_h, g_wkv_h);
    cudaGetSymbolAddress((void**)&wkv_l, g_wkv_l);
    cudaGetSymbolAddress((void**)&wo_h, g_wo_h);
    cudaGetSymbolAddress((void**)&wo_l, g_wo_l);
    cudaGetSymbolAddress((void**)&hidh, g_hid);
    cudaGetSymbolAddress((void**)&ctxh, g_ctx);
    cudaGetSymbolAddress((void**)&qs, g_qs);
    cudaGetSymbolAddress((void**)&att, g_att);
    cudaGetSymbolAddress((void**)&k_h, g_k_h);
    cudaGetSymbolAddress((void**)&k_l, g_k_l);
    cudaGetSymbolAddress((void**)&v_h, g_v_h);
    cudaGetSymbolAddress((void**)&v_l, g_v_l);
    cudaGetSymbolAddress((void**)&q, g_q);
    cudaGetSymbolAddress((void**)&kv, g_kv);

    cudaFuncSetAttribute(gemm_tc, cudaFuncAttributeMaxDynamicSharedMemorySize,
                         GEMM_SMEM_BYTES);
    cudaFuncSetAttribute(flash_attn, cudaFuncAttributeMaxDynamicSharedMemorySize,
                         FLASH_SMEM);

    dim3 tb(32, 8);
    transpose_split<<<dim3(CDIM / 32, CDIM / 32), tb>>>(Wq, wq_h, wq_l, CDIM, CDIM);
    transpose_split<<<dim3(CKV / 32, CDIM / 32), tb>>>(Wkv, wkv_h, wkv_l, CDIM, CKV);
    transpose_split<<<dim3(CDIM / 32, CDIM / 32), tb>>>(Wo, wo_h, wo_l, CDIM, CDIM);

    {
        size_t n4 = (size_t)CB * CS * CDIM / 4;
        tofp16<<<(unsigned)((n4 + 255) / 256), 256>>>(hid, hidh, n4);
        size_t m4 = (size_t)CB * CL * CDIM / 4;
        tofp16<<<(unsigned)((m4 + 255) / 256), 256>>>(ctx, ctxh, m4);
    }

    GP p{};

    // Q = hidden @ Wq + bq  -> fp32 q
    p.A = hidh; p.ldA = CDIM; p.sAb = 0; p.sAh = 0;
    p.Bhi = wq_h; p.Blo = wq_l; p.sBb = 0; p.sBh = 0;
    p.C = q; p.ldC = CDIM; p.sCb = 0; p.sCh = 0;
    p.bias = bq; p.K = CDIM; p.Hdiv = 1;
    gemm_tc<<<dim3(CDIM / 128, (CB * CS) / 128, 1), 128, GEMM_SMEM_BYTES>>>(p);

    rmsnorm_h<<<CB * CS, 256>>>(q, gq, qs);

    // KV = context @ Wkv + bkv -> fp32 kv
    p.A = ctxh; p.ldA = CDIM; p.sAb = 0; p.sAh = 0;
    p.Bhi = wkv_h; p.Blo = wkv_l; p.sBb = 0; p.sBh = 0;
    p.C = kv; p.ldC = CKV; p.sCb = 0; p.sCh = 0;
    p.bias = bkv; p.K = CDIM; p.Hdiv = 1;
    gemm_tc<<<dim3(CKV / 128, (CB * CL) / 128, 1), 128, GEMM_SMEM_BYTES>>>(p);

    rmsnorm_rows<<<CB * CL, 256>>>(kv, CKV, gk);

    {
        size_t nK = (size_t)CB * CH * CL * CHD;
        split_k<<<(unsigned)((nK + 255) / 256), 256>>>(kv, k_h, k_l);
        split_v<<<(unsigned)((nK + 255) / 256), 256>>>(kv, v_h, v_l);
    }

    // fused attention -> plain fp16 att
    flash_attn<<<dim3(CS / 128, CB * CH), 256, FLASH_SMEM>>>();

    // out = att @ Wo + bo
    p.A = att; p.ldA = CDIM; p.sAb = 0; p.sAh = 0;
    p.Bhi = wo_h; p.Blo = wo_l; p.sBb = 0; p.sBh = 0;
    p.C = out; p.ldC = CDIM; p.sCb = 0; p.sCh = 0;
    p.bias = bo; p.K = CDIM; p.Hdiv = 1;
    gemm_tc<<<dim3(CDIM / 128, (CB * CS) / 128, 1), 128, GEMM_SMEM_BYTES>>>(p);
}

// round 11
// speedup vs baseline: 3.2705x; 1.3233x over previous
#include <cuda_runtime.h>
#include <cuda_fp16.h>
#include <cstdint>
#include <cstddef>

#define CB   2
#define CS   4096
#define CL   512
#define CDIM 5120
#define CH   40
#define CHD  128
#define CKV  (2*CDIM)
#define FSCALE 0.08838834764831845f
#define FEPS 1e-6f

// ---------------- static device scratch ----------------
// weights: transposed plain fp16
__device__ __half g_wq  [(size_t)CDIM*CDIM];
__device__ __half g_wkv [(size_t)CDIM*CKV];
__device__ __half g_wo  [(size_t)CDIM*CDIM];
// attention K/V: fp16 hi/lo pairs (keep extra precision in attention)
__device__ __half g_k_h [(size_t)CB*CH*CL*CHD];
__device__ __half g_k_l [(size_t)CB*CH*CL*CHD];
__device__ __half g_v_h [(size_t)CB*CH*CHD*CL];
__device__ __half g_v_l [(size_t)CB*CH*CHD*CL];
// A-side operands: plain fp16
__device__ __half g_hid [(size_t)CB*CS*CDIM];
__device__ __half g_ctx [(size_t)CB*CL*CDIM];
__device__ __half g_qs  [(size_t)CB*CS*CDIM];
__device__ __half g_att [(size_t)CB*CS*CDIM];
// fp32 intermediates
__device__ float  g_q   [(size_t)CB*CS*CDIM];
__device__ float  g_kv  [(size_t)CB*CL*CKV];

// ---------------- helpers ----------------
__device__ __forceinline__ uint32_t smem_u32(const void* p) {
    uint32_t a;
    asm("{ .reg .u64 t; cvta.to.shared.u64 t, %1; cvt.u32.u64 %0, t; }" : "=r"(a) : "l"(p));
    return a;
}

__device__ __forceinline__ uint32_t pack2h(float x, float y) {
    __half2 h = __floats2half2_rn(x, y);
    return *reinterpret_cast<uint32_t*>(&h);
}

__device__ __forceinline__ void mma16816(float* c, const uint32_t* a, uint32_t b0, uint32_t b1) {
    asm volatile(
        "mma.sync.aligned.m16n8k16.row.col.f32.f16.f16.f32 "
        "{%0,%1,%2,%3},{%4,%5,%6,%7},{%8,%9},{%0,%1,%2,%3};\n"
        : "+f"(c[0]), "+f"(c[1]), "+f"(c[2]), "+f"(c[3])
        : "r"(a[0]), "r"(a[1]), "r"(a[2]), "r"(a[3]), "r"(b0), "r"(b1));
}

#define LDSM_X4(r, addr)                                                              \
    asm volatile("ldmatrix.sync.aligned.m8n8.x4.shared.b16 {%0,%1,%2,%3}, [%4];"      \
                 : "=r"((r)[0]), "=r"((r)[1]), "=r"((r)[2]), "=r"((r)[3]) : "r"(addr))

#define CP_ASYNC16(dst, src) \
    asm volatile("cp.async.ca.shared.global [%0], [%1], 16;\n" :: "r"(dst), "l"(src))
#define CP_COMMIT() asm volatile("cp.async.commit_group;\n" ::: "memory")
#define CP_WAIT0()  asm volatile("cp.async.wait_group 0;\n" ::: "memory")
#define CP_WAIT1()  asm volatile("cp.async.wait_group 1;\n" ::: "memory")

// ---------------- weight transpose to plain fp16:  T[n][k] = W[k][n] ----------------
__global__ void transpose_h(const float* __restrict__ W, __half* __restrict__ T,
                            int K, int N) {
    __shared__ float t[32][33];
    int n0 = blockIdx.x * 32, k0 = blockIdx.y * 32;
    int tx = threadIdx.x, ty = threadIdx.y;
#pragma unroll
    for (int i = 0; i < 32; i += 8)
        t[ty + i][tx] = W[(size_t)(k0 + ty + i) * N + n0 + tx];
    __syncthreads();
#pragma unroll
    for (int i = 0; i < 32; i += 8)
        T[(size_t)(n0 + ty + i) * K + k0 + tx] = __float2half_rn(t[tx][ty + i]);
}

// ---------------- elementwise fp32 -> plain fp16 ----------------
__global__ void tofp16(const float* __restrict__ X, __half* __restrict__ H, size_t n4) {
    size_t i = (size_t)blockIdx.x * 256 + threadIdx.x;
    if (i >= n4) return;
    float4 v = ((const float4*)X)[i];
    ((uint2*)H)[i] = make_uint2(pack2h(v.x, v.y), pack2h(v.z, v.w));
}

// ---------------- RMSNorm in place (fp32) ----------------
__global__ void rmsnorm_rows(float* __restrict__ X, long ld, const float* __restrict__ g) {
    float* row = X + (size_t)blockIdx.x * ld;
    int tid = threadIdx.x;
    float4* r4 = (float4*)row;
    const float4* g4 = (const float4*)g;
    float s = 0.f;
#pragma unroll 5
    for (int i = tid; i < CDIM / 4; i += 256) {
        float4 v = r4[i];
        s += v.x * v.x + v.y * v.y + v.z * v.z + v.w * v.w;
    }
#pragma unroll
    for (int o = 16; o; o >>= 1) s += __shfl_xor_sync(0xffffffffu, s, o);
    __shared__ float ws[8];
    if ((tid & 31) == 0) ws[tid >> 5] = s;
    __syncthreads();
    if (tid == 0) {
        float x = 0.f;
#pragma unroll
        for (int i = 0; i < 8; i++) x += ws[i];
        ws[0] = rsqrtf(x / (float)CDIM + FEPS);
    }
    __syncthreads();
    float rs = ws[0];
#pragma unroll 5
    for (int i = tid; i < CDIM / 4; i += 256) {
        float4 v = r4[i];
        float4 w = g4[i];
        v.x *= rs * w.x; v.y *= rs * w.y; v.z *= rs * w.z; v.w *= rs * w.w;
        r4[i] = v;
    }
}

// ---------------- RMSNorm reading fp32, writing plain fp16 ----------------
__global__ void rmsnorm_h(const float* __restrict__ X, const float* __restrict__ g,
                          __half* __restrict__ H) {
    const float* row = X + (size_t)blockIdx.x * CDIM;
    int tid = threadIdx.x;
    const float4* r4 = (const float4*)row;
    const float4* g4 = (const float4*)g;
    float s = 0.f;
#pragma unroll 5
    for (int i = tid; i < CDIM / 4; i += 256) {
        float4 v = r4[i];
        s += v.x * v.x + v.y * v.y + v.z * v.z + v.w * v.w;
    }
#pragma unroll
    for (int o = 16; o; o >>= 1) s += __shfl_xor_sync(0xffffffffu, s, o);
    __shared__ float ws[8];
    if ((tid & 31) == 0) ws[tid >> 5] = s;
    __syncthreads();
    if (tid == 0) {
        float x = 0.f;
#pragma unroll
        for (int i = 0; i < 8; i++) x += ws[i];
        ws[0] = rsqrtf(x / (float)CDIM + FEPS);
    }
    __syncthreads();
    float rs = ws[0];
    uint2* Hr = (uint2*)(H + (size_t)blockIdx.x * CDIM);
#pragma unroll 5
    for (int i = tid; i < CDIM / 4; i += 256) {
        float4 v = r4[i];
        float4 w = g4[i];
        v.x *= rs * w.x; v.y *= rs * w.y; v.z *= rs * w.z; v.w *= rs * w.w;
        Hr[i] = make_uint2(pack2h(v.x, v.y), pack2h(v.z, v.w));
    }
}

// ---------------- K split: per-head [ (b*H+h)*L + l ][ d ], fp16 hi/lo ----------------
__global__ void split_k(const float* __restrict__ kv, __half* __restrict__ h,
                        __half* __restrict__ l) {
    size_t i = (size_t)blockIdx.x * 256 + threadIdx.x;
    if (i >= (size_t)CB * CH * CL * CHD) return;
    int d = (int)(i & 127);
    size_t r = i >> 7;
    int ll = (int)(r & 511); r >>= 9;
    int hh = (int)(r % CH);
    int b  = (int)(r / CH);
    float v = kv[((size_t)(b * CL + ll)) * CKV + hh * CHD + d];
    __half x = __float2half_rn(v);
    h[i] = x;
    l[i] = __float2half_rn(v - __half2float(x));
}

// ---------------- V split transposed: [ (b*H+h)*D + d ][ l ], fp16 hi/lo ----------------
__global__ void split_v(const float* __restrict__ kv, __half* __restrict__ h,
                        __half* __restrict__ l) {
    size_t i = (size_t)blockIdx.x * 256 + threadIdx.x;
    if (i >= (size_t)CB * CH * CHD * CL) return;
    int ll = (int)(i & 511);
    size_t r = i >> 9;
    int d = (int)(r & 127); r >>= 7;
    int hh = (int)(r % CH);
    int b  = (int)(r / CH);
    float v = kv[((size_t)(b * CL + ll)) * CKV + CDIM + hh * CHD + d];
    __half x = __float2half_rn(v);
    h[i] = x;
    l[i] = __float2half_rn(v - __half2float(x));
}

// ---------------- fp16 GEMM: A, B plain fp16; C = A@B^T + bias ----------------
struct GP {
    const __half* A;  long ldA;
    const __half* B;
    float* C;  long ldC;
    const float* bias;
    int K;
};

#define TILE_B  (128 * 80)          // 10240 bytes
#define BUF_B   (2 * TILE_B)        // A, B
#define GEMM_SMEM_BYTES (2 * BUF_B) // 40960

extern __shared__ uint32_t dsm[];

__global__ __launch_bounds__(128, 2) void gemm_tc(GP p) {
    uint32_t sbase = smem_u32(dsm);

    int tid = threadIdx.x, lane = tid & 31, wp = tid >> 5;
    int wm = wp >> 1, wn = wp & 1;

    const __half* A = p.A + (size_t)blockIdx.y * 128 * p.ldA;
    const __half* B = p.B + (size_t)blockIdx.x * 128 * p.K;

    float acc[4][8][4];
#pragma unroll
    for (int mi = 0; mi < 4; mi++)
#pragma unroll
        for (int nj = 0; nj < 8; nj++)
#pragma unroll
            for (int q = 0; q < 4; q++) acc[mi][nj][q] = 0.f;

    int nk = p.K / 32;
    int r0 = tid >> 2, c0 = tid & 3;

    int lrowA = (lane & 7) + ((lane >> 3) & 1) * 8;
    int kselA = ((lane >> 4) & 1) * 16;
    int lrowB = (lane & 7) + ((lane >> 4) & 1) * 8;
    int kselB = ((lane >> 3) & 1) * 16;

    auto cpAll = [&](int kt, int buf) {
        uint32_t base = sbase + buf * BUF_B;
        long ka = (long)kt * 32 + c0 * 8;
#pragma unroll
        for (int i = 0; i < 4; i++) {
            int r = r0 + 32 * i;
            uint32_t d = (uint32_t)r * 80 + c0 * 16;
            CP_ASYNC16(base + d,          A + (size_t)r * p.ldA + ka);
            CP_ASYNC16(base + TILE_B + d, B + (size_t)r * p.K + ka);
        }
    };

    auto compute = [&](int buf) {
        uint32_t aB = sbase + buf * BUF_B;
        uint32_t bB = aB + TILE_B;
        uint32_t aAddr[4], bAddr[4];
#pragma unroll
        for (int mi = 0; mi < 4; mi++)
            aAddr[mi] = aB + (uint32_t)(wm * 64 + mi * 16 + lrowA) * 80 + kselA;
#pragma unroll
        for (int njp = 0; njp < 4; njp++)
            bAddr[njp] = bB + (uint32_t)(wn * 64 + njp * 16 + lrowB) * 80 + kselB;
#pragma unroll
        for (int kk = 0; kk < 2; kk++) {
            uint32_t ko = kk * 32;
            uint32_t ah[4][4];
#pragma unroll
            for (int mi = 0; mi < 4; mi++) LDSM_X4(ah[mi], aAddr[mi] + ko);
#pragma unroll
            for (int njp = 0; njp < 4; njp++) {
                uint32_t bf[4];
                LDSM_X4(bf, bAddr[njp] + ko);
#pragma unroll
                for (int sub = 0; sub < 2; sub++) {
                    int nj = njp * 2 + sub;
                    uint32_t b0 = bf[sub * 2], b1 = bf[sub * 2 + 1];
#pragma unroll
                    for (int mi = 0; mi < 4; mi++)
                        mma16816(acc[mi][nj], ah[mi], b0, b1);
                }
            }
        }
    };

    cpAll(0, 0);
    CP_COMMIT();
    CP_WAIT0();
    __syncthreads();

    for (int kt = 0; kt < nk; kt++) {
        if (kt + 1 < nk) {
            cpAll(kt + 1, (kt + 1) & 1);
            CP_COMMIT();
        }
        compute(kt & 1);
        CP_WAIT0();
        __syncthreads();
    }

    float* C = p.C + (size_t)blockIdx.y * 128 * p.ldC + (size_t)blockIdx.x * 128;
#pragma unroll
    for (int nj = 0; nj < 8; nj++) {
        int c = wn * 64 + nj * 8 + ((lane & 3) << 1);
        float b0 = 0.f, b1 = 0.f;
        if (p.bias) {
            size_t cg = (size_t)blockIdx.x * 128 + c;
            b0 = p.bias[cg];
            b1 = p.bias[cg + 1];
        }
#pragma unroll
        for (int mi = 0; mi < 4; mi++) {
            int r = wm * 64 + mi * 16 + (lane >> 2);
            *(float2*)&C[(size_t)r * p.ldC + c] =
                make_float2(acc[mi][nj][0] + b0, acc[mi][nj][1] + b1);
            *(float2*)&C[(size_t)(r + 8) * p.ldC + c] =
                make_float2(acc[mi][nj][2] + b0, acc[mi][nj][3] + b1);
        }
    }
}

// ---------------- fused flash attention: Q plain fp16; K,V split; P plain fp16 ----------------
#define FPITCH 272
#define FT     (128 * FPITCH)
#define FQ_OFF 0
#define FK_OFF (1 * FT)
#define FV_OFF (3 * FT)
#define FSTF   ((5 * FT) / 4)
#define F_M    (FSTF)
#define F_L    (FSTF + 128)
#define F_A    (FSTF + 256)
#define F_RMAX (FSTF + 384)
#define F_RSUM (FSTF + 640)
#define FLASH_SMEM (5 * FT + 3584)

__global__ __launch_bounds__(256, 1) void flash_attn() {
    uint32_t sb = smem_u32(dsm);
    float* fs = (float*)dsm;
    int tid = threadIdx.x, lane = tid & 31, wp = tid >> 5;
    int wm = wp >> 1, wn = wp & 1;
    int bh = blockIdx.y, b = bh / CH, hh = bh % CH;
    size_t qrow0 = (size_t)b * CS + (size_t)blockIdx.x * 128;

    const __half* Q  = g_qs + qrow0 * CDIM + hh * CHD;
    const __half* Kh = g_k_h + (size_t)bh * CL * CHD;
    const __half* Kl = g_k_l + (size_t)bh * CL * CHD;
    const __half* Vh = g_v_h + (size_t)bh * CHD * CL;
    const __half* Vl = g_v_l + (size_t)bh * CHD * CL;

    if (tid < 128) {
        fs[F_M + tid] = -1e30f;
        fs[F_L + tid] = 0.f;
    }

    float O[2][8][4];
#pragma unroll
    for (int mi = 0; mi < 2; mi++)
#pragma unroll
        for (int nj = 0; nj < 8; nj++)
#pragma unroll
            for (int q = 0; q < 4; q++) O[mi][nj][q] = 0.f;

    int lrA = (lane & 7) + ((lane >> 3) & 1) * 8;
    int ksA = ((lane >> 4) & 1) * 16;
    int lrB = (lane & 7) + ((lane >> 4) & 1) * 8;
    int ksB = ((lane >> 3) & 1) * 16;

    auto cpT = [&](uint32_t dst, const __half* src, long stride) {
#pragma unroll
        for (int i = 0; i < 8; i++) {
            int idx = tid + 256 * i;
            int row = idx >> 4, ch = idx & 15;
            CP_ASYNC16(dst + (uint32_t)row * FPITCH + ch * 16,
                       src + (size_t)row * stride + ch * 8);
        }
    };

    cpT(sb + FQ_OFF, Q, CDIM);
    cpT(sb + FK_OFF, Kh, CHD);
    cpT(sb + 2 * FT, Kl, CHD);
    CP_COMMIT();
    cpT(sb + FV_OFF, Vh, CL);
    cpT(sb + 4 * FT, Vl, CL);
    CP_COMMIT();

    uint32_t qA[2];
#pragma unroll
    for (int mi = 0; mi < 2; mi++)
        qA[mi] = sb + (uint32_t)(wm * 32 + mi * 16 + lrA) * FPITCH + ksA;
    uint32_t nB[4];
#pragma unroll
    for (int njp = 0; njp < 4; njp++)
        nB[njp] = (uint32_t)(wn * 64 + njp * 16 + lrB) * FPITCH + ksB;

    for (int j = 0; j < 4; j++) {
        CP_WAIT1();
        __syncthreads();

        float acc[2][8][4];
#pragma unroll
        for (int mi = 0; mi < 2; mi++)
#pragma unroll
            for (int nj = 0; nj < 8; nj++)
#pragma unroll
                for (int q = 0; q < 4; q++) acc[mi][nj][q] = 0.f;

#pragma unroll
        for (int ks = 0; ks < 8; ks++) {
            uint32_t ko = ks * 32;
            uint32_t aq[2][4];
#pragma unroll
            for (int mi = 0; mi < 2; mi++) LDSM_X4(aq[mi], qA[mi] + ko);
#pragma unroll
            for (int njp = 0; njp < 4; njp++) {
                uint32_t bhf[4], blf[4];
                LDSM_X4(bhf, sb + FK_OFF + nB[njp] + ko);
                LDSM_X4(blf, sb + 2 * FT + nB[njp] + ko);
#pragma unroll
                for (int sub = 0; sub < 2; sub++) {
                    int nj = njp * 2 + sub;
                    uint32_t b0h = bhf[sub * 2], b1h = bhf[sub * 2 + 1];
                    uint32_t b0l = blf[sub * 2], b1l = blf[sub * 2 + 1];
#pragma unroll
                    for (int mi = 0; mi < 2; mi++) {
                        mma16816(acc[mi][nj], aq[mi], b0h, b1h);
                        mma16816(acc[mi][nj], aq[mi], b0l, b1l);
                    }
                }
            }
        }
#pragma unroll
        for (int mi = 0; mi < 2; mi++)
#pragma unroll
            for (int nj = 0; nj < 8; nj++)
#pragma unroll
                for (int q = 0; q < 4; q++) acc[mi][nj][q] *= FSCALE;

        __syncthreads();

#pragma unroll
        for (int mi = 0; mi < 2; mi++)
#pragma unroll
            for (int h = 0; h < 2; h++) {
                float mx = -1e30f;
#pragma unroll
                for (int nj = 0; nj < 8; nj++)
                    mx = fmaxf(mx, fmaxf(acc[mi][nj][2 * h], acc[mi][nj][2 * h + 1]));
                mx = fmaxf(mx, __shfl_xor_sync(0xffffffffu, mx, 1));
                mx = fmaxf(mx, __shfl_xor_sync(0xffffffffu, mx, 2));
                if ((lane & 3) == 0) {
                    int row = wm * 32 + mi * 16 + (lane >> 2) + h * 8;
                    fs[F_RMAX + row * 2 + wn] = mx;
                }
            }
        __syncthreads();
        if (tid < 128) {
            float mc = fmaxf(fs[F_RMAX + tid * 2], fs[F_RMAX + tid * 2 + 1]);
            float mo = fs[F_M + tid];
            float mn = fmaxf(mo, mc);
            fs[F_M + tid] = mn;
            fs[F_A + tid] = __expf(mo - mn);
        }
        __syncthreads();

#pragma unroll
        for (int mi = 0; mi < 2; mi++)
#pragma unroll
            for (int h = 0; h < 2; h++) {
                int row = wm * 32 + mi * 16 + (lane >> 2) + h * 8;
                float mn = fs[F_M + row];
                float al = fs[F_A + row];
                float s = 0.f;
#pragma unroll
                for (int nj = 0; nj < 8; nj++) {
                    float p0 = __expf(acc[mi][nj][2 * h] - mn);
                    float p1 = __expf(acc[mi][nj][2 * h + 1] - mn);
                    s += p0 + p1;
                    int c = wn * 64 + nj * 8 + 2 * (lane & 3);
                    uint32_t off = ((uint32_t)row * FPITCH + c * 2) >> 2;
                    dsm[(FK_OFF >> 2) + off] = pack2h(p0, p1);
                    O[mi][nj][2 * h] *= al;
                    O[mi][nj][2 * h + 1] *= al;
                }
                s += __shfl_xor_sync(0xffffffffu, s, 1);
                s += __shfl_xor_sync(0xffffffffu, s, 2);
                if ((lane & 3) == 0) fs[F_RSUM + row * 2 + wn] = s;
            }
        __syncthreads();
        if (tid < 128)
            fs[F_L + tid] = fs[F_L + tid] * fs[F_A + tid] +
                            fs[F_RSUM + tid * 2] + fs[F_RSUM + tid * 2 + 1];

        CP_WAIT0();
        __syncthreads();

#pragma unroll
        for (int ks = 0; ks < 8; ks++) {
            uint32_t ko = ks * 32;
            uint32_t ap[2][4];
#pragma unroll
            for (int mi = 0; mi < 2; mi++) {
                uint32_t ro = (uint32_t)(wm * 32 + mi * 16 + lrA) * FPITCH + ksA;
                LDSM_X4(ap[mi], sb + FK_OFF + ro + ko);
            }
#pragma unroll
            for (int njp = 0; njp < 4; njp++) {
                uint32_t bhf[4], blf[4];
                LDSM_X4(bhf, sb + FV_OFF + nB[njp] + ko);
                LDSM_X4(blf, sb + 4 * FT + nB[njp] + ko);
#pragma unroll
                for (int sub = 0; sub < 2; sub++) {
                    int nj = njp * 2 + sub;
                    uint32_t b0h = bhf[sub * 2], b1h = bhf[sub * 2 + 1];
                    uint32_t b0l = blf[sub * 2], b1l = blf[sub * 2 + 1];
#pragma unroll
                    for (int mi = 0; mi < 2; mi++) {
                        mma16816(O[mi][nj], ap[mi], b0h, b1h);
                        mma16816(O[mi][nj], ap[mi], b0l, b1l);
                    }
                }
            }
        }
        __syncthreads();

        if (j < 3) {
            cpT(sb + FK_OFF, Kh + (size_t)(j + 1) * 128 * CHD, CHD);
            cpT(sb + 2 * FT, Kl + (size_t)(j + 1) * 128 * CHD, CHD);
            CP_COMMIT();
            cpT(sb + FV_OFF, Vh + (j + 1) * 128, CL);
            cpT(sb + 4 * FT, Vl + (j + 1) * 128, CL);
            CP_COMMIT();
        }
    }
    __syncthreads();

    __half* Att = g_att + qrow0 * CDIM + hh * CHD;
#pragma unroll
    for (int nj = 0; nj < 8; nj++) {
        int c = wn * 64 + nj * 8 + 2 * (lane & 3);
#pragma unroll
        for (int mi = 0; mi < 2; mi++) {
#pragma unroll
            for (int h = 0; h < 2; h++) {
                int row = wm * 32 + mi * 16 + (lane >> 2) + h * 8;
                float inv = 1.f / fs[F_L + row];
                *(uint32_t*)&Att[(size_t)row * CDIM + c] =
                    pack2h(O[mi][nj][2 * h] * inv, O[mi][nj][2 * h + 1] * inv);
            }
        }
    }
}

// ---------------- host launcher ----------------
extern "C" void kernel_launch(void* const* d_in, const int* in_sizes, int n_in,
                              void* d_out, int out_size) {
    (void)in_sizes; (void)n_in; (void)out_size;
    const float* hid = (const float*)d_in[0];
    const float* ctx = (const float*)d_in[1];
    const float* Wq  = (const float*)d_in[2];
    const float* bq  = (const float*)d_in[3];
    const float* Wkv = (const float*)d_in[4];
    const float* bkv = (const float*)d_in[5];
    const float* gq  = (const float*)d_in[6];
    const float* gk  = (const float*)d_in[7];
    const float* Wo  = (const float*)d_in[8];
    const float* bo  = (const float*)d_in[9];
    float* out = (float*)d_out;

    __half *wq, *wkv, *wo, *hidh, *ctxh, *qs, *att, *k_h, *k_l, *v_h, *v_l;
    float *q, *kv;
    cudaGetSymbolAddress((void**)&wq, g_wq);
    cudaGetSymbolAddress((void**)&wkv, g_wkv);
    cudaGetSymbolAddress((void**)&wo, g_wo);
    cudaGetSymbolAddress((void**)&hidh, g_hid);
    cudaGetSymbolAddress((void**)&ctxh, g_ctx);
    cudaGetSymbolAddress((void**)&qs, g_qs);
    cudaGetSymbolAddress((void**)&att, g_att);
    cudaGetSymbolAddress((void**)&k_h, g_k_h);
    cudaGetSymbolAddress((void**)&k_l, g_k_l);
    cudaGetSymbolAddress((void**)&v_h, g_v_h);
    cudaGetSymbolAddress((void**)&v_l, g_v_l);
    cudaGetSymbolAddress((void**)&q, g_q);
    cudaGetSymbolAddress((void**)&kv, g_kv);

    cudaFuncSetAttribute(gemm_tc, cudaFuncAttributeMaxDynamicSharedMemorySize,
                         GEMM_SMEM_BYTES);
    cudaFuncSetAttribute(flash_attn, cudaFuncAttributeMaxDynamicSharedMemorySize,
                         FLASH_SMEM);

    dim3 tb(32, 8);
    transpose_h<<<dim3(CDIM / 32, CDIM / 32), tb>>>(Wq, wq, CDIM, CDIM);
    transpose_h<<<dim3(CKV / 32, CDIM / 32), tb>>>(Wkv, wkv, CDIM, CKV);
    transpose_h<<<dim3(CDIM / 32, CDIM / 32), tb>>>(Wo, wo, CDIM, CDIM);

    {
        size_t n4 = (size_t)CB * CS * CDIM / 4;
        tofp16<<<(unsigned)((n4 + 255) / 256), 256>>>(hid, hidh, n4);
        size_t m4 = (size_t)CB * CL * CDIM / 4;
        tofp16<<<(unsigned)((m4 + 255) / 256), 256>>>(ctx, ctxh, m4);
    }

    GP p{};

    // Q = hidden @ Wq + bq  -> fp32 q
    p.A = hidh; p.ldA = CDIM; p.B = wq;
    p.C = q; p.ldC = CDIM; p.bias = bq; p.K = CDIM;
    gemm_tc<<<dim3(CDIM / 128, (CB * CS) / 128), 128, GEMM_SMEM_BYTES>>>(p);

    rmsnorm_h<<<CB * CS, 256>>>(q, gq, qs);

    // KV = context @ Wkv + bkv -> fp32 kv
    p.A = ctxh; p.ldA = CDIM; p.B = wkv;
    p.C = kv; p.ldC = CKV; p.bias = bkv; p.K = CDIM;
    gemm_tc<<<dim3(CKV / 128, (CB * CL) / 128), 128, GEMM_SMEM_BYTES>>>(p);

    rmsnorm_rows<<<CB * CL, 256>>>(kv, CKV, gk);

    {
        size_t nK = (size_t)CB * CH * CL * CHD;
        split_k<<<(unsigned)((nK + 255) / 256), 256>>>(kv, k_h, k_l);
        split_v<<<(unsigned)((nK + 255) / 256), 256>>>(kv, v_h, v_l);
    }

    // fused attention -> plain fp16 att
    flash_attn<<<dim3(CS / 128, CB * CH), 256, FLASH_SMEM>>>();

    // out = att @ Wo + bo
    p.A = att; p.ldA = CDIM; p.B = wo;
    p.C = out; p.ldC = CDIM; p.bias = bo; p.K = CDIM;
    gemm_tc<<<dim3(CDIM / 128, (CB * CS) / 128), 128, GEMM_SMEM_BYTES>>>(p);
}

// round 12
// speedup vs baseline: 4.2922x; 1.3124x over previous
#include <cuda_runtime.h>
#include <cuda_fp16.h>
#include <cstdint>
#include <cstddef>

#define CB   2
#define CS   4096
#define CL   512
#define CDIM 5120
#define CH   40
#define CHD  128
#define CKV  (2*CDIM)
#define FSCALE 0.08838834764831845f
#define FEPS 1e-6f

// ---------------- static device scratch ----------------
__device__ __half g_wq  [(size_t)CDIM*CDIM];
__device__ __half g_wkv [(size_t)CDIM*CKV];
__device__ __half g_wo  [(size_t)CDIM*CDIM];
__device__ __half g_k   [(size_t)CB*CH*CL*CHD];
__device__ __half g_v   [(size_t)CB*CH*CHD*CL];
__device__ __half g_hid [(size_t)CB*CS*CDIM];
__device__ __half g_ctx [(size_t)CB*CL*CDIM];
__device__ __half g_qs  [(size_t)CB*CS*CDIM];
__device__ __half g_att [(size_t)CB*CS*CDIM];
__device__ float  g_q   [(size_t)CB*CS*CDIM];
__device__ float  g_kv  [(size_t)CB*CL*CKV];

// ---------------- helpers ----------------
__device__ __forceinline__ uint32_t smem_u32(const void* p) {
    uint32_t a;
    asm("{ .reg .u64 t; cvta.to.shared.u64 t, %1; cvt.u32.u64 %0, t; }" : "=r"(a) : "l"(p));
    return a;
}

__device__ __forceinline__ uint32_t pack2h(float x, float y) {
    __half2 h = __floats2half2_rn(x, y);
    return *reinterpret_cast<uint32_t*>(&h);
}

__device__ __forceinline__ void mma16816(float* c, const uint32_t* a, uint32_t b0, uint32_t b1) {
    asm volatile(
        "mma.sync.aligned.m16n8k16.row.col.f32.f16.f16.f32 "
        "{%0,%1,%2,%3},{%4,%5,%6,%7},{%8,%9},{%0,%1,%2,%3};\n"
        : "+f"(c[0]), "+f"(c[1]), "+f"(c[2]), "+f"(c[3])
        : "r"(a[0]), "r"(a[1]), "r"(a[2]), "r"(a[3]), "r"(b0), "r"(b1));
}

#define LDSM_X4(r, addr)                                                              \
    asm volatile("ldmatrix.sync.aligned.m8n8.x4.shared.b16 {%0,%1,%2,%3}, [%4];"      \
                 : "=r"((r)[0]), "=r"((r)[1]), "=r"((r)[2]), "=r"((r)[3]) : "r"(addr))

#define CP_ASYNC16(dst, src) \
    asm volatile("cp.async.ca.shared.global [%0], [%1], 16;\n" :: "r"(dst), "l"(src))
#define CP_COMMIT() asm volatile("cp.async.commit_group;\n" ::: "memory")
#define CP_WAIT0()  asm volatile("cp.async.wait_group 0;\n" ::: "memory")
#define CP_WAIT1()  asm volatile("cp.async.wait_group 1;\n" ::: "memory")

// ---------------- weight transpose to plain fp16:  T[n][k] = W[k][n] ----------------
__global__ void transpose_h(const float* __restrict__ W, __half* __restrict__ T,
                            int K, int N) {
    __shared__ float t[32][33];
    int n0 = blockIdx.x * 32, k0 = blockIdx.y * 32;
    int tx = threadIdx.x, ty = threadIdx.y;
#pragma unroll
    for (int i = 0; i < 32; i += 8)
        t[ty + i][tx] = W[(size_t)(k0 + ty + i) * N + n0 + tx];
    __syncthreads();
#pragma unroll
    for (int i = 0; i < 32; i += 8)
        T[(size_t)(n0 + ty + i) * K + k0 + tx] = __float2half_rn(t[tx][ty + i]);
}

// ---------------- elementwise fp32 -> plain fp16 ----------------
__global__ void tofp16(const float* __restrict__ X, __half* __restrict__ H, size_t n4) {
    size_t i = (size_t)blockIdx.x * 256 + threadIdx.x;
    if (i >= n4) return;
    float4 v = ((const float4*)X)[i];
    ((uint2*)H)[i] = make_uint2(pack2h(v.x, v.y), pack2h(v.z, v.w));
}

// ---------------- RMSNorm in place (fp32) ----------------
__global__ void rmsnorm_rows(float* __restrict__ X, long ld, const float* __restrict__ g) {
    float* row = X + (size_t)blockIdx.x * ld;
    int tid = threadIdx.x;
    float4* r4 = (float4*)row;
    const float4* g4 = (const float4*)g;
    float s = 0.f;
#pragma unroll 5
    for (int i = tid; i < CDIM / 4; i += 256) {
        float4 v = r4[i];
        s += v.x * v.x + v.y * v.y + v.z * v.z + v.w * v.w;
    }
#pragma unroll
    for (int o = 16; o; o >>= 1) s += __shfl_xor_sync(0xffffffffu, s, o);
    __shared__ float ws[8];
    if ((tid & 31) == 0) ws[tid >> 5] = s;
    __syncthreads();
    if (tid == 0) {
        float x = 0.f;
#pragma unroll
        for (int i = 0; i < 8; i++) x += ws[i];
        ws[0] = rsqrtf(x / (float)CDIM + FEPS);
    }
    __syncthreads();
    float rs = ws[0];
#pragma unroll 5
    for (int i = tid; i < CDIM / 4; i += 256) {
        float4 v = r4[i];
        float4 w = g4[i];
        v.x *= rs * w.x; v.y *= rs * w.y; v.z *= rs * w.z; v.w *= rs * w.w;
        r4[i] = v;
    }
}

// ---------------- RMSNorm reading fp32, writing plain fp16 ----------------
__global__ void rmsnorm_h(const float* __restrict__ X, const float* __restrict__ g,
                          __half* __restrict__ H) {
    const float* row = X + (size_t)blockIdx.x * CDIM;
    int tid = threadIdx.x;
    const float4* r4 = (const float4*)row;
    const float4* g4 = (const float4*)g;
    float s = 0.f;
#pragma unroll 5
    for (int i = tid; i < CDIM / 4; i += 256) {
        float4 v = r4[i];
        s += v.x * v.x + v.y * v.y + v.z * v.z + v.w * v.w;
    }
#pragma unroll
    for (int o = 16; o; o >>= 1) s += __shfl_xor_sync(0xffffffffu, s, o);
    __shared__ float ws[8];
    if ((tid & 31) == 0) ws[tid >> 5] = s;
    __syncthreads();
    if (tid == 0) {
        float x = 0.f;
#pragma unroll
        for (int i = 0; i < 8; i++) x += ws[i];
        ws[0] = rsqrtf(x / (float)CDIM + FEPS);
    }
    __syncthreads();
    float rs = ws[0];
    uint2* Hr = (uint2*)(H + (size_t)blockIdx.x * CDIM);
#pragma unroll 5
    for (int i = tid; i < CDIM / 4; i += 256) {
        float4 v = r4[i];
        float4 w = g4[i];
        v.x *= rs * w.x; v.y *= rs * w.y; v.z *= rs * w.z; v.w *= rs * w.w;
        Hr[i] = make_uint2(pack2h(v.x, v.y), pack2h(v.z, v.w));
    }
}

// ---------------- K pack: per-head [ (b*H+h)*L + l ][ d ] fp16 ----------------
__global__ void pack_k(const float* __restrict__ kv, __half* __restrict__ h) {
    size_t i = (size_t)blockIdx.x * 256 + threadIdx.x;
    if (i >= (size_t)CB * CH * CL * CHD) return;
    int d = (int)(i & 127);
    size_t r = i >> 7;
    int ll = (int)(r & 511); r >>= 9;
    int hh = (int)(r % CH);
    int b  = (int)(r / CH);
    h[i] = __float2half_rn(kv[((size_t)(b * CL + ll)) * CKV + hh * CHD + d]);
}

// ---------------- V pack transposed: [ (b*H+h)*D + d ][ l ] fp16 ----------------
__global__ void pack_v(const float* __restrict__ kv, __half* __restrict__ h) {
    size_t i = (size_t)blockIdx.x * 256 + threadIdx.x;
    if (i >= (size_t)CB * CH * CHD * CL) return;
    int ll = (int)(i & 511);
    size_t r = i >> 9;
    int d = (int)(r & 127); r >>= 7;
    int hh = (int)(r % CH);
    int b  = (int)(r / CH);
    h[i] = __float2half_rn(kv[((size_t)(b * CL + ll)) * CKV + CDIM + hh * CHD + d]);
}

// ---------------- fp16 GEMM: BK=64, 4 warps 64x64 tiles, 2 CTAs/SM ----------------
struct GP {
    const __half* A;  long ldA;
    const __half* B;
    float* C;  long ldC;
    const float* bias;
    int K;
};

#define GPITCH  144
#define TILE_B  (128 * GPITCH)       // 18432
#define BUF_B   (2 * TILE_B)         // 36864
#define GEMM_SMEM_BYTES (2 * BUF_B)  // 73728

extern __shared__ uint32_t dsm[];

__global__ __launch_bounds__(128, 2) void gemm_tc(GP p) {
    uint32_t sbase = smem_u32(dsm);

    int tid = threadIdx.x, lane = tid & 31, wp = tid >> 5;
    int wm = wp >> 1, wn = wp & 1;

    const __half* A = p.A + (size_t)blockIdx.y * 128 * p.ldA;
    const __half* B = p.B + (size_t)blockIdx.x * 128 * p.K;

    float acc[4][8][4];
#pragma unroll
    for (int mi = 0; mi < 4; mi++)
#pragma unroll
        for (int nj = 0; nj < 8; nj++)
#pragma unroll
            for (int q = 0; q < 4; q++) acc[mi][nj][q] = 0.f;

    int nk = p.K / 64;
    int r0 = tid >> 3, c0 = tid & 7;   // row r0+16i, 16B chunk c0 (8 chunks = 128B row)

    int lrowA = (lane & 7) + ((lane >> 3) & 1) * 8;
    int kselA = ((lane >> 4) & 1) * 16;
    int lrowB = (lane & 7) + ((lane >> 4) & 1) * 8;
    int kselB = ((lane >> 3) & 1) * 16;

    auto cpAll = [&](int kt, int buf) {
        uint32_t base = sbase + buf * BUF_B;
        long ka = (long)kt * 64 + c0 * 8;
#pragma unroll
        for (int i = 0; i < 8; i++) {
            int r = r0 + 16 * i;
            uint32_t d = (uint32_t)r * GPITCH + c0 * 16;
            CP_ASYNC16(base + d,          A + (size_t)r * p.ldA + ka);
            CP_ASYNC16(base + TILE_B + d, B + (size_t)r * p.K + ka);
        }
    };

    auto compute = [&](int buf) {
        uint32_t aB = sbase + buf * BUF_B;
        uint32_t bB = aB + TILE_B;
        uint32_t aAddr[4], bAddr[4];
#pragma unroll
        for (int mi = 0; mi < 4; mi++)
            aAddr[mi] = aB + (uint32_t)(wm * 64 + mi * 16 + lrowA) * GPITCH + kselA;
#pragma unroll
        for (int njp = 0; njp < 4; njp++)
            bAddr[njp] = bB + (uint32_t)(wn * 64 + njp * 16 + lrowB) * GPITCH + kselB;
#pragma unroll
        for (int kk = 0; kk < 4; kk++) {
            uint32_t ko = kk * 32;
            uint32_t ah[4][4];
#pragma unroll
            for (int mi = 0; mi < 4; mi++) LDSM_X4(ah[mi], aAddr[mi] + ko);
#pragma unroll
            for (int njp = 0; njp < 4; njp++) {
                uint32_t bf[4];
                LDSM_X4(bf, bAddr[njp] + ko);
#pragma unroll
                for (int sub = 0; sub < 2; sub++) {
                    int nj = njp * 2 + sub;
                    uint32_t b0 = bf[sub * 2], b1 = bf[sub * 2 + 1];
#pragma unroll
                    for (int mi = 0; mi < 4; mi++)
                        mma16816(acc[mi][nj], ah[mi], b0, b1);
                }
            }
        }
    };

    cpAll(0, 0);
    CP_COMMIT();
    CP_WAIT0();
    __syncthreads();

    for (int kt = 0; kt < nk; kt++) {
        if (kt + 1 < nk) {
            cpAll(kt + 1, (kt + 1) & 1);
            CP_COMMIT();
        }
        compute(kt & 1);
        CP_WAIT0();
        __syncthreads();
    }

    float* C = p.C + (size_t)blockIdx.y * 128 * p.ldC + (size_t)blockIdx.x * 128;
#pragma unroll
    for (int nj = 0; nj < 8; nj++) {
        int c = wn * 64 + nj * 8 + ((lane & 3) << 1);
        float b0 = 0.f, b1 = 0.f;
        if (p.bias) {
            size_t cg = (size_t)blockIdx.x * 128 + c;
            b0 = p.bias[cg];
            b1 = p.bias[cg + 1];
        }
#pragma unroll
        for (int mi = 0; mi < 4; mi++) {
            int r = wm * 64 + mi * 16 + (lane >> 2);
            *(float2*)&C[(size_t)r * p.ldC + c] =
                make_float2(acc[mi][nj][0] + b0, acc[mi][nj][1] + b1);
            *(float2*)&C[(size_t)(r + 8) * p.ldC + c] =
                make_float2(acc[mi][nj][2] + b0, acc[mi][nj][3] + b1);
        }
    }
}

// ---------------- fused flash attention: all plain fp16 ----------------
#define FPITCH 272
#define FT     (128 * FPITCH)
#define FQ_OFF 0
#define FK_OFF (1 * FT)              // K (P overwrites)
#define FV_OFF (2 * FT)
#define FSTF   ((3 * FT) / 4)
#define F_M    (FSTF)
#define F_L    (FSTF + 128)
#define F_A    (FSTF + 256)
#define F_RMAX (FSTF + 384)
#define F_RSUM (FSTF + 640)
#define FLASH_SMEM (3 * FT + 3584)

__global__ __launch_bounds__(256, 1) void flash_attn() {
    uint32_t sb = smem_u32(dsm);
    float* fs = (float*)dsm;
    int tid = threadIdx.x, lane = tid & 31, wp = tid >> 5;
    int wm = wp >> 1, wn = wp & 1;
    int bh = blockIdx.y, b = bh / CH, hh = bh % CH;
    size_t qrow0 = (size_t)b * CS + (size_t)blockIdx.x * 128;

    const __half* Q = g_qs + qrow0 * CDIM + hh * CHD;
    const __half* K = g_k + (size_t)bh * CL * CHD;
    const __half* V = g_v + (size_t)bh * CHD * CL;

    if (tid < 128) {
        fs[F_M + tid] = -1e30f;
        fs[F_L + tid] = 0.f;
    }

    float O[2][8][4];
#pragma unroll
    for (int mi = 0; mi < 2; mi++)
#pragma unroll
        for (int nj = 0; nj < 8; nj++)
#pragma unroll
            for (int q = 0; q < 4; q++) O[mi][nj][q] = 0.f;

    int lrA = (lane & 7) + ((lane >> 3) & 1) * 8;
    int ksA = ((lane >> 4) & 1) * 16;
    int lrB = (lane & 7) + ((lane >> 4) & 1) * 8;
    int ksB = ((lane >> 3) & 1) * 16;

    auto cpT = [&](uint32_t dst, const __half* src, long stride) {
#pragma unroll
        for (int i = 0; i < 8; i++) {
            int idx = tid + 256 * i;
            int row = idx >> 4, ch = idx & 15;
            CP_ASYNC16(dst + (uint32_t)row * FPITCH + ch * 16,
                       src + (size_t)row * stride + ch * 8);
        }
    };

    cpT(sb + FQ_OFF, Q, CDIM);
    cpT(sb + FK_OFF, K, CHD);
    CP_COMMIT();
    cpT(sb + FV_OFF, V, CL);
    CP_COMMIT();

    uint32_t qA[2];
#pragma unroll
    for (int mi = 0; mi < 2; mi++)
        qA[mi] = sb + (uint32_t)(wm * 32 + mi * 16 + lrA) * FPITCH + ksA;
    uint32_t nB[4];
#pragma unroll
    for (int njp = 0; njp < 4; njp++)
        nB[njp] = (uint32_t)(wn * 64 + njp * 16 + lrB) * FPITCH + ksB;

    for (int j = 0; j < 4; j++) {
        CP_WAIT1();
        __syncthreads();

        float acc[2][8][4];
#pragma unroll
        for (int mi = 0; mi < 2; mi++)
#pragma unroll
            for (int nj = 0; nj < 8; nj++)
#pragma unroll
                for (int q = 0; q < 4; q++) acc[mi][nj][q] = 0.f;

#pragma unroll
        for (int ks = 0; ks < 8; ks++) {
            uint32_t ko = ks * 32;
            uint32_t aq[2][4];
#pragma unroll
            for (int mi = 0; mi < 2; mi++) LDSM_X4(aq[mi], qA[mi] + ko);
#pragma unroll
            for (int njp = 0; njp < 4; njp++) {
                uint32_t bf[4];
                LDSM_X4(bf, sb + FK_OFF + nB[njp] + ko);
#pragma unroll
                for (int sub = 0; sub < 2; sub++) {
                    int nj = njp * 2 + sub;
                    uint32_t b0 = bf[sub * 2], b1 = bf[sub * 2 + 1];
#pragma unroll
                    for (int mi = 0; mi < 2; mi++)
                        mma16816(acc[mi][nj], aq[mi], b0, b1);
                }
            }
        }
#pragma unroll
        for (int mi = 0; mi < 2; mi++)
#pragma unroll
            for (int nj = 0; nj < 8; nj++)
#pragma unroll
                for (int q = 0; q < 4; q++) acc[mi][nj][q] *= FSCALE;

        __syncthreads();

#pragma unroll
        for (int mi = 0; mi < 2; mi++)
#pragma unroll
            for (int h = 0; h < 2; h++) {
                float mx = -1e30f;
#pragma unroll
                for (int nj = 0; nj < 8; nj++)
                    mx = fmaxf(mx, fmaxf(acc[mi][nj][2 * h], acc[mi][nj][2 * h + 1]));
                mx = fmaxf(mx, __shfl_xor_sync(0xffffffffu, mx, 1));
                mx = fmaxf(mx, __shfl_xor_sync(0xffffffffu, mx, 2));
                if ((lane & 3) == 0) {
                    int row = wm * 32 + mi * 16 + (lane >> 2) + h * 8;
                    fs[F_RMAX + row * 2 + wn] = mx;
                }
            }
        __syncthreads();
        if (tid < 128) {
            float mc = fmaxf(fs[F_RMAX + tid * 2], fs[F_RMAX + tid * 2 + 1]);
            float mo = fs[F_M + tid];
            float mn = fmaxf(mo, mc);
            fs[F_M + tid] = mn;
            fs[F_A + tid] = __expf(mo - mn);
        }
        __syncthreads();

#pragma unroll
        for (int mi = 0; mi < 2; mi++)
#pragma unroll
            for (int h = 0; h < 2; h++) {
                int row = wm * 32 + mi * 16 + (lane >> 2) + h * 8;
                float mn = fs[F_M + row];
                float al = fs[F_A + row];
                float s = 0.f;
#pragma unroll
                for (int nj = 0; nj < 8; nj++) {
                    float p0 = __expf(acc[mi][nj][2 * h] - mn);
                    float p1 = __expf(acc[mi][nj][2 * h + 1] - mn);
                    s += p0 + p1;
                    int c = wn * 64 + nj * 8 + 2 * (lane & 3);
                    uint32_t off = ((uint32_t)row * FPITCH + c * 2) >> 2;
                    dsm[(FK_OFF >> 2) + off] = pack2h(p0, p1);
                    O[mi][nj][2 * h] *= al;
                    O[mi][nj][2 * h + 1] *= al;
                }
                s += __shfl_xor_sync(0xffffffffu, s, 1);
                s += __shfl_xor_sync(0xffffffffu, s, 2);
                if ((lane & 3) == 0) fs[F_RSUM + row * 2 + wn] = s;
            }
        __syncthreads();
        if (tid < 128)
            fs[F_L + tid] = fs[F_L + tid] * fs[F_A + tid] +
                            fs[F_RSUM + tid * 2] + fs[F_RSUM + tid * 2 + 1];

        CP_WAIT0();
        __syncthreads();

#pragma unroll
        for (int ks = 0; ks < 8; ks++) {
            uint32_t ko = ks * 32;
            uint32_t ap[2][4];
#pragma unroll
            for (int mi = 0; mi < 2; mi++) {
                uint32_t ro = (uint32_t)(wm * 32 + mi * 16 + lrA) * FPITCH + ksA;
                LDSM_X4(ap[mi], sb + FK_OFF + ro + ko);
            }
#pragma unroll
            for (int njp = 0; njp < 4; njp++) {
                uint32_t bf[4];
                LDSM_X4(bf, sb + FV_OFF + nB[njp] + ko);
#pragma unroll
                for (int sub = 0; sub < 2; sub++) {
                    int nj = njp * 2 + sub;
                    uint32_t b0 = bf[sub * 2], b1 = bf[sub * 2 + 1];
#pragma unroll
                    for (int mi = 0; mi < 2; mi++)
                        mma16816(O[mi][nj], ap[mi], b0, b1);
                }
            }
        }
        __syncthreads();

        if (j < 3) {
            cpT(sb + FK_OFF, K + (size_t)(j + 1) * 128 * CHD, CHD);
            CP_COMMIT();
            cpT(sb + FV_OFF, V + (j + 1) * 128, CL);
            CP_COMMIT();
        }
    }
    __syncthreads();

    __half* Att = g_att + qrow0 * CDIM + hh * CHD;
#pragma unroll
    for (int nj = 0; nj < 8; nj++) {
        int c = wn * 64 + nj * 8 + 2 * (lane & 3);
#pragma unroll
        for (int mi = 0; mi < 2; mi++) {
#pragma unroll
            for (int h = 0; h < 2; h++) {
                int row = wm * 32 + mi * 16 + (lane >> 2) + h * 8;
                float inv = 1.f / fs[F_L + row];
                *(uint32_t*)&Att[(size_t)row * CDIM + c] =
                    pack2h(O[mi][nj][2 * h] * inv, O[mi][nj][2 * h + 1] * inv);
            }
        }
    }
}

// ---------------- host launcher ----------------
extern "C" void kernel_launch(void* const* d_in, const int* in_sizes, int n_in,
                              void* d_out, int out_size) {
    (void)in_sizes; (void)n_in; (void)out_size;
    const float* hid = (const float*)d_in[0];
    const float* ctx = (const float*)d_in[1];
    const float* Wq  = (const float*)d_in[2];
    const float* bq  = (const float*)d_in[3];
    const float* Wkv = (const float*)d_in[4];
    const float* bkv = (const float*)d_in[5];
    const float* gq  = (const float*)d_in[6];
    const float* gk  = (const float*)d_in[7];
    const float* Wo  = (const float*)d_in[8];
    const float* bo  = (const float*)d_in[9];
    float* out = (float*)d_out;

    __half *wq, *wkv, *wo, *hidh, *ctxh, *qs, *att, *kh, *vh;
    float *q, *kv;
    cudaGetSymbolAddress((void**)&wq, g_wq);
    cudaGetSymbolAddress((void**)&wkv, g_wkv);
    cudaGetSymbolAddress((void**)&wo, g_wo);
    cudaGetSymbolAddress((void**)&hidh, g_hid);
    cudaGetSymbolAddress((void**)&ctxh, g_ctx);
    cudaGetSymbolAddress((void**)&qs, g_qs);
    cudaGetSymbolAddress((void**)&att, g_att);
    cudaGetSymbolAddress((void**)&kh, g_k);
    cudaGetSymbolAddress((void**)&vh, g_v);
    cudaGetSymbolAddress((void**)&q, g_q);
    cudaGetSymbolAddress((void**)&kv, g_kv);

    cudaFuncSetAttribute(gemm_tc, cudaFuncAttributeMaxDynamicSharedMemorySize,
                         GEMM_SMEM_BYTES);
    cudaFuncSetAttribute(flash_attn, cudaFuncAttributeMaxDynamicSharedMemorySize,
                         FLASH_SMEM);

    dim3 tb(32, 8);
    transpose_h<<<dim3(CDIM / 32, CDIM / 32), tb>>>(Wq, wq, CDIM, CDIM);
    transpose_h<<<dim3(CKV / 32, CDIM / 32), tb>>>(Wkv, wkv, CDIM, CKV);
    transpose_h<<<dim3(CDIM / 32, CDIM / 32), tb>>>(Wo, wo, CDIM, CDIM);

    {
        size_t n4 = (size_t)CB * CS * CDIM / 4;
        tofp16<<<(unsigned)((n4 + 255) / 256), 256>>>(hid, hidh, n4);
        size_t m4 = (size_t)CB * CL * CDIM / 4;
        tofp16<<<(unsigned)((m4 + 255) / 256), 256>>>(ctx, ctxh, m4);
    }

    GP p{};

    // Q = hidden @ Wq + bq  -> fp32 q
    p.A = hidh; p.ldA = CDIM; p.B = wq;
    p.C = q; p.ldC = CDIM; p.bias = bq; p.K = CDIM;
    gemm_tc<<<dim3(CDIM / 128, (CB * CS) / 128), 128, GEMM_SMEM_BYTES>>>(p);

    rmsnorm_h<<<CB * CS, 256>>>(q, gq, qs);

    // KV = context @ Wkv + bkv -> fp32 kv
    p.A = ctxh; p.ldA = CDIM; p.B = wkv;
    p.C = kv; p.ldC = CKV; p.bias = bkv; p.K = CDIM;
    gemm_tc<<<dim3(CKV / 128, (CB * CL) / 128), 128, GEMM_SMEM_BYTES>>>(p);

    rmsnorm_rows<<<CB * CL, 256>>>(kv, CKV, gk);

    {
        size_t nK = (size_t)CB * CH * CL * CHD;
        pack_k<<<(unsigned)((nK + 255) / 256), 256>>>(kv, kh);
        pack_v<<<(unsigned)((nK + 255) / 256), 256>>>(kv, vh);
    }

    // fused attention -> plain fp16 att
    flash_attn<<<dim3(CS / 128, CB * CH), 256, FLASH_SMEM>>>();

    // out = att @ Wo + bo
    p.A = att; p.ldA = CDIM; p.B = wo;
    p.C = out; p.ldC = CDIM; p.bias = bo; p.K = CDIM;
    gemm_tc<<<dim3(CDIM / 128, (CB * CS) / 128), 128, GEMM_SMEM_BYTES>>>(p);
}